// round 1
// baseline (speedup 1.0000x reference)
#include <cuda_runtime.h>
#include <math.h>
#include <stdint.h>

#define N_NODES 10000
#define N_EDGES 160000
#define ET (N_EDGES + N_NODES)

// ---------------- scratch (static __device__, no allocations) ----------------
__device__ float g_h[(size_t)N_NODES * 1536];   // GAT linear output (max 6 heads * 256)
__device__ float g_lin[(size_t)N_NODES * 1024]; // skip-linear output
__device__ float g_x1[(size_t)N_NODES * 1024];
__device__ float g_x2[(size_t)N_NODES * 1024];
__device__ float g_as[N_NODES * 6];
__device__ float g_ad[N_NODES * 6];
__device__ int   g_rowptr[N_NODES + 1];
__device__ int   g_cnt[N_NODES];
__device__ int   g_fill[N_NODES];
__device__ int   g_col[ET];

// ---------------- graph build: counting sort by dst ----------------
__global__ void k_zero_counts() {
    int i = blockIdx.x * blockDim.x + threadIdx.x;
    if (i < N_NODES) { g_cnt[i] = 0; g_fill[i] = 0; }
}

__global__ void k_count(const int* __restrict__ ei) {
    int i = blockIdx.x * blockDim.x + threadIdx.x;
    if (i >= ET) return;
    int d = (i < N_EDGES) ? ei[N_EDGES + i] : (i - N_EDGES);
    atomicAdd(&g_cnt[d], 1);
}

__global__ void k_scan() {
    __shared__ int tmp[1024];
    __shared__ int carry;
    int t = threadIdx.x;
    if (t == 0) { carry = 0; g_rowptr[0] = 0; }
    __syncthreads();
    for (int base = 0; base < N_NODES; base += 1024) {
        int v = (base + t < N_NODES) ? g_cnt[base + t] : 0;
        tmp[t] = v;
        __syncthreads();
        for (int off = 1; off < 1024; off <<= 1) {
            int add = (t >= off) ? tmp[t - off] : 0;
            __syncthreads();
            tmp[t] += add;
            __syncthreads();
        }
        if (base + t < N_NODES) g_rowptr[base + t + 1] = carry + tmp[t];
        __syncthreads();
        if (t == 0) carry += tmp[1023];
        __syncthreads();
    }
}

__global__ void k_scatter(const int* __restrict__ ei) {
    int i = blockIdx.x * blockDim.x + threadIdx.x;
    if (i >= ET) return;
    int s, d;
    if (i < N_EDGES) { s = ei[i]; d = ei[N_EDGES + i]; }
    else             { s = d = i - N_EDGES; }
    int pos = g_rowptr[d] + atomicAdd(&g_fill[d], 1);
    g_col[pos] = s;
}

// ---------------- SGEMM: C[M,N] = A[M,K] * B[N,K]^T ----------------
// 128x64 block tile, BK=16, 256 threads, 8x4 micro-tile per thread.
__global__ void sgemm_tn(const float* __restrict__ A, const float* __restrict__ B,
                         float* __restrict__ C, int M, int N, int K) {
    const int BM = 128, BN = 64, BK = 16;
    __shared__ float As[BK][BM + 4];
    __shared__ float Bs[BK][BN + 4];
    int bm = blockIdx.y * BM, bn = blockIdx.x * BN;
    int t = threadIdx.x;
    int tx = t & 15, ty = t >> 4;
    float acc[8][4];
#pragma unroll
    for (int i = 0; i < 8; i++)
#pragma unroll
        for (int j = 0; j < 4; j++) acc[i][j] = 0.f;

    for (int k0 = 0; k0 < K; k0 += BK) {
#pragma unroll
        for (int i = 0; i < 8; i++) {           // A tile: 128*16 / 256 = 8 each
            int idx = t + i * 256;
            int r = idx >> 4, kk = idx & 15;
            int gr = bm + r, gk = k0 + kk;
            As[kk][r] = (gr < M && gk < K) ? A[(size_t)gr * K + gk] : 0.f;
        }
#pragma unroll
        for (int i = 0; i < 4; i++) {           // B tile: 64*16 / 256 = 4 each
            int idx = t + i * 256;
            int r = idx >> 4, kk = idx & 15;
            int gr = bn + r, gk = k0 + kk;
            Bs[kk][r] = (gr < N && gk < K) ? B[(size_t)gr * K + gk] : 0.f;
        }
        __syncthreads();
#pragma unroll
        for (int kk = 0; kk < BK; kk++) {
            float a[8], b[4];
#pragma unroll
            for (int i = 0; i < 8; i++) a[i] = As[kk][ty * 8 + i];
#pragma unroll
            for (int j = 0; j < 4; j++) b[j] = Bs[kk][tx * 4 + j];
#pragma unroll
            for (int i = 0; i < 8; i++)
#pragma unroll
                for (int j = 0; j < 4; j++) acc[i][j] = fmaf(a[i], b[j], acc[i][j]);
        }
        __syncthreads();
    }
#pragma unroll
    for (int i = 0; i < 8; i++) {
        int r = bm + ty * 8 + i;
        if (r >= M) continue;
#pragma unroll
        for (int j = 0; j < 4; j++) {
            int c = bn + tx * 4 + j;
            if (c < N) C[(size_t)r * N + c] = acc[i][j];
        }
    }
}

// ---------------- attention logits: alpha_src / alpha_dst ----------------
template <int H>
__global__ void k_alpha(const float* __restrict__ a_s, const float* __restrict__ a_d) {
    int gw = (blockIdx.x * blockDim.x + threadIdx.x) >> 5;
    int lane = threadIdx.x & 31;
    if (gw >= N_NODES * H) return;
    int n = gw / H, h = gw - n * H;
    const float* row = g_h + (size_t)n * (H * 256) + h * 256;
    float ss = 0.f, sd = 0.f;
    for (int c = lane; c < 256; c += 32) {
        float v = row[c];
        ss = fmaf(v, a_s[h * 256 + c], ss);
        sd = fmaf(v, a_d[h * 256 + c], sd);
    }
#pragma unroll
    for (int o = 16; o; o >>= 1) {
        ss += __shfl_xor_sync(0xffffffffu, ss, o);
        sd += __shfl_xor_sync(0xffffffffu, sd, o);
    }
    if (lane == 0) { g_as[n * H + h] = ss; g_ad[n * H + h] = sd; }
}

__device__ __forceinline__ float lrelu(float x) { return x > 0.f ? x : 0.2f * x; }

// ---------------- fused segment-softmax + aggregation + epilogue ----------------
// One block of 256 threads per dst node; thread t owns channel t of every head.
template <int H, bool MEAN, bool APPLY_ELU>
__global__ void gat_agg(const float* __restrict__ bgat, const float* __restrict__ lb,
                        float* __restrict__ out) {
    int n = blockIdx.x;
    int t = threadIdx.x;
    int start = g_rowptr[n];
    int deg = g_rowptr[n + 1] - start;

    __shared__ float s_m[H], s_dinv[H];
    int w = t >> 5, lane = t & 31;
    if (w < H) {                               // warp w handles head w
        float ad = g_ad[n * H + w];
        float mx = -1e30f;
        for (int j = lane; j < deg; j += 32)
            mx = fmaxf(mx, lrelu(g_as[g_col[start + j] * H + w] + ad));
#pragma unroll
        for (int o = 16; o; o >>= 1) mx = fmaxf(mx, __shfl_xor_sync(0xffffffffu, mx, o));
        float sum = 0.f;
        for (int j = lane; j < deg; j += 32)
            sum += __expf(lrelu(g_as[g_col[start + j] * H + w] + ad) - mx);
#pragma unroll
        for (int o = 16; o; o >>= 1) sum += __shfl_xor_sync(0xffffffffu, sum, o);
        if (lane == 0) { s_m[w] = mx; s_dinv[w] = 1.f / (sum + 1e-16f); }
    }
    __syncthreads();

    const int CH = 32;
    __shared__ float s_coef[CH][H];
    __shared__ int   s_src[CH];
    float acc[H];
#pragma unroll
    for (int h = 0; h < H; h++) acc[h] = 0.f;

    for (int cs = 0; cs < deg; cs += CH) {
        int cnt = min(CH, deg - cs);
        if (t < cnt) s_src[t] = g_col[start + cs + t];
        for (int idx = t; idx < cnt * H; idx += 256) {
            int j = idx / H, h = idx - j * H;
            int s = g_col[start + cs + j];
            float ee = lrelu(g_as[s * H + h] + g_ad[n * H + h]);
            s_coef[j][h] = __expf(ee - s_m[h]) * s_dinv[h];
        }
        __syncthreads();
        for (int j = 0; j < cnt; j++) {
            const float* row = g_h + (size_t)s_src[j] * (H * 256) + t;
#pragma unroll
            for (int h = 0; h < H; h++)
                acc[h] = fmaf(row[h * 256], s_coef[j][h], acc[h]);
        }
        __syncthreads();
    }

    if (MEAN) {
        float v = 0.f;
#pragma unroll
        for (int h = 0; h < H; h++) v += acc[h];
        v = v * (1.f / (float)H) + bgat[t] + g_lin[(size_t)n * 256 + t] + lb[t];
        out[(size_t)n * 256 + t] = v;
    } else {
#pragma unroll
        for (int h = 0; h < H; h++) {
            int c = h * 256 + t;
            float v = acc[h] + bgat[c] + g_lin[(size_t)n * 1024 + c] + lb[c];
            if (APPLY_ELU) v = v > 0.f ? v : (__expf(v) - 1.f);
            out[(size_t)n * 1024 + c] = v;
        }
    }
}

// ---------------- host launcher ----------------
static inline void run_gemm(const float* A, const float* B, float* C, int M, int N, int K) {
    dim3 grid((N + 63) / 64, (M + 127) / 128);
    sgemm_tn<<<grid, 256>>>(A, B, C, M, N, K);
}

extern "C" void kernel_launch(void* const* d_in, const int* in_sizes, int n_in,
                              void* d_out, int out_size) {
    const float* x   = (const float*)d_in[0];
    const int*   ei  = (const int*)d_in[1];
    const float* W1  = (const float*)d_in[2];
    const float* a1s = (const float*)d_in[3];
    const float* a1d = (const float*)d_in[4];
    const float* b1  = (const float*)d_in[5];
    const float* lw1 = (const float*)d_in[6];
    const float* lb1 = (const float*)d_in[7];
    const float* W2  = (const float*)d_in[8];
    const float* a2s = (const float*)d_in[9];
    const float* a2d = (const float*)d_in[10];
    const float* b2  = (const float*)d_in[11];
    const float* lw2 = (const float*)d_in[12];
    const float* lb2 = (const float*)d_in[13];
    const float* W3  = (const float*)d_in[14];
    const float* a3s = (const float*)d_in[15];
    const float* a3d = (const float*)d_in[16];
    const float* b3  = (const float*)d_in[17];
    const float* lw3 = (const float*)d_in[18];
    const float* lb3 = (const float*)d_in[19];
    float* out = (float*)d_out;

    void *p_h, *p_lin, *p_x1, *p_x2;
    cudaGetSymbolAddress(&p_h, g_h);
    cudaGetSymbolAddress(&p_lin, g_lin);
    cudaGetSymbolAddress(&p_x1, g_x1);
    cudaGetSymbolAddress(&p_x2, g_x2);
    float* h   = (float*)p_h;
    float* lin = (float*)p_lin;
    float* x1  = (float*)p_x1;
    float* x2  = (float*)p_x2;

    // build CSR by dst (edges + self-loops)
    k_zero_counts<<<(N_NODES + 255) / 256, 256>>>();
    k_count<<<(ET + 255) / 256, 256>>>(ei);
    k_scan<<<1, 1024>>>();
    k_scatter<<<(ET + 255) / 256, 256>>>(ei);

    // ---- layer 1: 14 -> 4x256, concat, +skip, ELU ----
    run_gemm(x, W1, h, N_NODES, 1024, 14);
    run_gemm(x, lw1, lin, N_NODES, 1024, 14);
    k_alpha<4><<<(N_NODES * 4 * 32 + 255) / 256, 256>>>(a1s, a1d);
    gat_agg<4, false, true><<<N_NODES, 256>>>(b1, lb1, x1);

    // ---- layer 2: 1024 -> 4x256, concat, +skip, ELU ----
    run_gemm(x1, W2, h, N_NODES, 1024, 1024);
    run_gemm(x1, lw2, lin, N_NODES, 1024, 1024);
    k_alpha<4><<<(N_NODES * 4 * 32 + 255) / 256, 256>>>(a2s, a2d);
    gat_agg<4, false, true><<<N_NODES, 256>>>(b2, lb2, x2);

    // ---- layer 3: 1024 -> mean of 6x256, +skip, no ELU ----
    run_gemm(x2, W3, h, N_NODES, 1536, 1024);
    run_gemm(x2, lw3, lin, N_NODES, 256, 1024);
    k_alpha<6><<<(N_NODES * 6 * 32 + 255) / 256, 256>>>(a3s, a3d);
    gat_agg<6, true, false><<<N_NODES, 256>>>(b3, lb3, out);
}

// round 2
// speedup vs baseline: 2.1646x; 2.1646x over previous
#include <cuda_runtime.h>
#include <math.h>
#include <stdint.h>

#define N_NODES 10000
#define N_EDGES 160000
#define ET (N_EDGES + N_NODES)

// ---------------- scratch (static __device__, no allocations) ----------------
__device__ float g_h[(size_t)N_NODES * 1536];   // GAT linear output (max 6 heads * 256)
__device__ float g_lin[(size_t)N_NODES * 1024]; // skip-linear output
__device__ float g_x1[(size_t)N_NODES * 1024];
__device__ float g_x2[(size_t)N_NODES * 1024];
__device__ float g_as[N_NODES * 6];
__device__ float g_ad[N_NODES * 6];
__device__ int   g_rowptr[N_NODES + 1];
__device__ int   g_cnt[N_NODES];
__device__ int   g_fill[N_NODES];
__device__ int   g_col[ET];

// ---------------- graph build: counting sort by dst ----------------
__global__ void k_zero_counts() {
    int i = blockIdx.x * blockDim.x + threadIdx.x;
    if (i < N_NODES) { g_cnt[i] = 0; g_fill[i] = 0; }
}

__global__ void k_count(const int* __restrict__ ei) {
    int i = blockIdx.x * blockDim.x + threadIdx.x;
    if (i >= ET) return;
    int d = (i < N_EDGES) ? ei[N_EDGES + i] : (i - N_EDGES);
    atomicAdd(&g_cnt[d], 1);
}

__global__ void k_scan() {
    __shared__ int tmp[1024];
    __shared__ int carry;
    int t = threadIdx.x;
    if (t == 0) { carry = 0; g_rowptr[0] = 0; }
    __syncthreads();
    for (int base = 0; base < N_NODES; base += 1024) {
        int v = (base + t < N_NODES) ? g_cnt[base + t] : 0;
        tmp[t] = v;
        __syncthreads();
        for (int off = 1; off < 1024; off <<= 1) {
            int add = (t >= off) ? tmp[t - off] : 0;
            __syncthreads();
            tmp[t] += add;
            __syncthreads();
        }
        if (base + t < N_NODES) g_rowptr[base + t + 1] = carry + tmp[t];
        __syncthreads();
        if (t == 0) carry += tmp[1023];
        __syncthreads();
    }
}

__global__ void k_scatter(const int* __restrict__ ei) {
    int i = blockIdx.x * blockDim.x + threadIdx.x;
    if (i >= ET) return;
    int s, d;
    if (i < N_EDGES) { s = ei[i]; d = ei[N_EDGES + i]; }
    else             { s = d = i - N_EDGES; }
    int pos = g_rowptr[d] + atomicAdd(&g_fill[d], 1);
    g_col[pos] = s;
}

// ---------------- scalar SGEMM (layer 1 only, K=14) ----------------
__global__ void sgemm_tn(const float* __restrict__ A, const float* __restrict__ B,
                         float* __restrict__ C, int M, int N, int K) {
    const int BM = 128, BN = 64, BK = 16;
    __shared__ float As[BK][BM + 4];
    __shared__ float Bs[BK][BN + 4];
    int bm = blockIdx.y * BM, bn = blockIdx.x * BN;
    int t = threadIdx.x;
    int tx = t & 15, ty = t >> 4;
    float acc[8][4];
#pragma unroll
    for (int i = 0; i < 8; i++)
#pragma unroll
        for (int j = 0; j < 4; j++) acc[i][j] = 0.f;

    for (int k0 = 0; k0 < K; k0 += BK) {
#pragma unroll
        for (int i = 0; i < 8; i++) {
            int idx = t + i * 256;
            int r = idx >> 4, kk = idx & 15;
            int gr = bm + r, gk = k0 + kk;
            As[kk][r] = (gr < M && gk < K) ? A[(size_t)gr * K + gk] : 0.f;
        }
#pragma unroll
        for (int i = 0; i < 4; i++) {
            int idx = t + i * 256;
            int r = idx >> 4, kk = idx & 15;
            int gr = bn + r, gk = k0 + kk;
            Bs[kk][r] = (gr < N && gk < K) ? B[(size_t)gr * K + gk] : 0.f;
        }
        __syncthreads();
#pragma unroll
        for (int kk = 0; kk < BK; kk++) {
            float a[8], b[4];
#pragma unroll
            for (int i = 0; i < 8; i++) a[i] = As[kk][ty * 8 + i];
#pragma unroll
            for (int j = 0; j < 4; j++) b[j] = Bs[kk][tx * 4 + j];
#pragma unroll
            for (int i = 0; i < 8; i++)
#pragma unroll
                for (int j = 0; j < 4; j++) acc[i][j] = fmaf(a[i], b[j], acc[i][j]);
        }
        __syncthreads();
    }
#pragma unroll
    for (int i = 0; i < 8; i++) {
        int r = bm + ty * 8 + i;
        if (r >= M) continue;
#pragma unroll
        for (int j = 0; j < 4; j++) {
            int c = bn + tx * 4 + j;
            if (c < N) C[(size_t)r * N + c] = acc[i][j];
        }
    }
}

// ---------------- tf32 tensor-core GEMM: C[M,N] = A[M,K] * B[N,K]^T ----------------
// Requires K % 16 == 0. 128x128 block tile, BK=16, 256 threads (8 warps),
// warp tile 64x32 via 4x4 grid of m16n8k8 tf32 mma. Double-buffered smem.
#define TBM 128
#define TBN 128
#define TBK 16
#define TPAD 4   // smem row stride 20 floats -> conflict-free fragment loads

__device__ __forceinline__ uint32_t f2tf32(float x) {
    uint32_t r;
    asm("cvt.rna.tf32.f32 %0, %1;" : "=r"(r) : "f"(x));
    return r;
}

__device__ __forceinline__ void mma_tf32(float c[4], const uint32_t a[4], const uint32_t b[2]) {
    asm volatile(
        "mma.sync.aligned.m16n8k8.row.col.f32.tf32.tf32.f32 "
        "{%0,%1,%2,%3}, {%4,%5,%6,%7}, {%8,%9}, {%0,%1,%2,%3};"
        : "+f"(c[0]), "+f"(c[1]), "+f"(c[2]), "+f"(c[3])
        : "r"(a[0]), "r"(a[1]), "r"(a[2]), "r"(a[3]), "r"(b[0]), "r"(b[1]));
}

__global__ __launch_bounds__(256, 2)
void gemm_tf32(const float* __restrict__ A, const float* __restrict__ B,
               float* __restrict__ C, int M, int N, int K) {
    __shared__ uint32_t As[2][TBM][TBK + TPAD];   // 2*128*20*4 = 20 KB
    __shared__ uint32_t Bs[2][TBN][TBK + TPAD];   // 20 KB

    const int bm = blockIdx.y * TBM, bn = blockIdx.x * TBN;
    const int t = threadIdx.x;
    const int w = t >> 5, lane = t & 31;
    const int wm = (w >> 2) * 64;      // warp M offset within block (0/64)
    const int wn = (w & 3) * 32;       // warp N offset (0/32/64/96)
    const int g = lane >> 2;           // group id 0..7
    const int r = lane & 3;            // thread-in-group 0..3

    float acc[4][4][4];
#pragma unroll
    for (int mi = 0; mi < 4; mi++)
#pragma unroll
        for (int ni = 0; ni < 4; ni++)
#pragma unroll
            for (int q = 0; q < 4; q++) acc[mi][ni][q] = 0.f;

    const int nIter = K / TBK;

    // prologue: load tile 0
    {
        const int k0 = 0;
#pragma unroll
        for (int i = 0; i < 2; i++) {
            int idx = t + i * 256;
            int row = idx >> 2, c4 = (idx & 3) * 4;
            int gr = bm + row;
            float4 v = make_float4(0.f, 0.f, 0.f, 0.f);
            if (gr < M) v = *reinterpret_cast<const float4*>(A + (size_t)gr * K + k0 + c4);
            As[0][row][c4 + 0] = f2tf32(v.x);
            As[0][row][c4 + 1] = f2tf32(v.y);
            As[0][row][c4 + 2] = f2tf32(v.z);
            As[0][row][c4 + 3] = f2tf32(v.w);
            int gn = bn + row;
            float4 u = make_float4(0.f, 0.f, 0.f, 0.f);
            if (gn < N) u = *reinterpret_cast<const float4*>(B + (size_t)gn * K + k0 + c4);
            Bs[0][row][c4 + 0] = f2tf32(u.x);
            Bs[0][row][c4 + 1] = f2tf32(u.y);
            Bs[0][row][c4 + 2] = f2tf32(u.z);
            Bs[0][row][c4 + 3] = f2tf32(u.w);
        }
    }
    __syncthreads();

    for (int it = 0; it < nIter; it++) {
        const int buf = it & 1;
        // prefetch next tile into the other buffer
        if (it + 1 < nIter) {
            const int k0 = (it + 1) * TBK;
            const int nb = buf ^ 1;
#pragma unroll
            for (int i = 0; i < 2; i++) {
                int idx = t + i * 256;
                int row = idx >> 2, c4 = (idx & 3) * 4;
                int gr = bm + row;
                float4 v = make_float4(0.f, 0.f, 0.f, 0.f);
                if (gr < M) v = *reinterpret_cast<const float4*>(A + (size_t)gr * K + k0 + c4);
                As[nb][row][c4 + 0] = f2tf32(v.x);
                As[nb][row][c4 + 1] = f2tf32(v.y);
                As[nb][row][c4 + 2] = f2tf32(v.z);
                As[nb][row][c4 + 3] = f2tf32(v.w);
                int gn = bn + row;
                float4 u = make_float4(0.f, 0.f, 0.f, 0.f);
                if (gn < N) u = *reinterpret_cast<const float4*>(B + (size_t)gn * K + k0 + c4);
                Bs[nb][row][c4 + 0] = f2tf32(u.x);
                Bs[nb][row][c4 + 1] = f2tf32(u.y);
                Bs[nb][row][c4 + 2] = f2tf32(u.z);
                Bs[nb][row][c4 + 3] = f2tf32(u.w);
            }
        }
        // compute on current buffer: 2 k-subtiles of 8
#pragma unroll
        for (int ks = 0; ks < 2; ks++) {
            const int kb = ks * 8;
            uint32_t af[4][4];
            uint32_t bf[4][2];
#pragma unroll
            for (int mi = 0; mi < 4; mi++) {
                int row = wm + mi * 16 + g;
                af[mi][0] = As[buf][row][kb + r];
                af[mi][1] = As[buf][row + 8][kb + r];
                af[mi][2] = As[buf][row][kb + r + 4];
                af[mi][3] = As[buf][row + 8][kb + r + 4];
            }
#pragma unroll
            for (int ni = 0; ni < 4; ni++) {
                int col = wn + ni * 8 + g;
                bf[ni][0] = Bs[buf][col][kb + r];
                bf[ni][1] = Bs[buf][col][kb + r + 4];
            }
#pragma unroll
            for (int mi = 0; mi < 4; mi++)
#pragma unroll
                for (int ni = 0; ni < 4; ni++)
                    mma_tf32(acc[mi][ni], af[mi], bf[ni]);
        }
        __syncthreads();
    }

    // epilogue
#pragma unroll
    for (int mi = 0; mi < 4; mi++) {
        int row0 = bm + wm + mi * 16 + g;
        int row1 = row0 + 8;
#pragma unroll
        for (int ni = 0; ni < 4; ni++) {
            int col = bn + wn + ni * 8 + 2 * r;
            if (row0 < M) {
                C[(size_t)row0 * N + col]     = acc[mi][ni][0];
                C[(size_t)row0 * N + col + 1] = acc[mi][ni][1];
            }
            if (row1 < M) {
                C[(size_t)row1 * N + col]     = acc[mi][ni][2];
                C[(size_t)row1 * N + col + 1] = acc[mi][ni][3];
            }
        }
    }
}

// ---------------- attention logits: alpha_src / alpha_dst ----------------
template <int H>
__global__ void k_alpha(const float* __restrict__ a_s, const float* __restrict__ a_d) {
    int gw = (blockIdx.x * blockDim.x + threadIdx.x) >> 5;
    int lane = threadIdx.x & 31;
    if (gw >= N_NODES * H) return;
    int n = gw / H, h = gw - n * H;
    const float* row = g_h + (size_t)n * (H * 256) + h * 256;
    float ss = 0.f, sd = 0.f;
    for (int c = lane; c < 256; c += 32) {
        float v = row[c];
        ss = fmaf(v, a_s[h * 256 + c], ss);
        sd = fmaf(v, a_d[h * 256 + c], sd);
    }
#pragma unroll
    for (int o = 16; o; o >>= 1) {
        ss += __shfl_xor_sync(0xffffffffu, ss, o);
        sd += __shfl_xor_sync(0xffffffffu, sd, o);
    }
    if (lane == 0) { g_as[n * H + h] = ss; g_ad[n * H + h] = sd; }
}

__device__ __forceinline__ float lrelu(float x) { return x > 0.f ? x : 0.2f * x; }

// ---------------- fused segment-softmax + aggregation + epilogue ----------------
template <int H, bool MEAN, bool APPLY_ELU>
__global__ void gat_agg(const float* __restrict__ bgat, const float* __restrict__ lb,
                        float* __restrict__ out) {
    int n = blockIdx.x;
    int t = threadIdx.x;
    int start = g_rowptr[n];
    int deg = g_rowptr[n + 1] - start;

    __shared__ float s_m[H], s_dinv[H];
    int w = t >> 5, lane = t & 31;
    if (w < H) {
        float ad = g_ad[n * H + w];
        float mx = -1e30f;
        for (int j = lane; j < deg; j += 32)
            mx = fmaxf(mx, lrelu(g_as[g_col[start + j] * H + w] + ad));
#pragma unroll
        for (int o = 16; o; o >>= 1) mx = fmaxf(mx, __shfl_xor_sync(0xffffffffu, mx, o));
        float sum = 0.f;
        for (int j = lane; j < deg; j += 32)
            sum += __expf(lrelu(g_as[g_col[start + j] * H + w] + ad) - mx);
#pragma unroll
        for (int o = 16; o; o >>= 1) sum += __shfl_xor_sync(0xffffffffu, sum, o);
        if (lane == 0) { s_m[w] = mx; s_dinv[w] = 1.f / (sum + 1e-16f); }
    }
    __syncthreads();

    const int CH = 32;
    __shared__ float s_coef[CH][H];
    __shared__ int   s_src[CH];
    float acc[H];
#pragma unroll
    for (int h = 0; h < H; h++) acc[h] = 0.f;

    for (int cs = 0; cs < deg; cs += CH) {
        int cnt = min(CH, deg - cs);
        if (t < cnt) s_src[t] = g_col[start + cs + t];
        for (int idx = t; idx < cnt * H; idx += 256) {
            int j = idx / H, h = idx - j * H;
            int s = g_col[start + cs + j];
            float ee = lrelu(g_as[s * H + h] + g_ad[n * H + h]);
            s_coef[j][h] = __expf(ee - s_m[h]) * s_dinv[h];
        }
        __syncthreads();
        for (int j = 0; j < cnt; j++) {
            const float* row = g_h + (size_t)s_src[j] * (H * 256) + t;
#pragma unroll
            for (int h = 0; h < H; h++)
                acc[h] = fmaf(row[h * 256], s_coef[j][h], acc[h]);
        }
        __syncthreads();
    }

    if (MEAN) {
        float v = 0.f;
#pragma unroll
        for (int h = 0; h < H; h++) v += acc[h];
        v = v * (1.f / (float)H) + bgat[t] + g_lin[(size_t)n * 256 + t] + lb[t];
        out[(size_t)n * 256 + t] = v;
    } else {
#pragma unroll
        for (int h = 0; h < H; h++) {
            int c = h * 256 + t;
            float v = acc[h] + bgat[c] + g_lin[(size_t)n * 1024 + c] + lb[c];
            if (APPLY_ELU) v = v > 0.f ? v : (__expf(v) - 1.f);
            out[(size_t)n * 1024 + c] = v;
        }
    }
}

// ---------------- host launcher ----------------
static inline void run_gemm_sc(const float* A, const float* B, float* C, int M, int N, int K) {
    dim3 grid((N + 63) / 64, (M + 127) / 128);
    sgemm_tn<<<grid, 256>>>(A, B, C, M, N, K);
}

static inline void run_gemm_tc(const float* A, const float* B, float* C, int M, int N, int K) {
    dim3 grid((N + TBN - 1) / TBN, (M + TBM - 1) / TBM);
    gemm_tf32<<<grid, 256>>>(A, B, C, M, N, K);
}

extern "C" void kernel_launch(void* const* d_in, const int* in_sizes, int n_in,
                              void* d_out, int out_size) {
    const float* x   = (const float*)d_in[0];
    const int*   ei  = (const int*)d_in[1];
    const float* W1  = (const float*)d_in[2];
    const float* a1s = (const float*)d_in[3];
    const float* a1d = (const float*)d_in[4];
    const float* b1  = (const float*)d_in[5];
    const float* lw1 = (const float*)d_in[6];
    const float* lb1 = (const float*)d_in[7];
    const float* W2  = (const float*)d_in[8];
    const float* a2s = (const float*)d_in[9];
    const float* a2d = (const float*)d_in[10];
    const float* b2  = (const float*)d_in[11];
    const float* lw2 = (const float*)d_in[12];
    const float* lb2 = (const float*)d_in[13];
    const float* W3  = (const float*)d_in[14];
    const float* a3s = (const float*)d_in[15];
    const float* a3d = (const float*)d_in[16];
    const float* b3  = (const float*)d_in[17];
    const float* lw3 = (const float*)d_in[18];
    const float* lb3 = (const float*)d_in[19];
    float* out = (float*)d_out;

    void *p_h, *p_lin, *p_x1, *p_x2;
    cudaGetSymbolAddress(&p_h, g_h);
    cudaGetSymbolAddress(&p_lin, g_lin);
    cudaGetSymbolAddress(&p_x1, g_x1);
    cudaGetSymbolAddress(&p_x2, g_x2);
    float* h   = (float*)p_h;
    float* lin = (float*)p_lin;
    float* x1  = (float*)p_x1;
    float* x2  = (float*)p_x2;

    // build CSR by dst (edges + self-loops)
    k_zero_counts<<<(N_NODES + 255) / 256, 256>>>();
    k_count<<<(ET + 255) / 256, 256>>>(ei);
    k_scan<<<1, 1024>>>();
    k_scatter<<<(ET + 255) / 256, 256>>>(ei);

    // ---- layer 1: 14 -> 4x256, concat, +skip, ELU ----
    run_gemm_sc(x, W1, h, N_NODES, 1024, 14);
    run_gemm_sc(x, lw1, lin, N_NODES, 1024, 14);
    k_alpha<4><<<(N_NODES * 4 * 32 + 255) / 256, 256>>>(a1s, a1d);
    gat_agg<4, false, true><<<N_NODES, 256>>>(b1, lb1, x1);

    // ---- layer 2: 1024 -> 4x256, concat, +skip, ELU ----
    run_gemm_tc(x1, W2, h, N_NODES, 1024, 1024);
    run_gemm_tc(x1, lw2, lin, N_NODES, 1024, 1024);
    k_alpha<4><<<(N_NODES * 4 * 32 + 255) / 256, 256>>>(a2s, a2d);
    gat_agg<4, false, true><<<N_NODES, 256>>>(b2, lb2, x2);

    // ---- layer 3: 1024 -> mean of 6x256, +skip, no ELU ----
    run_gemm_tc(x2, W3, h, N_NODES, 1536, 1024);
    run_gemm_tc(x2, lw3, lin, N_NODES, 256, 1024);
    k_alpha<6><<<(N_NODES * 6 * 32 + 255) / 256, 256>>>(a3s, a3d);
    gat_agg<6, true, false><<<N_NODES, 256>>>(b3, lb3, out);
}

// round 3
// speedup vs baseline: 2.3730x; 1.0963x over previous
#include <cuda_runtime.h>
#include <math.h>
#include <stdint.h>

#define N_NODES 10000
#define N_EDGES 160000
#define ET (N_EDGES + N_NODES)

// ---------------- scratch (static __device__, no allocations) ----------------
__device__ float g_h[(size_t)N_NODES * 1536];
__device__ float g_lin[(size_t)N_NODES * 1024];
__device__ float g_x1[(size_t)N_NODES * 1024];
__device__ float g_x2[(size_t)N_NODES * 1024];
__device__ float g_as[N_NODES * 6];
__device__ float g_ad[N_NODES * 6];
__device__ int   g_rowptr[N_NODES + 1];
__device__ int   g_cnt[N_NODES];
__device__ int   g_fill[N_NODES];
__device__ int   g_col[ET];

// ---------------- graph build ----------------
__global__ void k_zero_counts() {
    int i = blockIdx.x * blockDim.x + threadIdx.x;
    if (i < N_NODES) { g_cnt[i] = 0; g_fill[i] = 0; }
}
__global__ void k_count(const int* __restrict__ ei) {
    int i = blockIdx.x * blockDim.x + threadIdx.x;
    if (i >= ET) return;
    int d = (i < N_EDGES) ? ei[N_EDGES + i] : (i - N_EDGES);
    atomicAdd(&g_cnt[d], 1);
}
__global__ void k_scan() {
    __shared__ int tmp[1024];
    __shared__ int carry;
    int t = threadIdx.x;
    if (t == 0) { carry = 0; g_rowptr[0] = 0; }
    __syncthreads();
    for (int base = 0; base < N_NODES; base += 1024) {
        int v = (base + t < N_NODES) ? g_cnt[base + t] : 0;
        tmp[t] = v;
        __syncthreads();
        for (int off = 1; off < 1024; off <<= 1) {
            int add = (t >= off) ? tmp[t - off] : 0;
            __syncthreads();
            tmp[t] += add;
            __syncthreads();
        }
        if (base + t < N_NODES) g_rowptr[base + t + 1] = carry + tmp[t];
        __syncthreads();
        if (t == 0) carry += tmp[1023];
        __syncthreads();
    }
}
__global__ void k_scatter(const int* __restrict__ ei) {
    int i = blockIdx.x * blockDim.x + threadIdx.x;
    if (i >= ET) return;
    int s, d;
    if (i < N_EDGES) { s = ei[i]; d = ei[N_EDGES + i]; }
    else             { s = d = i - N_EDGES; }
    int pos = g_rowptr[d] + atomicAdd(&g_fill[d], 1);
    g_col[pos] = s;
}

// ---------------- scalar SGEMM (layer 1, K=14) ----------------
__global__ void sgemm_tn(const float* __restrict__ A, const float* __restrict__ B,
                         float* __restrict__ C, int M, int N, int K) {
    const int BM = 128, BN = 64, BK = 16;
    __shared__ float As[BK][BM + 4];
    __shared__ float Bs[BK][BN + 4];
    int bm = blockIdx.y * BM, bn = blockIdx.x * BN;
    int t = threadIdx.x;
    int tx = t & 15, ty = t >> 4;
    float acc[8][4];
#pragma unroll
    for (int i = 0; i < 8; i++)
#pragma unroll
        for (int j = 0; j < 4; j++) acc[i][j] = 0.f;
    for (int k0 = 0; k0 < K; k0 += BK) {
#pragma unroll
        for (int i = 0; i < 8; i++) {
            int idx = t + i * 256;
            int r = idx >> 4, kk = idx & 15;
            int gr = bm + r, gk = k0 + kk;
            As[kk][r] = (gr < M && gk < K) ? A[(size_t)gr * K + gk] : 0.f;
        }
#pragma unroll
        for (int i = 0; i < 4; i++) {
            int idx = t + i * 256;
            int r = idx >> 4, kk = idx & 15;
            int gr = bn + r, gk = k0 + kk;
            Bs[kk][r] = (gr < N && gk < K) ? B[(size_t)gr * K + gk] : 0.f;
        }
        __syncthreads();
#pragma unroll
        for (int kk = 0; kk < BK; kk++) {
            float a[8], b[4];
#pragma unroll
            for (int i = 0; i < 8; i++) a[i] = As[kk][ty * 8 + i];
#pragma unroll
            for (int j = 0; j < 4; j++) b[j] = Bs[kk][tx * 4 + j];
#pragma unroll
            for (int i = 0; i < 8; i++)
#pragma unroll
                for (int j = 0; j < 4; j++) acc[i][j] = fmaf(a[i], b[j], acc[i][j]);
        }
        __syncthreads();
    }
#pragma unroll
    for (int i = 0; i < 8; i++) {
        int r = bm + ty * 8 + i;
        if (r >= M) continue;
#pragma unroll
        for (int j = 0; j < 4; j++) {
            int c = bn + tx * 4 + j;
            if (c < N) C[(size_t)r * N + c] = acc[i][j];
        }
    }
}

// ---------------- tf32 TC GEMM: C[M,N] = A[M,K]*B[N,K]^T, K%16==0, N%128==0 ----
// 128x128 block, 4 warps (128 thr), warp tile 64x64.
// cp.async double buffer, ldmatrix fragment loads, cvt.rna on fragments.
#define GBK 16
#define GSTRIDE 20          // floats per smem row (16 + 4 pad), 80B: 16B-aligned

__device__ __forceinline__ uint32_t f2tf32(float x) {
    uint32_t r;
    asm("cvt.rna.tf32.f32 %0, %1;" : "=r"(r) : "f"(x));
    return r;
}
__device__ __forceinline__ void mma_tf32(float c[4], const uint32_t a[4], const uint32_t b[2]) {
    asm volatile(
        "mma.sync.aligned.m16n8k8.row.col.f32.tf32.tf32.f32 "
        "{%0,%1,%2,%3}, {%4,%5,%6,%7}, {%8,%9}, {%0,%1,%2,%3};"
        : "+f"(c[0]), "+f"(c[1]), "+f"(c[2]), "+f"(c[3])
        : "r"(a[0]), "r"(a[1]), "r"(a[2]), "r"(a[3]), "r"(b[0]), "r"(b[1]));
}
__device__ __forceinline__ void ldsm_x4(uint32_t r[4], uint32_t saddr) {
    asm volatile("ldmatrix.sync.aligned.m8n8.x4.shared.b16 {%0,%1,%2,%3}, [%4];"
                 : "=r"(r[0]), "=r"(r[1]), "=r"(r[2]), "=r"(r[3]) : "r"(saddr));
}
__device__ __forceinline__ void cp_async16(uint32_t saddr, const void* gaddr, int src_sz) {
    asm volatile("cp.async.cg.shared.global [%0], [%1], 16, %2;\n"
                 :: "r"(saddr), "l"(gaddr), "r"(src_sz));
}
__device__ __forceinline__ void cp_commit() { asm volatile("cp.async.commit_group;\n"); }
template <int N> __device__ __forceinline__ void cp_wait() {
    asm volatile("cp.async.wait_group %0;\n" :: "n"(N));
}

__global__ __launch_bounds__(128, 2)
void gemm_tf32(const float* __restrict__ A, const float* __restrict__ B,
               float* __restrict__ C, int M, int N, int K) {
    __shared__ float As[2][128][GSTRIDE];   // 20 KB
    __shared__ float Bs[2][128][GSTRIDE];   // 20 KB

    const int bm = blockIdx.y * 128, bn = blockIdx.x * 128;
    const int t = threadIdx.x;
    const int w = t >> 5, lane = t & 31;
    const int wm = (w >> 1) * 64;   // warp M offset: 0/64
    const int wn = (w & 1) * 64;    // warp N offset: 0/64
    const int g = lane >> 2;        // 0..7
    const int r = lane & 3;         // 0..3

    uint32_t sA, sB;
    {
        uint32_t base;
        asm("{ .reg .u64 tmp; cvta.to.shared.u64 tmp, %1; cvt.u32.u64 %0, tmp; }"
            : "=r"(base) : "l"(&As[0][0][0]));
        sA = base;
        asm("{ .reg .u64 tmp; cvta.to.shared.u64 tmp, %1; cvt.u32.u64 %0, tmp; }"
            : "=r"(base) : "l"(&Bs[0][0][0]));
        sB = base;
    }
    const uint32_t STAGE = 128 * GSTRIDE * 4;   // bytes per stage

    // ldmatrix lane address components
    const int sub = lane >> 3;                 // 0..3 (tile id)
    const int lrow = (sub & 1) * 8 + (lane & 7);
    const int lcol = (sub >> 1) * 4;           // 0 or 4 (k offset within subtile)
    // For B x4: tiles = {ni kb, ni+1 kb, ni kb+4, ni+1 kb+4}
    const int brow = (sub & 1) * 8 + (lane & 7);   // row within ni-pair (16 rows)

    float acc[4][8][4];
#pragma unroll
    for (int mi = 0; mi < 4; mi++)
#pragma unroll
        for (int ni = 0; ni < 8; ni++)
#pragma unroll
            for (int q = 0; q < 4; q++) acc[mi][ni][q] = 0.f;

    const int nIter = K / GBK;

    // cp.async tile loader: 1024 float4 per stage (A 512 + B 512), 8 per thread
    auto load_stage = [&](int it, int buf) {
        const int k0 = it * GBK;
#pragma unroll
        for (int i = 0; i < 8; i++) {
            int idx = t + i * 128;
            bool isA = idx < 512;
            int li = isA ? idx : idx - 512;
            int row = li >> 2, c4 = (li & 3) * 4;
            if (isA) {
                int gr = bm + row;
                const float* gp = A + (size_t)min(gr, M - 1) * K + k0 + c4;
                cp_async16(sA + buf * STAGE + (row * GSTRIDE + c4) * 4, gp, gr < M ? 16 : 0);
            } else {
                int gn = bn + row;   // N % 128 == 0 -> always in range
                const float* gp = B + (size_t)gn * K + k0 + c4;
                cp_async16(sB + buf * STAGE + (row * GSTRIDE + c4) * 4, gp, 16);
            }
        }
        cp_commit();
    };

    load_stage(0, 0);

    for (int it = 0; it < nIter; it++) {
        const int buf = it & 1;
        if (it + 1 < nIter) {
            load_stage(it + 1, buf ^ 1);
            cp_wait<1>();
        } else {
            cp_wait<0>();
        }
        __syncthreads();

#pragma unroll
        for (int ks = 0; ks < 2; ks++) {
            const int kb = ks * 8;
            uint32_t af[4][4], bf[8][2];
#pragma unroll
            for (int mi = 0; mi < 4; mi++) {
                uint32_t addr = sA + buf * STAGE +
                                ((wm + mi * 16 + lrow) * GSTRIDE + kb + lcol) * 4;
                uint32_t rr[4];
                ldsm_x4(rr, addr);
#pragma unroll
                for (int q = 0; q < 4; q++)
                    af[mi][q] = f2tf32(__uint_as_float(rr[q]));
            }
#pragma unroll
            for (int np = 0; np < 4; np++) {   // ni pair: loads ni=2np, 2np+1
                uint32_t addr = sB + buf * STAGE +
                                ((wn + np * 16 + brow) * GSTRIDE + kb + lcol) * 4;
                uint32_t rr[4];
                ldsm_x4(rr, addr);
                bf[2 * np + 0][0] = f2tf32(__uint_as_float(rr[0]));
                bf[2 * np + 1][0] = f2tf32(__uint_as_float(rr[1]));
                bf[2 * np + 0][1] = f2tf32(__uint_as_float(rr[2]));
                bf[2 * np + 1][1] = f2tf32(__uint_as_float(rr[3]));
            }
#pragma unroll
            for (int mi = 0; mi < 4; mi++)
#pragma unroll
                for (int ni = 0; ni < 8; ni++)
                    mma_tf32(acc[mi][ni], af[mi], bf[ni]);
        }
        __syncthreads();
    }

    // epilogue
#pragma unroll
    for (int mi = 0; mi < 4; mi++) {
        int row0 = bm + wm + mi * 16 + g;
        int row1 = row0 + 8;
#pragma unroll
        for (int ni = 0; ni < 8; ni++) {
            int col = bn + wn + ni * 8 + 2 * r;
            if (row0 < M)
                *reinterpret_cast<float2*>(C + (size_t)row0 * N + col) =
                    make_float2(acc[mi][ni][0], acc[mi][ni][1]);
            if (row1 < M)
                *reinterpret_cast<float2*>(C + (size_t)row1 * N + col) =
                    make_float2(acc[mi][ni][2], acc[mi][ni][3]);
        }
    }
}

// ---------------- attention logits ----------------
template <int H>
__global__ void k_alpha(const float* __restrict__ a_s, const float* __restrict__ a_d) {
    int gw = (blockIdx.x * blockDim.x + threadIdx.x) >> 5;
    int lane = threadIdx.x & 31;
    if (gw >= N_NODES * H) return;
    int n = gw / H, h = gw - n * H;
    const float* row = g_h + (size_t)n * (H * 256) + h * 256;
    float ss = 0.f, sd = 0.f;
    for (int c = lane; c < 256; c += 32) {
        float v = row[c];
        ss = fmaf(v, a_s[h * 256 + c], ss);
        sd = fmaf(v, a_d[h * 256 + c], sd);
    }
#pragma unroll
    for (int o = 16; o; o >>= 1) {
        ss += __shfl_xor_sync(0xffffffffu, ss, o);
        sd += __shfl_xor_sync(0xffffffffu, sd, o);
    }
    if (lane == 0) { g_as[n * H + h] = ss; g_ad[n * H + h] = sd; }
}

__device__ __forceinline__ float lrelu(float x) { return x > 0.f ? x : 0.2f * x; }

// ---------------- fused segment-softmax + aggregation + epilogue ----------------
template <int H, bool MEAN, bool APPLY_ELU>
__global__ void gat_agg(const float* __restrict__ bgat, const float* __restrict__ lb,
                        float* __restrict__ out) {
    int n = blockIdx.x;
    int t = threadIdx.x;
    int start = g_rowptr[n];
    int deg = g_rowptr[n + 1] - start;

    __shared__ float s_m[H], s_dinv[H];
    int w = t >> 5, lane = t & 31;
    if (w < H) {
        float ad = g_ad[n * H + w];
        float mx = -1e30f;
        for (int j = lane; j < deg; j += 32)
            mx = fmaxf(mx, lrelu(g_as[g_col[start + j] * H + w] + ad));
#pragma unroll
        for (int o = 16; o; o >>= 1) mx = fmaxf(mx, __shfl_xor_sync(0xffffffffu, mx, o));
        float sum = 0.f;
        for (int j = lane; j < deg; j += 32)
            sum += __expf(lrelu(g_as[g_col[start + j] * H + w] + ad) - mx);
#pragma unroll
        for (int o = 16; o; o >>= 1) sum += __shfl_xor_sync(0xffffffffu, sum, o);
        if (lane == 0) { s_m[w] = mx; s_dinv[w] = 1.f / (sum + 1e-16f); }
    }
    __syncthreads();

    const int CH = 32;
    __shared__ float s_coef[CH][H];
    __shared__ int   s_src[CH];
    float acc[H];
#pragma unroll
    for (int h = 0; h < H; h++) acc[h] = 0.f;

    for (int cs = 0; cs < deg; cs += CH) {
        int cnt = min(CH, deg - cs);
        if (t < cnt) s_src[t] = g_col[start + cs + t];
        for (int idx = t; idx < cnt * H; idx += 256) {
            int j = idx / H, h = idx - j * H;
            int s = g_col[start + cs + j];
            float ee = lrelu(g_as[s * H + h] + g_ad[n * H + h]);
            s_coef[j][h] = __expf(ee - s_m[h]) * s_dinv[h];
        }
        __syncthreads();
        for (int j = 0; j < cnt; j++) {
            const float* row = g_h + (size_t)s_src[j] * (H * 256) + t;
#pragma unroll
            for (int h = 0; h < H; h++)
                acc[h] = fmaf(row[h * 256], s_coef[j][h], acc[h]);
        }
        __syncthreads();
    }

    if (MEAN) {
        float v = 0.f;
#pragma unroll
        for (int h = 0; h < H; h++) v += acc[h];
        v = v * (1.f / (float)H) + bgat[t] + g_lin[(size_t)n * 256 + t] + lb[t];
        out[(size_t)n * 256 + t] = v;
    } else {
#pragma unroll
        for (int h = 0; h < H; h++) {
            int c = h * 256 + t;
            float v = acc[h] + bgat[c] + g_lin[(size_t)n * 1024 + c] + lb[c];
            if (APPLY_ELU) v = v > 0.f ? v : (__expf(v) - 1.f);
            out[(size_t)n * 1024 + c] = v;
        }
    }
}

// ---------------- host launcher ----------------
static inline void run_gemm_sc(const float* A, const float* B, float* C, int M, int N, int K) {
    dim3 grid((N + 63) / 64, (M + 127) / 128);
    sgemm_tn<<<grid, 256>>>(A, B, C, M, N, K);
}
static inline void run_gemm_tc(const float* A, const float* B, float* C, int M, int N, int K) {
    dim3 grid(N / 128, (M + 127) / 128);
    gemm_tf32<<<grid, 128>>>(A, B, C, M, N, K);
}

extern "C" void kernel_launch(void* const* d_in, const int* in_sizes, int n_in,
                              void* d_out, int out_size) {
    const float* x   = (const float*)d_in[0];
    const int*   ei  = (const int*)d_in[1];
    const float* W1  = (const float*)d_in[2];
    const float* a1s = (const float*)d_in[3];
    const float* a1d = (const float*)d_in[4];
    const float* b1  = (const float*)d_in[5];
    const float* lw1 = (const float*)d_in[6];
    const float* lb1 = (const float*)d_in[7];
    const float* W2  = (const float*)d_in[8];
    const float* a2s = (const float*)d_in[9];
    const float* a2d = (const float*)d_in[10];
    const float* b2  = (const float*)d_in[11];
    const float* lw2 = (const float*)d_in[12];
    const float* lb2 = (const float*)d_in[13];
    const float* W3  = (const float*)d_in[14];
    const float* a3s = (const float*)d_in[15];
    const float* a3d = (const float*)d_in[16];
    const float* b3  = (const float*)d_in[17];
    const float* lw3 = (const float*)d_in[18];
    const float* lb3 = (const float*)d_in[19];
    float* out = (float*)d_out;

    void *p_h, *p_lin, *p_x1, *p_x2;
    cudaGetSymbolAddress(&p_h, g_h);
    cudaGetSymbolAddress(&p_lin, g_lin);
    cudaGetSymbolAddress(&p_x1, g_x1);
    cudaGetSymbolAddress(&p_x2, g_x2);
    float* h   = (float*)p_h;
    float* lin = (float*)p_lin;
    float* x1  = (float*)p_x1;
    float* x2  = (float*)p_x2;

    // build CSR by dst (edges + self-loops)
    k_zero_counts<<<(N_NODES + 255) / 256, 256>>>();
    k_count<<<(ET + 255) / 256, 256>>>(ei);
    k_scan<<<1, 1024>>>();
    k_scatter<<<(ET + 255) / 256, 256>>>(ei);

    // ---- layer 1: 14 -> 4x256, concat, +skip, ELU ----
    run_gemm_sc(x, W1, h, N_NODES, 1024, 14);
    run_gemm_sc(x, lw1, lin, N_NODES, 1024, 14);
    k_alpha<4><<<(N_NODES * 4 * 32 + 255) / 256, 256>>>(a1s, a1d);
    gat_agg<4, false, true><<<N_NODES, 256>>>(b1, lb1, x1);

    // ---- layer 2: 1024 -> 4x256, concat, +skip, ELU ----
    run_gemm_tc(x1, W2, h, N_NODES, 1024, 1024);
    run_gemm_tc(x1, lw2, lin, N_NODES, 1024, 1024);
    k_alpha<4><<<(N_NODES * 4 * 32 + 255) / 256, 256>>>(a2s, a2d);
    gat_agg<4, false, true><<<N_NODES, 256>>>(b2, lb2, x2);

    // ---- layer 3: 1024 -> mean of 6x256, +skip, no ELU ----
    run_gemm_tc(x2, W3, h, N_NODES, 1536, 1024);
    run_gemm_tc(x2, lw3, lin, N_NODES, 256, 1024);
    k_alpha<6><<<(N_NODES * 6 * 32 + 255) / 256, 256>>>(a3s, a3d);
    gat_agg<6, true, false><<<N_NODES, 256>>>(b3, lb3, out);
}

// round 5
// speedup vs baseline: 2.8494x; 1.2007x over previous
#include <cuda_runtime.h>
#include <cuda_fp16.h>
#include <math.h>
#include <stdint.h>

#define N_NODES 10000
#define N_EDGES 160000
#define ET (N_EDGES + N_NODES)

// ---------------- scratch (static __device__, no allocations) ----------------
__device__ float  g_h[(size_t)N_NODES * 1536];
__device__ float  g_lin[(size_t)N_NODES * 1024];
__device__ __half g_x1h[(size_t)N_NODES * 1024];
__device__ __half g_x2h[(size_t)N_NODES * 1024];
__device__ __half g_w2h[1024 * 1024];
__device__ __half g_lw2h[1024 * 1024];
__device__ __half g_w3h[1536 * 1024];
__device__ __half g_lw3h[256 * 1024];
__device__ float  g_as[N_NODES * 6];
__device__ float  g_ad[N_NODES * 6];
__device__ int    g_rowptr[N_NODES + 1];
__device__ int    g_cnt[N_NODES];
__device__ int    g_fill[N_NODES];
__device__ int    g_col[ET];

// ---------------- graph build ----------------
__global__ void k_zero_counts() {
    int i = blockIdx.x * blockDim.x + threadIdx.x;
    if (i < N_NODES) { g_cnt[i] = 0; g_fill[i] = 0; }
}
__global__ void k_count(const int* __restrict__ ei) {
    int i = blockIdx.x * blockDim.x + threadIdx.x;
    if (i >= ET) return;
    int d = (i < N_EDGES) ? ei[N_EDGES + i] : (i - N_EDGES);
    atomicAdd(&g_cnt[d], 1);
}
__global__ void k_scan() {
    __shared__ int tmp[1024];
    __shared__ int carry;
    int t = threadIdx.x;
    if (t == 0) { carry = 0; g_rowptr[0] = 0; }
    __syncthreads();
    for (int base = 0; base < N_NODES; base += 1024) {
        int v = (base + t < N_NODES) ? g_cnt[base + t] : 0;
        tmp[t] = v;
        __syncthreads();
        for (int off = 1; off < 1024; off <<= 1) {
            int add = (t >= off) ? tmp[t - off] : 0;
            __syncthreads();
            tmp[t] += add;
            __syncthreads();
        }
        if (base + t < N_NODES) g_rowptr[base + t + 1] = carry + tmp[t];
        __syncthreads();
        if (t == 0) carry += tmp[1023];
        __syncthreads();
    }
}
__global__ void k_scatter(const int* __restrict__ ei) {
    int i = blockIdx.x * blockDim.x + threadIdx.x;
    if (i >= ET) return;
    int s, d;
    if (i < N_EDGES) { s = ei[i]; d = ei[N_EDGES + i]; }
    else             { s = d = i - N_EDGES; }
    int pos = g_rowptr[d] + atomicAdd(&g_fill[d], 1);
    g_col[pos] = s;
}

// ---------------- fp32 -> fp16 weight conversion ----------------
__global__ void k_f2h(const float* __restrict__ src, __half* __restrict__ dst, int n) {
    int i = blockIdx.x * blockDim.x + threadIdx.x;
    if (i < n) dst[i] = __float2half_rn(src[i]);
}

// ---------------- scalar SGEMM (layer 1, K=14) ----------------
__global__ void sgemm_tn(const float* __restrict__ A, const float* __restrict__ B,
                         float* __restrict__ C, int M, int N, int K) {
    const int BM = 128, BN = 64, BK = 16;
    __shared__ float As[BK][BM + 4];
    __shared__ float Bs[BK][BN + 4];
    int bm = blockIdx.y * BM, bn = blockIdx.x * BN;
    int t = threadIdx.x;
    int tx = t & 15, ty = t >> 4;
    float acc[8][4];
#pragma unroll
    for (int i = 0; i < 8; i++)
#pragma unroll
        for (int j = 0; j < 4; j++) acc[i][j] = 0.f;
    for (int k0 = 0; k0 < K; k0 += BK) {
#pragma unroll
        for (int i = 0; i < 8; i++) {
            int idx = t + i * 256;
            int r = idx >> 4, kk = idx & 15;
            int gr = bm + r, gk = k0 + kk;
            As[kk][r] = (gr < M && gk < K) ? A[(size_t)gr * K + gk] : 0.f;
        }
#pragma unroll
        for (int i = 0; i < 4; i++) {
            int idx = t + i * 256;
            int r = idx >> 4, kk = idx & 15;
            int gr = bn + r, gk = k0 + kk;
            Bs[kk][r] = (gr < N && gk < K) ? B[(size_t)gr * K + gk] : 0.f;
        }
        __syncthreads();
#pragma unroll
        for (int kk = 0; kk < BK; kk++) {
            float a[8], b[4];
#pragma unroll
            for (int i = 0; i < 8; i++) a[i] = As[kk][ty * 8 + i];
#pragma unroll
            for (int j = 0; j < 4; j++) b[j] = Bs[kk][tx * 4 + j];
#pragma unroll
            for (int i = 0; i < 8; i++)
#pragma unroll
                for (int j = 0; j < 4; j++) acc[i][j] = fmaf(a[i], b[j], acc[i][j]);
        }
        __syncthreads();
    }
#pragma unroll
    for (int i = 0; i < 8; i++) {
        int r = bm + ty * 8 + i;
        if (r >= M) continue;
#pragma unroll
        for (int j = 0; j < 4; j++) {
            int c = bn + tx * 4 + j;
            if (c < N) C[(size_t)r * N + c] = acc[i][j];
        }
    }
}

// ======== fp16 tensor-core GEMM (legacy mma.sync m16n8k16): C = A * B^T ========
// A fp16 [M,K] row-major, B fp16 [N,K] row-major, C fp32 [M,N].
// Requires K % 32 == 0, N % 128 == 0. 128 threads, 128x128 CTA tile,
// warp tile 64x64, BK=32 halves, cp.async double buffer + ldmatrix.

#define HBK 32                 // halves per K tile
#define HSTRIDE 40             // halves per smem row (32 + 8 pad) = 80B, 16B-aligned

__device__ __forceinline__ void mma_f16(float c[4], const uint32_t a[4], const uint32_t b[2]) {
    asm volatile(
        "mma.sync.aligned.m16n8k16.row.col.f32.f16.f16.f32 "
        "{%0,%1,%2,%3}, {%4,%5,%6,%7}, {%8,%9}, {%0,%1,%2,%3};"
        : "+f"(c[0]), "+f"(c[1]), "+f"(c[2]), "+f"(c[3])
        : "r"(a[0]), "r"(a[1]), "r"(a[2]), "r"(a[3]), "r"(b[0]), "r"(b[1]));
}
__device__ __forceinline__ void ldsm_x4(uint32_t r[4], uint32_t saddr) {
    asm volatile("ldmatrix.sync.aligned.m8n8.x4.shared.b16 {%0,%1,%2,%3}, [%4];"
                 : "=r"(r[0]), "=r"(r[1]), "=r"(r[2]), "=r"(r[3]) : "r"(saddr));
}
__device__ __forceinline__ void cp_async16(uint32_t saddr, const void* gaddr) {
    asm volatile("cp.async.cg.shared.global [%0], [%1], 16;" :: "r"(saddr), "l"(gaddr));
}
__device__ __forceinline__ void cp_commit() { asm volatile("cp.async.commit_group;"); }
template <int N_> __device__ __forceinline__ void cp_wait() {
    asm volatile("cp.async.wait_group %0;" :: "n"(N_));
}
static __device__ __forceinline__ uint32_t smem_u32(const void* p) {
    uint32_t a;
    asm("{ .reg .u64 t; cvta.to.shared.u64 t, %1; cvt.u32.u64 %0, t; }" : "=r"(a) : "l"(p));
    return a;
}

__global__ __launch_bounds__(128, 2)
void gemm_f16(const __half* __restrict__ A, const __half* __restrict__ B,
              float* __restrict__ C, int M, int N, int K) {
    __shared__ __half As[2][128][HSTRIDE];   // 20 KB
    __shared__ __half Bs[2][128][HSTRIDE];   // 20 KB

    const int bm = blockIdx.y * 128, bn = blockIdx.x * 128;
    const int t = threadIdx.x;
    const int w = t >> 5, lane = t & 31;
    const int wm = (w >> 1) * 64;   // 0/64
    const int wn = (w & 1) * 64;    // 0/64
    const int g = lane >> 2;        // 0..7
    const int r = lane & 3;         // 0..3

    const uint32_t sA = smem_u32(&As[0][0][0]);
    const uint32_t sB = smem_u32(&Bs[0][0][0]);
    const uint32_t STAGE = 128 * HSTRIDE * 2;   // bytes

    // ldmatrix lane addressing (x4: 4 8x8 b16 tiles)
    const int sub = lane >> 3;                     // 0..3
    const int frow = (sub & 1) * 8 + (lane & 7);   // row within 16-row group
    const int fkof = (sub >> 1) * 8;               // k offset within 16-half k group

    float acc[4][8][4];
#pragma unroll
    for (int mi = 0; mi < 4; mi++)
#pragma unroll
        for (int ni = 0; ni < 8; ni++)
#pragma unroll
            for (int q = 0; q < 4; q++) acc[mi][ni][q] = 0.f;

    const int nIter = K / HBK;
    const int arow = min(bm + t, M - 1);          // clamp OOB rows
    const __half* gA = A + (size_t)arow * K;
    const __half* gB = B + (size_t)(bn + t) * K;  // N%128==0, always valid

    auto load_stage = [&](int it, int buf) {
        const int k0 = it * HBK;
        const uint32_t aBase = sA + buf * STAGE + (uint32_t)t * (HSTRIDE * 2);
        const uint32_t bBase = sB + buf * STAGE + (uint32_t)t * (HSTRIDE * 2);
#pragma unroll
        for (int c = 0; c < 4; c++) cp_async16(aBase + c * 16, gA + k0 + c * 8);
#pragma unroll
        for (int c = 0; c < 4; c++) cp_async16(bBase + c * 16, gB + k0 + c * 8);
        cp_commit();
    };

    load_stage(0, 0);

    for (int it = 0; it < nIter; it++) {
        const int buf = it & 1;
        if (it + 1 < nIter) {
            load_stage(it + 1, buf ^ 1);
            cp_wait<1>();
        } else {
            cp_wait<0>();
        }
        __syncthreads();

#pragma unroll
        for (int ks = 0; ks < 2; ks++) {
            const int kb = ks * 16;
            uint32_t af[4][4], bf[8][2];
#pragma unroll
            for (int mi = 0; mi < 4; mi++) {
                uint32_t addr = sA + buf * STAGE +
                                ((wm + mi * 16 + frow) * HSTRIDE + kb + fkof) * 2;
                ldsm_x4(af[mi], addr);
            }
#pragma unroll
            for (int np = 0; np < 4; np++) {
                uint32_t addr = sB + buf * STAGE +
                                ((wn + np * 16 + frow) * HSTRIDE + kb + fkof) * 2;
                uint32_t rr[4];
                ldsm_x4(rr, addr);
                bf[2 * np + 0][0] = rr[0];
                bf[2 * np + 1][0] = rr[1];
                bf[2 * np + 0][1] = rr[2];
                bf[2 * np + 1][1] = rr[3];
            }
#pragma unroll
            for (int mi = 0; mi < 4; mi++)
#pragma unroll
                for (int ni = 0; ni < 8; ni++)
                    mma_f16(acc[mi][ni], af[mi], bf[ni]);
        }
        __syncthreads();
    }

    // epilogue
#pragma unroll
    for (int mi = 0; mi < 4; mi++) {
        int row0 = bm + wm + mi * 16 + g;
        int row1 = row0 + 8;
#pragma unroll
        for (int ni = 0; ni < 8; ni++) {
            int col = bn + wn + ni * 8 + 2 * r;
            if (row0 < M)
                *reinterpret_cast<float2*>(C + (size_t)row0 * N + col) =
                    make_float2(acc[mi][ni][0], acc[mi][ni][1]);
            if (row1 < M)
                *reinterpret_cast<float2*>(C + (size_t)row1 * N + col) =
                    make_float2(acc[mi][ni][2], acc[mi][ni][3]);
        }
    }
}

// ---------------- attention logits ----------------
template <int H>
__global__ void k_alpha(const float* __restrict__ a_s, const float* __restrict__ a_d) {
    int gw = (blockIdx.x * blockDim.x + threadIdx.x) >> 5;
    int lane = threadIdx.x & 31;
    if (gw >= N_NODES * H) return;
    int n = gw / H, h = gw - n * H;
    const float* row = g_h + (size_t)n * (H * 256) + h * 256;
    float ss = 0.f, sd = 0.f;
    for (int c = lane; c < 256; c += 32) {
        float v = row[c];
        ss = fmaf(v, a_s[h * 256 + c], ss);
        sd = fmaf(v, a_d[h * 256 + c], sd);
    }
#pragma unroll
    for (int o = 16; o; o >>= 1) {
        ss += __shfl_xor_sync(0xffffffffu, ss, o);
        sd += __shfl_xor_sync(0xffffffffu, sd, o);
    }
    if (lane == 0) { g_as[n * H + h] = ss; g_ad[n * H + h] = sd; }
}

__device__ __forceinline__ float lrelu(float x) { return x > 0.f ? x : 0.2f * x; }

template <typename OT> __device__ __forceinline__ OT to_ot(float v);
template <> __device__ __forceinline__ float  to_ot<float>(float v) { return v; }
template <> __device__ __forceinline__ __half to_ot<__half>(float v) { return __float2half_rn(v); }

// ---------------- fused segment-softmax + aggregation + epilogue ----------------
template <int H, bool MEAN, bool APPLY_ELU, typename OT>
__global__ void gat_agg(const float* __restrict__ bgat, const float* __restrict__ lb,
                        OT* __restrict__ out) {
    int n = blockIdx.x;
    int t = threadIdx.x;
    int start = g_rowptr[n];
    int deg = g_rowptr[n + 1] - start;

    __shared__ float s_m[H], s_dinv[H];
    int w = t >> 5, lane = t & 31;
    if (w < H) {
        float ad = g_ad[n * H + w];
        float mx = -1e30f;
        for (int j = lane; j < deg; j += 32)
            mx = fmaxf(mx, lrelu(g_as[g_col[start + j] * H + w] + ad));
#pragma unroll
        for (int o = 16; o; o >>= 1) mx = fmaxf(mx, __shfl_xor_sync(0xffffffffu, mx, o));
        float sum = 0.f;
        for (int j = lane; j < deg; j += 32)
            sum += __expf(lrelu(g_as[g_col[start + j] * H + w] + ad) - mx);
#pragma unroll
        for (int o = 16; o; o >>= 1) sum += __shfl_xor_sync(0xffffffffu, sum, o);
        if (lane == 0) { s_m[w] = mx; s_dinv[w] = 1.f / (sum + 1e-16f); }
    }
    __syncthreads();

    const int CH = 32;
    __shared__ float s_coef[CH][H];
    __shared__ int   s_src[CH];
    float acc[H];
#pragma unroll
    for (int h = 0; h < H; h++) acc[h] = 0.f;

    for (int cs = 0; cs < deg; cs += CH) {
        int cnt = min(CH, deg - cs);
        if (t < cnt) s_src[t] = g_col[start + cs + t];
        for (int idx = t; idx < cnt * H; idx += 256) {
            int j = idx / H, h = idx - j * H;
            int s = g_col[start + cs + j];
            float ee = lrelu(g_as[s * H + h] + g_ad[n * H + h]);
            s_coef[j][h] = __expf(ee - s_m[h]) * s_dinv[h];
        }
        __syncthreads();
        for (int j = 0; j < cnt; j++) {
            const float* row = g_h + (size_t)s_src[j] * (H * 256) + t;
#pragma unroll
            for (int h = 0; h < H; h++)
                acc[h] = fmaf(row[h * 256], s_coef[j][h], acc[h]);
        }
        __syncthreads();
    }

    if (MEAN) {
        float v = 0.f;
#pragma unroll
        for (int h = 0; h < H; h++) v += acc[h];
        v = v * (1.f / (float)H) + bgat[t] + g_lin[(size_t)n * 256 + t] + lb[t];
        out[(size_t)n * 256 + t] = to_ot<OT>(v);
    } else {
#pragma unroll
        for (int h = 0; h < H; h++) {
            int c = h * 256 + t;
            float v = acc[h] + bgat[c] + g_lin[(size_t)n * 1024 + c] + lb[c];
            if (APPLY_ELU) v = v > 0.f ? v : (__expf(v) - 1.f);
            out[(size_t)n * 1024 + c] = to_ot<OT>(v);
        }
    }
}

// ---------------- host launcher ----------------
static inline void run_gemm_sc(const float* A, const float* B, float* C, int M, int N, int K) {
    dim3 grid((N + 63) / 64, (M + 127) / 128);
    sgemm_tn<<<grid, 256>>>(A, B, C, M, N, K);
}
static inline void run_gemm_tc(const __half* A, const __half* B, float* C, int M, int N, int K) {
    dim3 grid(N / 128, (M + 127) / 128);
    gemm_f16<<<grid, 128>>>(A, B, C, M, N, K);
}

extern "C" void kernel_launch(void* const* d_in, const int* in_sizes, int n_in,
                              void* d_out, int out_size) {
    const float* x   = (const float*)d_in[0];
    const int*   ei  = (const int*)d_in[1];
    const float* W1  = (const float*)d_in[2];
    const float* a1s = (const float*)d_in[3];
    const float* a1d = (const float*)d_in[4];
    const float* b1  = (const float*)d_in[5];
    const float* lw1 = (const float*)d_in[6];
    const float* lb1 = (const float*)d_in[7];
    const float* W2  = (const float*)d_in[8];
    const float* a2s = (const float*)d_in[9];
    const float* a2d = (const float*)d_in[10];
    const float* b2  = (const float*)d_in[11];
    const float* lw2 = (const float*)d_in[12];
    const float* lb2 = (const float*)d_in[13];
    const float* W3  = (const float*)d_in[14];
    const float* a3s = (const float*)d_in[15];
    const float* a3d = (const float*)d_in[16];
    const float* b3  = (const float*)d_in[17];
    const float* lw3 = (const float*)d_in[18];
    const float* lb3 = (const float*)d_in[19];
    float* out = (float*)d_out;

    void *p_h, *p_lin, *p_x1h, *p_x2h, *p_w2h, *p_lw2h, *p_w3h, *p_lw3h;
    cudaGetSymbolAddress(&p_h, g_h);
    cudaGetSymbolAddress(&p_lin, g_lin);
    cudaGetSymbolAddress(&p_x1h, g_x1h);
    cudaGetSymbolAddress(&p_x2h, g_x2h);
    cudaGetSymbolAddress(&p_w2h, g_w2h);
    cudaGetSymbolAddress(&p_lw2h, g_lw2h);
    cudaGetSymbolAddress(&p_w3h, g_w3h);
    cudaGetSymbolAddress(&p_lw3h, g_lw3h);
    float*  h    = (float*)p_h;
    float*  lin  = (float*)p_lin;
    __half* x1h  = (__half*)p_x1h;
    __half* x2h  = (__half*)p_x2h;
    __half* w2h  = (__half*)p_w2h;
    __half* lw2h = (__half*)p_lw2h;
    __half* w3h  = (__half*)p_w3h;
    __half* lw3h = (__half*)p_lw3h;

    // build CSR by dst (edges + self-loops)
    k_zero_counts<<<(N_NODES + 255) / 256, 256>>>();
    k_count<<<(ET + 255) / 256, 256>>>(ei);
    k_scan<<<1, 1024>>>();
    k_scatter<<<(ET + 255) / 256, 256>>>(ei);

    // convert weights to fp16 (once per launch)
    k_f2h<<<(1024 * 1024 + 255) / 256, 256>>>(W2, w2h, 1024 * 1024);
    k_f2h<<<(1024 * 1024 + 255) / 256, 256>>>(lw2, lw2h, 1024 * 1024);
    k_f2h<<<(1536 * 1024 + 255) / 256, 256>>>(W3, w3h, 1536 * 1024);
    k_f2h<<<(256 * 1024 + 255) / 256, 256>>>(lw3, lw3h, 256 * 1024);

    // ---- layer 1: 14 -> 4x256, concat, +skip, ELU ----
    run_gemm_sc(x, W1, h, N_NODES, 1024, 14);
    run_gemm_sc(x, lw1, lin, N_NODES, 1024, 14);
    k_alpha<4><<<(N_NODES * 4 * 32 + 255) / 256, 256>>>(a1s, a1d);
    gat_agg<4, false, true, __half><<<N_NODES, 256>>>(b1, lb1, x1h);

    // ---- layer 2: 1024 -> 4x256, concat, +skip, ELU ----
    run_gemm_tc(x1h, w2h, h, N_NODES, 1024, 1024);
    run_gemm_tc(x1h, lw2h, lin, N_NODES, 1024, 1024);
    k_alpha<4><<<(N_NODES * 4 * 32 + 255) / 256, 256>>>(a2s, a2d);
    gat_agg<4, false, true, __half><<<N_NODES, 256>>>(b2, lb2, x2h);

    // ---- layer 3: 1024 -> mean of 6x256, +skip, no ELU ----
    run_gemm_tc(x2h, w3h, h, N_NODES, 1536, 1024);
    run_gemm_tc(x2h, lw3h, lin, N_NODES, 256, 1024);
    k_alpha<6><<<(N_NODES * 6 * 32 + 255) / 256, 256>>>(a3s, a3d);
    gat_agg<6, true, false, float><<<N_NODES, 256>>>(b3, lb3, out);
}

// round 6
// speedup vs baseline: 3.0521x; 1.0711x over previous
#include <cuda_runtime.h>
#include <cuda_fp16.h>
#include <math.h>
#include <stdint.h>

#define N_NODES 10000
#define N_EDGES 160000
#define ET (N_EDGES + N_NODES)

// ---------------- scratch (static __device__, no allocations) ----------------
__device__ float  g_h[(size_t)N_NODES * 1536];
__device__ float  g_lin[(size_t)N_NODES * 1024];
__device__ __half g_x1h[(size_t)N_NODES * 1024];
__device__ __half g_x2h[(size_t)N_NODES * 1024];
__device__ __half g_w2h[1024 * 1024];
__device__ __half g_lw2h[1024 * 1024];
__device__ __half g_w3h[1536 * 1024];
__device__ __half g_lw3h[256 * 1024];
__device__ float  g_as[N_NODES * 6];
__device__ float  g_ad[N_NODES * 6];
__device__ int    g_rowptr[N_NODES + 1];
__device__ int    g_cnt[N_NODES];
__device__ int    g_fill[N_NODES];
__device__ int    g_col[ET];

// ---------------- graph build ----------------
__global__ void k_zero_counts() {
    int i = blockIdx.x * blockDim.x + threadIdx.x;
    if (i < N_NODES) { g_cnt[i] = 0; g_fill[i] = 0; }
}
__global__ void k_count(const int* __restrict__ ei) {
    int i = blockIdx.x * blockDim.x + threadIdx.x;
    if (i >= ET) return;
    int d = (i < N_EDGES) ? ei[N_EDGES + i] : (i - N_EDGES);
    atomicAdd(&g_cnt[d], 1);
}
__global__ void k_scan() {
    __shared__ int tmp[1024];
    __shared__ int carry;
    int t = threadIdx.x;
    if (t == 0) { carry = 0; g_rowptr[0] = 0; }
    __syncthreads();
    for (int base = 0; base < N_NODES; base += 1024) {
        int v = (base + t < N_NODES) ? g_cnt[base + t] : 0;
        tmp[t] = v;
        __syncthreads();
        for (int off = 1; off < 1024; off <<= 1) {
            int add = (t >= off) ? tmp[t - off] : 0;
            __syncthreads();
            tmp[t] += add;
            __syncthreads();
        }
        if (base + t < N_NODES) g_rowptr[base + t + 1] = carry + tmp[t];
        __syncthreads();
        if (t == 0) carry += tmp[1023];
        __syncthreads();
    }
}
__global__ void k_scatter(const int* __restrict__ ei) {
    int i = blockIdx.x * blockDim.x + threadIdx.x;
    if (i >= ET) return;
    int s, d;
    if (i < N_EDGES) { s = ei[i]; d = ei[N_EDGES + i]; }
    else             { s = d = i - N_EDGES; }
    int pos = g_rowptr[d] + atomicAdd(&g_fill[d], 1);
    g_col[pos] = s;
}

// ---------------- fp32 -> fp16 weight conversion ----------------
__global__ void k_f2h(const float* __restrict__ src, __half* __restrict__ dst, int n) {
    int i = blockIdx.x * blockDim.x + threadIdx.x;
    if (i < n) dst[i] = __float2half_rn(src[i]);
}

// -------- scalar SGEMM dual-output (layer 1, K=14): C = A * [B1|B2]^T --------
__global__ void sgemm_dual(const float* __restrict__ A,
                           const float* __restrict__ B1, const float* __restrict__ B2,
                           float* __restrict__ C1, float* __restrict__ C2,
                           int M, int N1, int N2, int K) {
    const int BM = 128, BN = 64, BK = 16;
    __shared__ float As[BK][BM + 4];
    __shared__ float Bs[BK][BN + 4];
    int bnG = blockIdx.x * BN;
    bool second = bnG >= N1;
    const float* B = second ? B2 : B1;
    float* C = second ? C2 : C1;
    int bn = second ? bnG - N1 : bnG;
    int Nc = second ? N2 : N1;

    int bm = blockIdx.y * BM;
    int t = threadIdx.x;
    int tx = t & 15, ty = t >> 4;
    float acc[8][4];
#pragma unroll
    for (int i = 0; i < 8; i++)
#pragma unroll
        for (int j = 0; j < 4; j++) acc[i][j] = 0.f;
    for (int k0 = 0; k0 < K; k0 += BK) {
#pragma unroll
        for (int i = 0; i < 8; i++) {
            int idx = t + i * 256;
            int r = idx >> 4, kk = idx & 15;
            int gr = bm + r, gk = k0 + kk;
            As[kk][r] = (gr < M && gk < K) ? A[(size_t)gr * K + gk] : 0.f;
        }
#pragma unroll
        for (int i = 0; i < 4; i++) {
            int idx = t + i * 256;
            int r = idx >> 4, kk = idx & 15;
            int gr = bn + r, gk = k0 + kk;
            Bs[kk][r] = (gr < Nc && gk < K) ? B[(size_t)gr * K + gk] : 0.f;
        }
        __syncthreads();
#pragma unroll
        for (int kk = 0; kk < BK; kk++) {
            float a[8], b[4];
#pragma unroll
            for (int i = 0; i < 8; i++) a[i] = As[kk][ty * 8 + i];
#pragma unroll
            for (int j = 0; j < 4; j++) b[j] = Bs[kk][tx * 4 + j];
#pragma unroll
            for (int i = 0; i < 8; i++)
#pragma unroll
                for (int j = 0; j < 4; j++) acc[i][j] = fmaf(a[i], b[j], acc[i][j]);
        }
        __syncthreads();
    }
#pragma unroll
    for (int i = 0; i < 8; i++) {
        int r = bm + ty * 8 + i;
        if (r >= M) continue;
#pragma unroll
        for (int j = 0; j < 4; j++) {
            int c = bn + tx * 4 + j;
            if (c < Nc) C[(size_t)r * Nc + c] = acc[i][j];
        }
    }
}

// ====== fp16 tensor-core dual GEMM (mma.sync m16n8k16): [C1|C2] = A*[B1|B2]^T ======
// A fp16 [M,K] rm, B1 fp16 [N1,K] rm, B2 fp16 [N2,K] rm, C fp32.
// K % 32 == 0, N1 % 128 == 0, N2 % 128 == 0.
// 128 threads, 128x128 CTA tile, warp 64x64, 3-stage cp.async, ldmatrix.

#define HBK 32                 // halves per K tile
#define HSTRIDE 40             // halves per smem row (32 + 8 pad)
#define HSTAGE_BYTES (2 * 128 * HSTRIDE * 2)     // A + B per stage = 20480
#define HSMEM_BYTES  (3 * HSTAGE_BYTES)          // 61440

__device__ __forceinline__ void mma_f16(float c[4], const uint32_t a[4], const uint32_t b[2]) {
    asm volatile(
        "mma.sync.aligned.m16n8k16.row.col.f32.f16.f16.f32 "
        "{%0,%1,%2,%3}, {%4,%5,%6,%7}, {%8,%9}, {%0,%1,%2,%3};"
        : "+f"(c[0]), "+f"(c[1]), "+f"(c[2]), "+f"(c[3])
        : "r"(a[0]), "r"(a[1]), "r"(a[2]), "r"(a[3]), "r"(b[0]), "r"(b[1]));
}
__device__ __forceinline__ void ldsm_x4(uint32_t r[4], uint32_t saddr) {
    asm volatile("ldmatrix.sync.aligned.m8n8.x4.shared.b16 {%0,%1,%2,%3}, [%4];"
                 : "=r"(r[0]), "=r"(r[1]), "=r"(r[2]), "=r"(r[3]) : "r"(saddr));
}
__device__ __forceinline__ void cp_async16(uint32_t saddr, const void* gaddr) {
    asm volatile("cp.async.cg.shared.global [%0], [%1], 16;" :: "r"(saddr), "l"(gaddr));
}
__device__ __forceinline__ void cp_commit() { asm volatile("cp.async.commit_group;"); }
template <int N_> __device__ __forceinline__ void cp_wait() {
    asm volatile("cp.async.wait_group %0;" :: "n"(N_));
}
static __device__ __forceinline__ uint32_t smem_u32(const void* p) {
    uint32_t a;
    asm("{ .reg .u64 t; cvta.to.shared.u64 t, %1; cvt.u32.u64 %0, t; }" : "=r"(a) : "l"(p));
    return a;
}

__global__ __launch_bounds__(128, 2)
void gemm_f16_dual(const __half* __restrict__ A,
                   const __half* __restrict__ B1, const __half* __restrict__ B2,
                   float* __restrict__ C1, float* __restrict__ C2,
                   int M, int N1, int N2, int K) {
    extern __shared__ __half hsm[];
    const uint32_t s0 = smem_u32(hsm);

    const int bnG = blockIdx.x * 128;
    const bool second = bnG >= N1;
    const __half* B = second ? B2 : B1;
    float* C = second ? C2 : C1;
    const int bn = second ? bnG - N1 : bnG;
    const int Nc = second ? N2 : N1;

    const int bm = blockIdx.y * 128;
    const int t = threadIdx.x;
    const int w = t >> 5, lane = t & 31;
    const int wm = (w >> 1) * 64;
    const int wn = (w & 1) * 64;
    const int g = lane >> 2;
    const int r = lane & 3;

    const int sub = lane >> 3;
    const int frow = (sub & 1) * 8 + (lane & 7);
    const int fkof = (sub >> 1) * 8;

    float acc[4][8][4];
#pragma unroll
    for (int mi = 0; mi < 4; mi++)
#pragma unroll
        for (int ni = 0; ni < 8; ni++)
#pragma unroll
            for (int q = 0; q < 4; q++) acc[mi][ni][q] = 0.f;

    const int nIter = K / HBK;
    const int arow = min(bm + t, M - 1);
    const __half* gA = A + (size_t)arow * K;
    const __half* gB = B + (size_t)(bn + t) * K;

    auto load_stage = [&](int j) {
        const int s = j % 3;
        const int k0 = j * HBK;
        const uint32_t aBase = s0 + s * HSTAGE_BYTES + (uint32_t)t * (HSTRIDE * 2);
        const uint32_t bBase = aBase + 128 * HSTRIDE * 2;
#pragma unroll
        for (int c = 0; c < 4; c++) cp_async16(aBase + c * 16, gA + k0 + c * 8);
#pragma unroll
        for (int c = 0; c < 4; c++) cp_async16(bBase + c * 16, gB + k0 + c * 8);
        cp_commit();
    };

    load_stage(0);
    load_stage(1);

    for (int j = 0; j < nIter; j++) {
        const int s = j % 3;
        if (j + 2 < nIter) { load_stage(j + 2); cp_wait<2>(); }
        else if (j + 1 < nIter) cp_wait<1>();
        else cp_wait<0>();
        __syncthreads();

        const uint32_t aS = s0 + s * HSTAGE_BYTES;
        const uint32_t bS = aS + 128 * HSTRIDE * 2;
#pragma unroll
        for (int ks = 0; ks < 2; ks++) {
            const int kb = ks * 16;
            uint32_t af[4][4], bf[8][2];
#pragma unroll
            for (int mi = 0; mi < 4; mi++)
                ldsm_x4(af[mi], aS + ((wm + mi * 16 + frow) * HSTRIDE + kb + fkof) * 2);
#pragma unroll
            for (int np = 0; np < 4; np++) {
                uint32_t rr[4];
                ldsm_x4(rr, bS + ((wn + np * 16 + frow) * HSTRIDE + kb + fkof) * 2);
                bf[2 * np + 0][0] = rr[0];
                bf[2 * np + 1][0] = rr[1];
                bf[2 * np + 0][1] = rr[2];
                bf[2 * np + 1][1] = rr[3];
            }
#pragma unroll
            for (int mi = 0; mi < 4; mi++)
#pragma unroll
                for (int ni = 0; ni < 8; ni++)
                    mma_f16(acc[mi][ni], af[mi], bf[ni]);
        }
        __syncthreads();
    }

    // epilogue
#pragma unroll
    for (int mi = 0; mi < 4; mi++) {
        int row0 = bm + wm + mi * 16 + g;
        int row1 = row0 + 8;
#pragma unroll
        for (int ni = 0; ni < 8; ni++) {
            int col = bn + wn + ni * 8 + 2 * r;
            if (row0 < M)
                *reinterpret_cast<float2*>(C + (size_t)row0 * Nc + col) =
                    make_float2(acc[mi][ni][0], acc[mi][ni][1]);
            if (row1 < M)
                *reinterpret_cast<float2*>(C + (size_t)row1 * Nc + col) =
                    make_float2(acc[mi][ni][2], acc[mi][ni][3]);
        }
    }
}

// ---------------- attention logits ----------------
template <int H>
__global__ void k_alpha(const float* __restrict__ a_s, const float* __restrict__ a_d) {
    int gw = (blockIdx.x * blockDim.x + threadIdx.x) >> 5;
    int lane = threadIdx.x & 31;
    if (gw >= N_NODES * H) return;
    int n = gw / H, h = gw - n * H;
    const float* row = g_h + (size_t)n * (H * 256) + h * 256;
    float ss = 0.f, sd = 0.f;
    for (int c = lane; c < 256; c += 32) {
        float v = row[c];
        ss = fmaf(v, a_s[h * 256 + c], ss);
        sd = fmaf(v, a_d[h * 256 + c], sd);
    }
#pragma unroll
    for (int o = 16; o; o >>= 1) {
        ss += __shfl_xor_sync(0xffffffffu, ss, o);
        sd += __shfl_xor_sync(0xffffffffu, sd, o);
    }
    if (lane == 0) { g_as[n * H + h] = ss; g_ad[n * H + h] = sd; }
}

__device__ __forceinline__ float lrelu(float x) { return x > 0.f ? x : 0.2f * x; }

template <typename OT> __device__ __forceinline__ OT to_ot(float v);
template <> __device__ __forceinline__ float  to_ot<float>(float v) { return v; }
template <> __device__ __forceinline__ __half to_ot<__half>(float v) { return __float2half_rn(v); }

// ---------------- fused segment-softmax + aggregation + epilogue ----------------
template <int H, bool MEAN, bool APPLY_ELU, typename OT>
__global__ void gat_agg(const float* __restrict__ bgat, const float* __restrict__ lb,
                        OT* __restrict__ out) {
    int n = blockIdx.x;
    int t = threadIdx.x;
    int start = g_rowptr[n];
    int deg = g_rowptr[n + 1] - start;

    __shared__ float s_m[H], s_dinv[H];
    int w = t >> 5, lane = t & 31;
    if (w < H) {
        float ad = g_ad[n * H + w];
        float mx = -1e30f;
        for (int j = lane; j < deg; j += 32)
            mx = fmaxf(mx, lrelu(g_as[g_col[start + j] * H + w] + ad));
#pragma unroll
        for (int o = 16; o; o >>= 1) mx = fmaxf(mx, __shfl_xor_sync(0xffffffffu, mx, o));
        float sum = 0.f;
        for (int j = lane; j < deg; j += 32)
            sum += __expf(lrelu(g_as[g_col[start + j] * H + w] + ad) - mx);
#pragma unroll
        for (int o = 16; o; o >>= 1) sum += __shfl_xor_sync(0xffffffffu, sum, o);
        if (lane == 0) { s_m[w] = mx; s_dinv[w] = 1.f / (sum + 1e-16f); }
    }
    __syncthreads();

    const int CH = 32;
    __shared__ float s_coef[CH][H];
    __shared__ int   s_src[CH];
    float acc[H];
#pragma unroll
    for (int h = 0; h < H; h++) acc[h] = 0.f;

    for (int cs = 0; cs < deg; cs += CH) {
        int cnt = min(CH, deg - cs);
        if (t < cnt) s_src[t] = g_col[start + cs + t];
        for (int idx = t; idx < cnt * H; idx += 256) {
            int j = idx / H, h = idx - j * H;
            int s = g_col[start + cs + j];
            float ee = lrelu(g_as[s * H + h] + g_ad[n * H + h]);
            s_coef[j][h] = __expf(ee - s_m[h]) * s_dinv[h];
        }
        __syncthreads();
        for (int j = 0; j < cnt; j++) {
            const float* row = g_h + (size_t)s_src[j] * (H * 256) + t;
#pragma unroll
            for (int h = 0; h < H; h++)
                acc[h] = fmaf(row[h * 256], s_coef[j][h], acc[h]);
        }
        __syncthreads();
    }

    if (MEAN) {
        float v = 0.f;
#pragma unroll
        for (int h = 0; h < H; h++) v += acc[h];
        v = v * (1.f / (float)H) + bgat[t] + g_lin[(size_t)n * 256 + t] + lb[t];
        out[(size_t)n * 256 + t] = to_ot<OT>(v);
    } else {
#pragma unroll
        for (int h = 0; h < H; h++) {
            int c = h * 256 + t;
            float v = acc[h] + bgat[c] + g_lin[(size_t)n * 1024 + c] + lb[c];
            if (APPLY_ELU) v = v > 0.f ? v : (__expf(v) - 1.f);
            out[(size_t)n * 1024 + c] = to_ot<OT>(v);
        }
    }
}

// ---------------- host launcher ----------------
static inline void run_gemm_dual_tc(const __half* A, const __half* B1, const __half* B2,
                                    float* C1, float* C2, int M, int N1, int N2, int K) {
    dim3 grid((N1 + N2) / 128, (M + 127) / 128);
    gemm_f16_dual<<<grid, 128, HSMEM_BYTES>>>(A, B1, B2, C1, C2, M, N1, N2, K);
}

extern "C" void kernel_launch(void* const* d_in, const int* in_sizes, int n_in,
                              void* d_out, int out_size) {
    const float* x   = (const float*)d_in[0];
    const int*   ei  = (const int*)d_in[1];
    const float* W1  = (const float*)d_in[2];
    const float* a1s = (const float*)d_in[3];
    const float* a1d = (const float*)d_in[4];
    const float* b1  = (const float*)d_in[5];
    const float* lw1 = (const float*)d_in[6];
    const float* lb1 = (const float*)d_in[7];
    const float* W2  = (const float*)d_in[8];
    const float* a2s = (const float*)d_in[9];
    const float* a2d = (const float*)d_in[10];
    const float* b2  = (const float*)d_in[11];
    const float* lw2 = (const float*)d_in[12];
    const float* lb2 = (const float*)d_in[13];
    const float* W3  = (const float*)d_in[14];
    const float* a3s = (const float*)d_in[15];
    const float* a3d = (const float*)d_in[16];
    const float* b3  = (const float*)d_in[17];
    const float* lw3 = (const float*)d_in[18];
    const float* lb3 = (const float*)d_in[19];
    float* out = (float*)d_out;

    cudaFuncSetAttribute(gemm_f16_dual, cudaFuncAttributeMaxDynamicSharedMemorySize,
                         HSMEM_BYTES);

    void *p_h, *p_lin, *p_x1h, *p_x2h, *p_w2h, *p_lw2h, *p_w3h, *p_lw3h;
    cudaGetSymbolAddress(&p_h, g_h);
    cudaGetSymbolAddress(&p_lin, g_lin);
    cudaGetSymbolAddress(&p_x1h, g_x1h);
    cudaGetSymbolAddress(&p_x2h, g_x2h);
    cudaGetSymbolAddress(&p_w2h, g_w2h);
    cudaGetSymbolAddress(&p_lw2h, g_lw2h);
    cudaGetSymbolAddress(&p_w3h, g_w3h);
    cudaGetSymbolAddress(&p_lw3h, g_lw3h);
    float*  h    = (float*)p_h;
    float*  lin  = (float*)p_lin;
    __half* x1h  = (__half*)p_x1h;
    __half* x2h  = (__half*)p_x2h;
    __half* w2h  = (__half*)p_w2h;
    __half* lw2h = (__half*)p_lw2h;
    __half* w3h  = (__half*)p_w3h;
    __half* lw3h = (__half*)p_lw3h;

    // build CSR by dst (edges + self-loops)
    k_zero_counts<<<(N_NODES + 255) / 256, 256>>>();
    k_count<<<(ET + 255) / 256, 256>>>(ei);
    k_scan<<<1, 1024>>>();
    k_scatter<<<(ET + 255) / 256, 256>>>(ei);

    // convert weights to fp16 (once per launch)
    k_f2h<<<(1024 * 1024 + 255) / 256, 256>>>(W2, w2h, 1024 * 1024);
    k_f2h<<<(1024 * 1024 + 255) / 256, 256>>>(lw2, lw2h, 1024 * 1024);
    k_f2h<<<(1536 * 1024 + 255) / 256, 256>>>(W3, w3h, 1536 * 1024);
    k_f2h<<<(256 * 1024 + 255) / 256, 256>>>(lw3, lw3h, 256 * 1024);

    // ---- layer 1: 14 -> 4x256, concat, +skip, ELU ----
    {
        dim3 grid((1024 + 1024) / 64, (N_NODES + 127) / 128);
        sgemm_dual<<<grid, 256>>>(x, W1, lw1, h, lin, N_NODES, 1024, 1024, 14);
    }
    k_alpha<4><<<(N_NODES * 4 * 32 + 255) / 256, 256>>>(a1s, a1d);
    gat_agg<4, false, true, __half><<<N_NODES, 256>>>(b1, lb1, x1h);

    // ---- layer 2: 1024 -> 4x256, concat, +skip, ELU ----
    run_gemm_dual_tc(x1h, w2h, lw2h, h, lin, N_NODES, 1024, 1024, 1024);
    k_alpha<4><<<(N_NODES * 4 * 32 + 255) / 256, 256>>>(a2s, a2d);
    gat_agg<4, false, true, __half><<<N_NODES, 256>>>(b2, lb2, x2h);

    // ---- layer 3: 1024 -> mean of 6x256, +skip, no ELU ----
    run_gemm_dual_tc(x2h, w3h, lw3h, h, lin, N_NODES, 1536, 256, 1024);
    k_alpha<6><<<(N_NODES * 6 * 32 + 255) / 256, 256>>>(a3s, a3d);
    gat_agg<6, true, false, float><<<N_NODES, 256>>>(b3, lb3, out);
}

// round 7
// speedup vs baseline: 3.5195x; 1.1531x over previous
#include <cuda_runtime.h>
#include <cuda_fp16.h>
#include <math.h>
#include <stdint.h>

#define N_NODES 10000
#define N_EDGES 160000
#define ET (N_EDGES + N_NODES)

// ---------------- scratch (static __device__, no allocations) ----------------
__device__ __half g_h[(size_t)N_NODES * 1536];     // GAT linear output, fp16
__device__ float  g_lin[(size_t)N_NODES * 1024];   // skip-linear output, fp32
__device__ __half g_x1h[(size_t)N_NODES * 1024];
__device__ __half g_x2h[(size_t)N_NODES * 1024];
__device__ __half g_w2h[1024 * 1024];
__device__ __half g_lw2h[1024 * 1024];
__device__ __half g_w3h[1536 * 1024];
__device__ __half g_lw3h[256 * 1024];
__device__ float  g_as[N_NODES * 6];
__device__ float  g_ad[N_NODES * 6];
__device__ int    g_rowptr[N_NODES + 1];
__device__ int    g_cnt[N_NODES];
__device__ int    g_fill[N_NODES];
__device__ int    g_col[ET];

// ---------------- graph build ----------------
__global__ void k_zero_counts() {
    int i = blockIdx.x * blockDim.x + threadIdx.x;
    if (i < N_NODES) { g_cnt[i] = 0; g_fill[i] = 0; }
}
__global__ void k_count(const int* __restrict__ ei) {
    int i = blockIdx.x * blockDim.x + threadIdx.x;
    if (i >= ET) return;
    int d = (i < N_EDGES) ? ei[N_EDGES + i] : (i - N_EDGES);
    atomicAdd(&g_cnt[d], 1);
}
__global__ void k_scan() {
    __shared__ int tmp[1024];
    __shared__ int carry;
    int t = threadIdx.x;
    if (t == 0) { carry = 0; g_rowptr[0] = 0; }
    __syncthreads();
    for (int base = 0; base < N_NODES; base += 1024) {
        int v = (base + t < N_NODES) ? g_cnt[base + t] : 0;
        tmp[t] = v;
        __syncthreads();
        for (int off = 1; off < 1024; off <<= 1) {
            int add = (t >= off) ? tmp[t - off] : 0;
            __syncthreads();
            tmp[t] += add;
            __syncthreads();
        }
        if (base + t < N_NODES) g_rowptr[base + t + 1] = carry + tmp[t];
        __syncthreads();
        if (t == 0) carry += tmp[1023];
        __syncthreads();
    }
}
__global__ void k_scatter(const int* __restrict__ ei) {
    int i = blockIdx.x * blockDim.x + threadIdx.x;
    if (i >= ET) return;
    int s, d;
    if (i < N_EDGES) { s = ei[i]; d = ei[N_EDGES + i]; }
    else             { s = d = i - N_EDGES; }
    int pos = g_rowptr[d] + atomicAdd(&g_fill[d], 1);
    g_col[pos] = s;
}

// ---------------- fp32 -> fp16 weight conversion ----------------
__global__ void k_f2h(const float* __restrict__ src, __half* __restrict__ dst, int n) {
    int i = blockIdx.x * blockDim.x + threadIdx.x;
    if (i < n) dst[i] = __float2half_rn(src[i]);
}

// -------- scalar SGEMM dual-output (layer 1, K=14): [C1|C2] = A * [B1|B2]^T --------
// C1 fp16, C2 fp32.
__global__ void sgemm_dual(const float* __restrict__ A,
                           const float* __restrict__ B1, const float* __restrict__ B2,
                           __half* __restrict__ C1, float* __restrict__ C2,
                           int M, int N1, int N2, int K) {
    const int BM = 128, BN = 64, BK = 16;
    __shared__ float As[BK][BM + 4];
    __shared__ float Bs[BK][BN + 4];
    int bnG = blockIdx.x * BN;
    bool second = bnG >= N1;
    const float* B = second ? B2 : B1;
    int bn = second ? bnG - N1 : bnG;
    int Nc = second ? N2 : N1;

    int bm = blockIdx.y * BM;
    int t = threadIdx.x;
    int tx = t & 15, ty = t >> 4;
    float acc[8][4];
#pragma unroll
    for (int i = 0; i < 8; i++)
#pragma unroll
        for (int j = 0; j < 4; j++) acc[i][j] = 0.f;
    for (int k0 = 0; k0 < K; k0 += BK) {
#pragma unroll
        for (int i = 0; i < 8; i++) {
            int idx = t + i * 256;
            int r = idx >> 4, kk = idx & 15;
            int gr = bm + r, gk = k0 + kk;
            As[kk][r] = (gr < M && gk < K) ? A[(size_t)gr * K + gk] : 0.f;
        }
#pragma unroll
        for (int i = 0; i < 4; i++) {
            int idx = t + i * 256;
            int r = idx >> 4, kk = idx & 15;
            int gr = bn + r, gk = k0 + kk;
            Bs[kk][r] = (gr < Nc && gk < K) ? B[(size_t)gr * K + gk] : 0.f;
        }
        __syncthreads();
#pragma unroll
        for (int kk = 0; kk < BK; kk++) {
            float a[8], b[4];
#pragma unroll
            for (int i = 0; i < 8; i++) a[i] = As[kk][ty * 8 + i];
#pragma unroll
            for (int j = 0; j < 4; j++) b[j] = Bs[kk][tx * 4 + j];
#pragma unroll
            for (int i = 0; i < 8; i++)
#pragma unroll
                for (int j = 0; j < 4; j++) acc[i][j] = fmaf(a[i], b[j], acc[i][j]);
        }
        __syncthreads();
    }
#pragma unroll
    for (int i = 0; i < 8; i++) {
        int r = bm + ty * 8 + i;
        if (r >= M) continue;
#pragma unroll
        for (int j = 0; j < 4; j++) {
            int c = bn + tx * 4 + j;
            if (c < Nc) {
                if (second) C2[(size_t)r * Nc + c] = acc[i][j];
                else        C1[(size_t)r * Nc + c] = __float2half_rn(acc[i][j]);
            }
        }
    }
}

// ====== fp16 tensor-core dual GEMM (mma.sync m16n8k16): [C1|C2] = A*[B1|B2]^T ======
// A fp16 [M,K] rm, B1/B2 fp16 rm, C1 fp16 (h), C2 fp32 (lin).
// K % 32 == 0, N1 % 128 == 0, N2 % 128 == 0.

#define HBK 32
#define HSTRIDE 40
#define HSTAGE_BYTES (2 * 128 * HSTRIDE * 2)     // 20480
#define HSMEM_BYTES  (3 * HSTAGE_BYTES)          // 61440

__device__ __forceinline__ void mma_f16(float c[4], const uint32_t a[4], const uint32_t b[2]) {
    asm volatile(
        "mma.sync.aligned.m16n8k16.row.col.f32.f16.f16.f32 "
        "{%0,%1,%2,%3}, {%4,%5,%6,%7}, {%8,%9}, {%0,%1,%2,%3};"
        : "+f"(c[0]), "+f"(c[1]), "+f"(c[2]), "+f"(c[3])
        : "r"(a[0]), "r"(a[1]), "r"(a[2]), "r"(a[3]), "r"(b[0]), "r"(b[1]));
}
__device__ __forceinline__ void ldsm_x4(uint32_t r[4], uint32_t saddr) {
    asm volatile("ldmatrix.sync.aligned.m8n8.x4.shared.b16 {%0,%1,%2,%3}, [%4];"
                 : "=r"(r[0]), "=r"(r[1]), "=r"(r[2]), "=r"(r[3]) : "r"(saddr));
}
__device__ __forceinline__ void cp_async16(uint32_t saddr, const void* gaddr) {
    asm volatile("cp.async.cg.shared.global [%0], [%1], 16;" :: "r"(saddr), "l"(gaddr));
}
__device__ __forceinline__ void cp_commit() { asm volatile("cp.async.commit_group;"); }
template <int N_> __device__ __forceinline__ void cp_wait() {
    asm volatile("cp.async.wait_group %0;" :: "n"(N_));
}
static __device__ __forceinline__ uint32_t smem_u32(const void* p) {
    uint32_t a;
    asm("{ .reg .u64 t; cvta.to.shared.u64 t, %1; cvt.u32.u64 %0, t; }" : "=r"(a) : "l"(p));
    return a;
}

__global__ __launch_bounds__(128, 2)
void gemm_f16_dual(const __half* __restrict__ A,
                   const __half* __restrict__ B1, const __half* __restrict__ B2,
                   __half* __restrict__ C1, float* __restrict__ C2,
                   int M, int N1, int N2, int K) {
    extern __shared__ __half hsm[];
    const uint32_t s0 = smem_u32(hsm);

    const int bnG = blockIdx.x * 128;
    const bool second = bnG >= N1;
    const __half* B = second ? B2 : B1;
    const int bn = second ? bnG - N1 : bnG;
    const int Nc = second ? N2 : N1;

    const int bm = blockIdx.y * 128;
    const int t = threadIdx.x;
    const int w = t >> 5, lane = t & 31;
    const int wm = (w >> 1) * 64;
    const int wn = (w & 1) * 64;
    const int g = lane >> 2;
    const int r = lane & 3;

    const int sub = lane >> 3;
    const int frow = (sub & 1) * 8 + (lane & 7);
    const int fkof = (sub >> 1) * 8;

    float acc[4][8][4];
#pragma unroll
    for (int mi = 0; mi < 4; mi++)
#pragma unroll
        for (int ni = 0; ni < 8; ni++)
#pragma unroll
            for (int q = 0; q < 4; q++) acc[mi][ni][q] = 0.f;

    const int nIter = K / HBK;
    const int arow = min(bm + t, M - 1);
    const __half* gA = A + (size_t)arow * K;
    const __half* gB = B + (size_t)(bn + t) * K;

    auto load_stage = [&](int j) {
        const int s = j % 3;
        const int k0 = j * HBK;
        const uint32_t aBase = s0 + s * HSTAGE_BYTES + (uint32_t)t * (HSTRIDE * 2);
        const uint32_t bBase = aBase + 128 * HSTRIDE * 2;
#pragma unroll
        for (int c = 0; c < 4; c++) cp_async16(aBase + c * 16, gA + k0 + c * 8);
#pragma unroll
        for (int c = 0; c < 4; c++) cp_async16(bBase + c * 16, gB + k0 + c * 8);
        cp_commit();
    };

    load_stage(0);
    load_stage(1);

    for (int j = 0; j < nIter; j++) {
        const int s = j % 3;
        if (j + 2 < nIter) { load_stage(j + 2); cp_wait<2>(); }
        else if (j + 1 < nIter) cp_wait<1>();
        else cp_wait<0>();
        __syncthreads();

        const uint32_t aS = s0 + s * HSTAGE_BYTES;
        const uint32_t bS = aS + 128 * HSTRIDE * 2;
#pragma unroll
        for (int ks = 0; ks < 2; ks++) {
            const int kb = ks * 16;
            uint32_t af[4][4], bf[8][2];
#pragma unroll
            for (int mi = 0; mi < 4; mi++)
                ldsm_x4(af[mi], aS + ((wm + mi * 16 + frow) * HSTRIDE + kb + fkof) * 2);
#pragma unroll
            for (int np = 0; np < 4; np++) {
                uint32_t rr[4];
                ldsm_x4(rr, bS + ((wn + np * 16 + frow) * HSTRIDE + kb + fkof) * 2);
                bf[2 * np + 0][0] = rr[0];
                bf[2 * np + 1][0] = rr[1];
                bf[2 * np + 0][1] = rr[2];
                bf[2 * np + 1][1] = rr[3];
            }
#pragma unroll
            for (int mi = 0; mi < 4; mi++)
#pragma unroll
                for (int ni = 0; ni < 8; ni++)
                    mma_f16(acc[mi][ni], af[mi], bf[ni]);
        }
        __syncthreads();
    }

    // epilogue
#pragma unroll
    for (int mi = 0; mi < 4; mi++) {
        int row0 = bm + wm + mi * 16 + g;
        int row1 = row0 + 8;
#pragma unroll
        for (int ni = 0; ni < 8; ni++) {
            int col = bn + wn + ni * 8 + 2 * r;
            if (second) {
                if (row0 < M)
                    *reinterpret_cast<float2*>(C2 + (size_t)row0 * Nc + col) =
                        make_float2(acc[mi][ni][0], acc[mi][ni][1]);
                if (row1 < M)
                    *reinterpret_cast<float2*>(C2 + (size_t)row1 * Nc + col) =
                        make_float2(acc[mi][ni][2], acc[mi][ni][3]);
            } else {
                if (row0 < M)
                    *reinterpret_cast<__half2*>(C1 + (size_t)row0 * Nc + col) =
                        __floats2half2_rn(acc[mi][ni][0], acc[mi][ni][1]);
                if (row1 < M)
                    *reinterpret_cast<__half2*>(C1 + (size_t)row1 * Nc + col) =
                        __floats2half2_rn(acc[mi][ni][2], acc[mi][ni][3]);
            }
        }
    }
}

// ---------------- attention logits (fp16 h, half2 loads) ----------------
template <int H>
__global__ void k_alpha(const float* __restrict__ a_s, const float* __restrict__ a_d) {
    int gw = (blockIdx.x * blockDim.x + threadIdx.x) >> 5;
    int lane = threadIdx.x & 31;
    if (gw >= N_NODES * H) return;
    int n = gw / H, h = gw - n * H;
    const __half2* row = reinterpret_cast<const __half2*>(g_h + (size_t)n * (H * 256)) + h * 128;
    float ss = 0.f, sd = 0.f;
    for (int c = lane; c < 128; c += 32) {
        float2 v = __half22float2(row[c]);
        float2 a1 = *reinterpret_cast<const float2*>(a_s + h * 256 + 2 * c);
        float2 a2 = *reinterpret_cast<const float2*>(a_d + h * 256 + 2 * c);
        ss = fmaf(v.x, a1.x, fmaf(v.y, a1.y, ss));
        sd = fmaf(v.x, a2.x, fmaf(v.y, a2.y, sd));
    }
#pragma unroll
    for (int o = 16; o; o >>= 1) {
        ss += __shfl_xor_sync(0xffffffffu, ss, o);
        sd += __shfl_xor_sync(0xffffffffu, sd, o);
    }
    if (lane == 0) { g_as[n * H + h] = ss; g_ad[n * H + h] = sd; }
}

__device__ __forceinline__ float lrelu(float x) { return x > 0.f ? x : 0.2f * x; }

// ---------------- fused segment-softmax + aggregation + epilogue ----------------
// Channel-pair mapping: thread t owns half2 slot p = t + 256*s (s < H/2);
// slot p covers channels {2p, 2p+1} of head p/128.
template <int H, bool MEAN, bool APPLY_ELU, typename OT>
__global__ void gat_agg(const float* __restrict__ bgat, const float* __restrict__ lb,
                        OT* __restrict__ out) {
    constexpr int S = H / 2;
    int n = blockIdx.x;
    int t = threadIdx.x;
    int start = g_rowptr[n];
    int deg = g_rowptr[n + 1] - start;

    __shared__ float s_m[H], s_dinv[H];
    int w = t >> 5, lane = t & 31;
    if (w < H) {
        float ad = g_ad[n * H + w];
        float mx = -1e30f;
        for (int j = lane; j < deg; j += 32)
            mx = fmaxf(mx, lrelu(g_as[g_col[start + j] * H + w] + ad));
#pragma unroll
        for (int o = 16; o; o >>= 1) mx = fmaxf(mx, __shfl_xor_sync(0xffffffffu, mx, o));
        float sum = 0.f;
        for (int j = lane; j < deg; j += 32)
            sum += __expf(lrelu(g_as[g_col[start + j] * H + w] + ad) - mx);
#pragma unroll
        for (int o = 16; o; o >>= 1) sum += __shfl_xor_sync(0xffffffffu, sum, o);
        if (lane == 0) { s_m[w] = mx; s_dinv[w] = 1.f / (sum + 1e-16f); }
    }
    __syncthreads();

    const int CH = 32;
    __shared__ float s_coef[CH][H];
    __shared__ int   s_src[CH];
    const int hb = t >> 7;             // 0 or 1

    float2 acc[S];
#pragma unroll
    for (int s = 0; s < S; s++) acc[s] = make_float2(0.f, 0.f);

    for (int cs = 0; cs < deg; cs += CH) {
        int cnt = min(CH, deg - cs);
        if (t < cnt) s_src[t] = g_col[start + cs + t];
        for (int idx = t; idx < cnt * H; idx += 256) {
            int j = idx / H, h = idx - j * H;
            int s = g_col[start + cs + j];
            float ee = lrelu(g_as[s * H + h] + g_ad[n * H + h]);
            s_coef[j][h] = __expf(ee - s_m[h]) * s_dinv[h];
        }
        __syncthreads();
        for (int j = 0; j < cnt; j++) {
            const __half2* row =
                reinterpret_cast<const __half2*>(g_h + (size_t)s_src[j] * (H * 256));
            float cf[S];
#pragma unroll
            for (int s = 0; s < S; s++) cf[s] = s_coef[j][hb + 2 * s];
#pragma unroll
            for (int s = 0; s < S; s++) {
                float2 f = __half22float2(row[t + 256 * s]);
                acc[s].x = fmaf(f.x, cf[s], acc[s].x);
                acc[s].y = fmaf(f.y, cf[s], acc[s].y);
            }
        }
        __syncthreads();
    }

    if (MEAN) {
        // thread t holds heads {hb, hb+2, hb+4} of channel pair c = (2t) % 256.
        __shared__ float2 s_red[128];
        float2 sum = make_float2(0.f, 0.f);
#pragma unroll
        for (int s = 0; s < S; s++) { sum.x += acc[s].x; sum.y += acc[s].y; }
        if (t >= 128) s_red[t - 128] = sum;
        __syncthreads();
        if (t < 128) {
            float2 tot = make_float2(sum.x + s_red[t].x, sum.y + s_red[t].y);
            int c = 2 * t;
            float2 bg = *reinterpret_cast<const float2*>(bgat + c);
            float2 lb2 = *reinterpret_cast<const float2*>(lb + c);
            float2 ln = *reinterpret_cast<const float2*>(g_lin + (size_t)n * 256 + c);
            float2 v;
            v.x = tot.x * (1.f / (float)H) + bg.x + ln.x + lb2.x;
            v.y = tot.y * (1.f / (float)H) + bg.y + ln.y + lb2.y;
            *reinterpret_cast<float2*>(reinterpret_cast<float*>(out) + (size_t)n * 256 + c) = v;
        }
    } else {
        __half2* oh = reinterpret_cast<__half2*>(out);
#pragma unroll
        for (int s = 0; s < S; s++) {
            int p = t + 256 * s;
            int c = 2 * p;
            float2 bg = *reinterpret_cast<const float2*>(bgat + c);
            float2 lb2 = *reinterpret_cast<const float2*>(lb + c);
            float2 ln = *reinterpret_cast<const float2*>(g_lin + (size_t)n * 1024 + c);
            float vx = acc[s].x + bg.x + ln.x + lb2.x;
            float vy = acc[s].y + bg.y + ln.y + lb2.y;
            if (APPLY_ELU) {
                vx = vx > 0.f ? vx : (__expf(vx) - 1.f);
                vy = vy > 0.f ? vy : (__expf(vy) - 1.f);
            }
            oh[(size_t)n * (H * 128) + p] = __floats2half2_rn(vx, vy);
        }
    }
}

// ---------------- host launcher ----------------
static inline void run_gemm_dual_tc(const __half* A, const __half* B1, const __half* B2,
                                    __half* C1, float* C2, int M, int N1, int N2, int K) {
    dim3 grid((N1 + N2) / 128, (M + 127) / 128);
    gemm_f16_dual<<<grid, 128, HSMEM_BYTES>>>(A, B1, B2, C1, C2, M, N1, N2, K);
}

extern "C" void kernel_launch(void* const* d_in, const int* in_sizes, int n_in,
                              void* d_out, int out_size) {
    const float* x   = (const float*)d_in[0];
    const int*   ei  = (const int*)d_in[1];
    const float* W1  = (const float*)d_in[2];
    const float* a1s = (const float*)d_in[3];
    const float* a1d = (const float*)d_in[4];
    const float* b1  = (const float*)d_in[5];
    const float* lw1 = (const float*)d_in[6];
    const float* lb1 = (const float*)d_in[7];
    const float* W2  = (const float*)d_in[8];
    const float* a2s = (const float*)d_in[9];
    const float* a2d = (const float*)d_in[10];
    const float* b2  = (const float*)d_in[11];
    const float* lw2 = (const float*)d_in[12];
    const float* lb2 = (const float*)d_in[13];
    const float* W3  = (const float*)d_in[14];
    const float* a3s = (const float*)d_in[15];
    const float* a3d = (const float*)d_in[16];
    const float* b3  = (const float*)d_in[17];
    const float* lw3 = (const float*)d_in[18];
    const float* lb3 = (const float*)d_in[19];
    float* out = (float*)d_out;

    cudaFuncSetAttribute(gemm_f16_dual, cudaFuncAttributeMaxDynamicSharedMemorySize,
                         HSMEM_BYTES);

    void *p_h, *p_lin, *p_x1h, *p_x2h, *p_w2h, *p_lw2h, *p_w3h, *p_lw3h;
    cudaGetSymbolAddress(&p_h, g_h);
    cudaGetSymbolAddress(&p_lin, g_lin);
    cudaGetSymbolAddress(&p_x1h, g_x1h);
    cudaGetSymbolAddress(&p_x2h, g_x2h);
    cudaGetSymbolAddress(&p_w2h, g_w2h);
    cudaGetSymbolAddress(&p_lw2h, g_lw2h);
    cudaGetSymbolAddress(&p_w3h, g_w3h);
    cudaGetSymbolAddress(&p_lw3h, g_lw3h);
    __half* h    = (__half*)p_h;
    float*  lin  = (float*)p_lin;
    __half* x1h  = (__half*)p_x1h;
    __half* x2h  = (__half*)p_x2h;
    __half* w2h  = (__half*)p_w2h;
    __half* lw2h = (__half*)p_lw2h;
    __half* w3h  = (__half*)p_w3h;
    __half* lw3h = (__half*)p_lw3h;

    // build CSR by dst (edges + self-loops)
    k_zero_counts<<<(N_NODES + 255) / 256, 256>>>();
    k_count<<<(ET + 255) / 256, 256>>>(ei);
    k_scan<<<1, 1024>>>();
    k_scatter<<<(ET + 255) / 256, 256>>>(ei);

    // convert weights to fp16 (once per launch)
    k_f2h<<<(1024 * 1024 + 255) / 256, 256>>>(W2, w2h, 1024 * 1024);
    k_f2h<<<(1024 * 1024 + 255) / 256, 256>>>(lw2, lw2h, 1024 * 1024);
    k_f2h<<<(1536 * 1024 + 255) / 256, 256>>>(W3, w3h, 1536 * 1024);
    k_f2h<<<(256 * 1024 + 255) / 256, 256>>>(lw3, lw3h, 256 * 1024);

    // ---- layer 1: 14 -> 4x256, concat, +skip, ELU ----
    {
        dim3 grid((1024 + 1024) / 64, (N_NODES + 127) / 128);
        sgemm_dual<<<grid, 256>>>(x, W1, lw1, h, lin, N_NODES, 1024, 1024, 14);
    }
    k_alpha<4><<<(N_NODES * 4 * 32 + 255) / 256, 256>>>(a1s, a1d);
    gat_agg<4, false, true, __half><<<N_NODES, 256>>>(b1, lb1, x1h);

    // ---- layer 2: 1024 -> 4x256, concat, +skip, ELU ----
    run_gemm_dual_tc(x1h, w2h, lw2h, h, lin, N_NODES, 1024, 1024, 1024);
    k_alpha<4><<<(N_NODES * 4 * 32 + 255) / 256, 256>>>(a2s, a2d);
    gat_agg<4, false, true, __half><<<N_NODES, 256>>>(b2, lb2, x2h);

    // ---- layer 3: 1024 -> mean of 6x256, +skip, no ELU ----
    run_gemm_dual_tc(x2h, w3h, lw3h, h, lin, N_NODES, 1536, 256, 1024);
    k_alpha<6><<<(N_NODES * 6 * 32 + 255) / 256, 256>>>(a3s, a3d);
    gat_agg<6, true, false, float><<<N_NODES, 256>>>(b3, lb3, out);
}

// round 8
// speedup vs baseline: 4.5908x; 1.3044x over previous
#include <cuda_runtime.h>
#include <cuda_fp16.h>
#include <math.h>
#include <stdint.h>

#define N_NODES 10000
#define N_EDGES 160000
#define ET (N_EDGES + N_NODES)

// ---------------- scratch (static __device__, no allocations) ----------------
__device__ __half g_h[(size_t)N_NODES * 1536];     // GAT linear output, fp16
__device__ float  g_lin[(size_t)N_NODES * 1024];   // skip-linear output, fp32
__device__ __half g_x1h[(size_t)N_NODES * 1024];
__device__ __half g_x2h[(size_t)N_NODES * 1024];
__device__ __half g_w2h[1024 * 1024];
__device__ __half g_lw2h[1024 * 1024];
__device__ __half g_w3h[1536 * 1024];
__device__ __half g_lw3h[256 * 1024];
__device__ float  g_as[N_NODES * 6];
__device__ float  g_ad[N_NODES * 6];
__device__ int    g_rowptr[N_NODES + 1];
__device__ int    g_cnt[N_NODES];
__device__ int    g_fill[N_NODES];
__device__ int    g_col[ET];

// ---------------- graph build ----------------
__global__ void k_zero_counts() {
    int i = blockIdx.x * blockDim.x + threadIdx.x;
    if (i < N_NODES) { g_cnt[i] = 0; g_fill[i] = 0; }
}
__global__ void k_count(const int* __restrict__ ei) {
    int i = blockIdx.x * blockDim.x + threadIdx.x;
    if (i >= ET) return;
    int d = (i < N_EDGES) ? ei[N_EDGES + i] : (i - N_EDGES);
    atomicAdd(&g_cnt[d], 1);
}
__global__ void k_scan() {
    __shared__ int tmp[1024];
    __shared__ int carry;
    int t = threadIdx.x;
    if (t == 0) { carry = 0; g_rowptr[0] = 0; }
    __syncthreads();
    for (int base = 0; base < N_NODES; base += 1024) {
        int v = (base + t < N_NODES) ? g_cnt[base + t] : 0;
        tmp[t] = v;
        __syncthreads();
        for (int off = 1; off < 1024; off <<= 1) {
            int add = (t >= off) ? tmp[t - off] : 0;
            __syncthreads();
            tmp[t] += add;
            __syncthreads();
        }
        if (base + t < N_NODES) g_rowptr[base + t + 1] = carry + tmp[t];
        __syncthreads();
        if (t == 0) carry += tmp[1023];
        __syncthreads();
    }
}
__global__ void k_scatter(const int* __restrict__ ei) {
    int i = blockIdx.x * blockDim.x + threadIdx.x;
    if (i >= ET) return;
    int s, d;
    if (i < N_EDGES) { s = ei[i]; d = ei[N_EDGES + i]; }
    else             { s = d = i - N_EDGES; }
    int pos = g_rowptr[d] + atomicAdd(&g_fill[d], 1);
    g_col[pos] = s;
}

// ---------------- fp32 -> fp16 weight conversion ----------------
__global__ void k_f2h(const float* __restrict__ src, __half* __restrict__ dst, int n) {
    int i = blockIdx.x * blockDim.x + threadIdx.x;
    if (i < n) dst[i] = __float2half_rn(src[i]);
}

// -------- scalar SGEMM dual-output (layer 1, K=14): [C1|C2] = A * [B1|B2]^T --------
__global__ void sgemm_dual(const float* __restrict__ A,
                           const float* __restrict__ B1, const float* __restrict__ B2,
                           __half* __restrict__ C1, float* __restrict__ C2,
                           int M, int N1, int N2, int K) {
    const int BM = 128, BN = 64, BK = 16;
    __shared__ float As[BK][BM + 4];
    __shared__ float Bs[BK][BN + 4];
    int bnG = blockIdx.x * BN;
    bool second = bnG >= N1;
    const float* B = second ? B2 : B1;
    int bn = second ? bnG - N1 : bnG;
    int Nc = second ? N2 : N1;

    int bm = blockIdx.y * BM;
    int t = threadIdx.x;
    int tx = t & 15, ty = t >> 4;
    float acc[8][4];
#pragma unroll
    for (int i = 0; i < 8; i++)
#pragma unroll
        for (int j = 0; j < 4; j++) acc[i][j] = 0.f;
    for (int k0 = 0; k0 < K; k0 += BK) {
#pragma unroll
        for (int i = 0; i < 8; i++) {
            int idx = t + i * 256;
            int r = idx >> 4, kk = idx & 15;
            int gr = bm + r, gk = k0 + kk;
            As[kk][r] = (gr < M && gk < K) ? A[(size_t)gr * K + gk] : 0.f;
        }
#pragma unroll
        for (int i = 0; i < 4; i++) {
            int idx = t + i * 256;
            int r = idx >> 4, kk = idx & 15;
            int gr = bn + r, gk = k0 + kk;
            Bs[kk][r] = (gr < Nc && gk < K) ? B[(size_t)gr * K + gk] : 0.f;
        }
        __syncthreads();
#pragma unroll
        for (int kk = 0; kk < BK; kk++) {
            float a[8], b[4];
#pragma unroll
            for (int i = 0; i < 8; i++) a[i] = As[kk][ty * 8 + i];
#pragma unroll
            for (int j = 0; j < 4; j++) b[j] = Bs[kk][tx * 4 + j];
#pragma unroll
            for (int i = 0; i < 8; i++)
#pragma unroll
                for (int j = 0; j < 4; j++) acc[i][j] = fmaf(a[i], b[j], acc[i][j]);
        }
        __syncthreads();
    }
#pragma unroll
    for (int i = 0; i < 8; i++) {
        int r = bm + ty * 8 + i;
        if (r >= M) continue;
#pragma unroll
        for (int j = 0; j < 4; j++) {
            int c = bn + tx * 4 + j;
            if (c < Nc) {
                if (second) C2[(size_t)r * Nc + c] = acc[i][j];
                else        C1[(size_t)r * Nc + c] = __float2half_rn(acc[i][j]);
            }
        }
    }
}

// ====== fp16 tensor-core dual GEMM (mma.sync m16n8k16): [C1|C2] = A*[B1|B2]^T ======
// 256 threads, 128x128 CTA tile, warp tile 32x64 (8 warps, 4x2), 3-stage cp.async.
// A fp16 [M,K] rm, B1/B2 fp16 rm, C1 fp16 (h), C2 fp32 (lin).
// K % 32 == 0, N1 % 128 == 0, N2 % 128 == 0.

#define HBK 32
#define HSTRIDE 40
#define HSTAGE_BYTES (2 * 128 * HSTRIDE * 2)     // A + B per stage = 20480
#define HSMEM_BYTES  (3 * HSTAGE_BYTES)          // 61440

__device__ __forceinline__ void mma_f16(float c[4], const uint32_t a[4], const uint32_t b[2]) {
    asm volatile(
        "mma.sync.aligned.m16n8k16.row.col.f32.f16.f16.f32 "
        "{%0,%1,%2,%3}, {%4,%5,%6,%7}, {%8,%9}, {%0,%1,%2,%3};"
        : "+f"(c[0]), "+f"(c[1]), "+f"(c[2]), "+f"(c[3])
        : "r"(a[0]), "r"(a[1]), "r"(a[2]), "r"(a[3]), "r"(b[0]), "r"(b[1]));
}
__device__ __forceinline__ void ldsm_x4(uint32_t r[4], uint32_t saddr) {
    asm volatile("ldmatrix.sync.aligned.m8n8.x4.shared.b16 {%0,%1,%2,%3}, [%4];"
                 : "=r"(r[0]), "=r"(r[1]), "=r"(r[2]), "=r"(r[3]) : "r"(saddr));
}
__device__ __forceinline__ void ldsm_x2(uint32_t r[2], uint32_t saddr) {
    asm volatile("ldmatrix.sync.aligned.m8n8.x2.shared.b16 {%0,%1}, [%2];"
                 : "=r"(r[0]), "=r"(r[1]) : "r"(saddr));
}
__device__ __forceinline__ void cp_async16(uint32_t saddr, const void* gaddr) {
    asm volatile("cp.async.cg.shared.global [%0], [%1], 16;" :: "r"(saddr), "l"(gaddr));
}
__device__ __forceinline__ void cp_commit() { asm volatile("cp.async.commit_group;"); }
template <int N_> __device__ __forceinline__ void cp_wait() {
    asm volatile("cp.async.wait_group %0;" :: "n"(N_));
}
static __device__ __forceinline__ uint32_t smem_u32(const void* p) {
    uint32_t a;
    asm("{ .reg .u64 t; cvta.to.shared.u64 t, %1; cvt.u32.u64 %0, t; }" : "=r"(a) : "l"(p));
    return a;
}

__global__ __launch_bounds__(256, 2)
void gemm_f16_dual(const __half* __restrict__ A,
                   const __half* __restrict__ B1, const __half* __restrict__ B2,
                   __half* __restrict__ C1, float* __restrict__ C2,
                   int M, int N1, int N2, int K) {
    extern __shared__ __half hsm[];
    const uint32_t s0 = smem_u32(hsm);

    const int bnG = blockIdx.x * 128;
    const bool second = bnG >= N1;
    const __half* B = second ? B2 : B1;
    const int bn = second ? bnG - N1 : bnG;
    const int Nc = second ? N2 : N1;

    const int bm = blockIdx.y * 128;
    const int t = threadIdx.x;
    const int w = t >> 5, lane = t & 31;
    const int wm = (w >> 1) * 32;   // 0/32/64/96
    const int wn = (w & 1) * 64;    // 0/64
    const int g = lane >> 2;
    const int r = lane & 3;

    const int sub = lane >> 3;                     // 0..3
    const int frow = (sub & 1) * 8 + (lane & 7);   // row within 16-row group
    const int fkof = (sub >> 1) * 8;               // k offset within 16-half group

    float acc[2][8][4];
#pragma unroll
    for (int mi = 0; mi < 2; mi++)
#pragma unroll
        for (int ni = 0; ni < 8; ni++)
#pragma unroll
            for (int q = 0; q < 4; q++) acc[mi][ni][q] = 0.f;

    const int nIter = K / HBK;

    // per-thread load slots: 2 A-chunks + 2 B-chunks of 16B each
    const int c0 = t, c1 = t + 256;                // chunk ids (0..511)
    const int r0 = c0 >> 2, kc0 = (c0 & 3) * 8;
    const int r1 = c1 >> 2, kc1 = (c1 & 3) * 8;
    const __half* gA0 = A + (size_t)min(bm + r0, M - 1) * K + kc0;
    const __half* gA1 = A + (size_t)min(bm + r1, M - 1) * K + kc1;
    const __half* gB0 = B + (size_t)(bn + r0) * K + kc0;
    const __half* gB1 = B + (size_t)(bn + r1) * K + kc1;
    const uint32_t sa0 = (uint32_t)(r0 * HSTRIDE + kc0) * 2;
    const uint32_t sa1 = (uint32_t)(r1 * HSTRIDE + kc1) * 2;

    auto load_stage = [&](int j) {
        const int s = j % 3;
        const int k0 = j * HBK;
        const uint32_t aS = s0 + s * HSTAGE_BYTES;
        const uint32_t bS = aS + 128 * HSTRIDE * 2;
        cp_async16(aS + sa0, gA0 + k0);
        cp_async16(aS + sa1, gA1 + k0);
        cp_async16(bS + sa0, gB0 + k0);
        cp_async16(bS + sa1, gB1 + k0);
        cp_commit();
    };

    load_stage(0);
    load_stage(1);

    for (int j = 0; j < nIter; j++) {
        const int s = j % 3;
        if (j + 2 < nIter) { load_stage(j + 2); cp_wait<2>(); }
        else if (j + 1 < nIter) cp_wait<1>();
        else cp_wait<0>();
        __syncthreads();

        const uint32_t aS = s0 + s * HSTAGE_BYTES;
        const uint32_t bS = aS + 128 * HSTRIDE * 2;
#pragma unroll
        for (int ks = 0; ks < 2; ks++) {
            const int kb = ks * 16;
            uint32_t af[4], bf[8][2];
            // A: one x4 covers 32 rows x 16 k (2 m-frags)
            ldsm_x4(af, aS + ((wm + frow) * HSTRIDE + kb + fkof) * 2);
#pragma unroll
            for (int np = 0; np < 4; np++) {
                uint32_t rr[4];
                ldsm_x4(rr, bS + ((wn + np * 16 + frow) * HSTRIDE + kb + fkof) * 2);
                bf[2 * np + 0][0] = rr[0];
                bf[2 * np + 1][0] = rr[1];
                bf[2 * np + 0][1] = rr[2];
                bf[2 * np + 1][1] = rr[3];
            }
            // af = {m0k0, m1k0(row+8? no)...}: x4 tiles at rows {frow, frow+8} x k {+0,+8}
            // tile order: {r0k0, r8k0, r0k8, r8k8} -> m16 frag = {af[0],af[1],af[2],af[3]}
            // second m-frag (rows 16..31): need another ldsm
            uint32_t af2[4];
            ldsm_x4(af2, aS + ((wm + 16 + frow) * HSTRIDE + kb + fkof) * 2);
#pragma unroll
            for (int ni = 0; ni < 8; ni++) {
                mma_f16(acc[0][ni], af, bf[ni]);
                mma_f16(acc[1][ni], af2, bf[ni]);
            }
        }
        __syncthreads();
    }

    // epilogue
#pragma unroll
    for (int mi = 0; mi < 2; mi++) {
        int row0 = bm + wm + mi * 16 + g;
        int row1 = row0 + 8;
#pragma unroll
        for (int ni = 0; ni < 8; ni++) {
            int col = bn + wn + ni * 8 + 2 * r;
            if (second) {
                if (row0 < M)
                    *reinterpret_cast<float2*>(C2 + (size_t)row0 * Nc + col) =
                        make_float2(acc[mi][ni][0], acc[mi][ni][1]);
                if (row1 < M)
                    *reinterpret_cast<float2*>(C2 + (size_t)row1 * Nc + col) =
                        make_float2(acc[mi][ni][2], acc[mi][ni][3]);
            } else {
                if (row0 < M)
                    *reinterpret_cast<__half2*>(C1 + (size_t)row0 * Nc + col) =
                        __floats2half2_rn(acc[mi][ni][0], acc[mi][ni][1]);
                if (row1 < M)
                    *reinterpret_cast<__half2*>(C1 + (size_t)row1 * Nc + col) =
                        __floats2half2_rn(acc[mi][ni][2], acc[mi][ni][3]);
            }
        }
    }
}

// ---------------- attention logits (fp16 h, half2 loads) ----------------
template <int H>
__global__ void k_alpha(const float* __restrict__ a_s, const float* __restrict__ a_d) {
    int gw = (blockIdx.x * blockDim.x + threadIdx.x) >> 5;
    int lane = threadIdx.x & 31;
    if (gw >= N_NODES * H) return;
    int n = gw / H, h = gw - n * H;
    const __half2* row = reinterpret_cast<const __half2*>(g_h + (size_t)n * (H * 256)) + h * 128;
    float ss = 0.f, sd = 0.f;
    for (int c = lane; c < 128; c += 32) {
        float2 v = __half22float2(row[c]);
        float2 a1 = *reinterpret_cast<const float2*>(a_s + h * 256 + 2 * c);
        float2 a2 = *reinterpret_cast<const float2*>(a_d + h * 256 + 2 * c);
        ss = fmaf(v.x, a1.x, fmaf(v.y, a1.y, ss));
        sd = fmaf(v.x, a2.x, fmaf(v.y, a2.y, sd));
    }
#pragma unroll
    for (int o = 16; o; o >>= 1) {
        ss += __shfl_xor_sync(0xffffffffu, ss, o);
        sd += __shfl_xor_sync(0xffffffffu, sd, o);
    }
    if (lane == 0) { g_as[n * H + h] = ss; g_ad[n * H + h] = sd; }
}

__device__ __forceinline__ float lrelu(float x) { return x > 0.f ? x : 0.2f * x; }

// ---------------- fused segment-softmax + aggregation + epilogue ----------------
template <int H, bool MEAN, bool APPLY_ELU, typename OT>
__global__ void gat_agg(const float* __restrict__ bgat, const float* __restrict__ lb,
                        OT* __restrict__ out) {
    constexpr int S = H / 2;
    int n = blockIdx.x;
    int t = threadIdx.x;
    int start = g_rowptr[n];
    int deg = g_rowptr[n + 1] - start;

    __shared__ float s_m[H], s_dinv[H];
    int w = t >> 5, lane = t & 31;
    if (w < H) {
        float ad = g_ad[n * H + w];
        float mx = -1e30f;
        for (int j = lane; j < deg; j += 32)
            mx = fmaxf(mx, lrelu(g_as[g_col[start + j] * H + w] + ad));
#pragma unroll
        for (int o = 16; o; o >>= 1) mx = fmaxf(mx, __shfl_xor_sync(0xffffffffu, mx, o));
        float sum = 0.f;
        for (int j = lane; j < deg; j += 32)
            sum += __expf(lrelu(g_as[g_col[start + j] * H + w] + ad) - mx);
#pragma unroll
        for (int o = 16; o; o >>= 1) sum += __shfl_xor_sync(0xffffffffu, sum, o);
        if (lane == 0) { s_m[w] = mx; s_dinv[w] = 1.f / (sum + 1e-16f); }
    }
    __syncthreads();

    const int CH = 32;
    __shared__ float s_coef[CH][H];
    __shared__ int   s_src[CH];
    const int hb = t >> 7;             // 0 or 1

    float2 acc[S];
#pragma unroll
    for (int s = 0; s < S; s++) acc[s] = make_float2(0.f, 0.f);

    for (int cs = 0; cs < deg; cs += CH) {
        int cnt = min(CH, deg - cs);
        if (t < cnt) s_src[t] = g_col[start + cs + t];
        for (int idx = t; idx < cnt * H; idx += 256) {
            int j = idx / H, h = idx - j * H;
            int s = g_col[start + cs + j];
            float ee = lrelu(g_as[s * H + h] + g_ad[n * H + h]);
            s_coef[j][h] = __expf(ee - s_m[h]) * s_dinv[h];
        }
        __syncthreads();
        for (int j = 0; j < cnt; j++) {
            const __half2* row =
                reinterpret_cast<const __half2*>(g_h + (size_t)s_src[j] * (H * 256));
            float cf[S];
#pragma unroll
            for (int s = 0; s < S; s++) cf[s] = s_coef[j][hb + 2 * s];
#pragma unroll
            for (int s = 0; s < S; s++) {
                float2 f = __half22float2(row[t + 256 * s]);
                acc[s].x = fmaf(f.x, cf[s], acc[s].x);
                acc[s].y = fmaf(f.y, cf[s], acc[s].y);
            }
        }
        __syncthreads();
    }

    if (MEAN) {
        __shared__ float2 s_red[128];
        float2 sum = make_float2(0.f, 0.f);
#pragma unroll
        for (int s = 0; s < S; s++) { sum.x += acc[s].x; sum.y += acc[s].y; }
        if (t >= 128) s_red[t - 128] = sum;
        __syncthreads();
        if (t < 128) {
            float2 tot = make_float2(sum.x + s_red[t].x, sum.y + s_red[t].y);
            int c = 2 * t;
            float2 bg = *reinterpret_cast<const float2*>(bgat + c);
            float2 lb2 = *reinterpret_cast<const float2*>(lb + c);
            float2 ln = *reinterpret_cast<const float2*>(g_lin + (size_t)n * 256 + c);
            float2 v;
            v.x = tot.x * (1.f / (float)H) + bg.x + ln.x + lb2.x;
            v.y = tot.y * (1.f / (float)H) + bg.y + ln.y + lb2.y;
            *reinterpret_cast<float2*>(reinterpret_cast<float*>(out) + (size_t)n * 256 + c) = v;
        }
    } else {
        __half2* oh = reinterpret_cast<__half2*>(out);
#pragma unroll
        for (int s = 0; s < S; s++) {
            int p = t + 256 * s;
            int c = 2 * p;
            float2 bg = *reinterpret_cast<const float2*>(bgat + c);
            float2 lb2 = *reinterpret_cast<const float2*>(lb + c);
            float2 ln = *reinterpret_cast<const float2*>(g_lin + (size_t)n * 1024 + c);
            float vx = acc[s].x + bg.x + ln.x + lb2.x;
            float vy = acc[s].y + bg.y + ln.y + lb2.y;
            if (APPLY_ELU) {
                vx = vx > 0.f ? vx : (__expf(vx) - 1.f);
                vy = vy > 0.f ? vy : (__expf(vy) - 1.f);
            }
            oh[(size_t)n * (H * 128) + p] = __floats2half2_rn(vx, vy);
        }
    }
}

// ---------------- host launcher ----------------
static inline void run_gemm_dual_tc(const __half* A, const __half* B1, const __half* B2,
                                    __half* C1, float* C2, int M, int N1, int N2, int K) {
    dim3 grid((N1 + N2) / 128, (M + 127) / 128);
    gemm_f16_dual<<<grid, 256, HSMEM_BYTES>>>(A, B1, B2, C1, C2, M, N1, N2, K);
}

extern "C" void kernel_launch(void* const* d_in, const int* in_sizes, int n_in,
                              void* d_out, int out_size) {
    const float* x   = (const float*)d_in[0];
    const int*   ei  = (const int*)d_in[1];
    const float* W1  = (const float*)d_in[2];
    const float* a1s = (const float*)d_in[3];
    const float* a1d = (const float*)d_in[4];
    const float* b1  = (const float*)d_in[5];
    const float* lw1 = (const float*)d_in[6];
    const float* lb1 = (const float*)d_in[7];
    const float* W2  = (const float*)d_in[8];
    const float* a2s = (const float*)d_in[9];
    const float* a2d = (const float*)d_in[10];
    const float* b2  = (const float*)d_in[11];
    const float* lw2 = (const float*)d_in[12];
    const float* lb2 = (const float*)d_in[13];
    const float* W3  = (const float*)d_in[14];
    const float* a3s = (const float*)d_in[15];
    const float* a3d = (const float*)d_in[16];
    const float* b3  = (const float*)d_in[17];
    const float* lw3 = (const float*)d_in[18];
    const float* lb3 = (const float*)d_in[19];
    float* out = (float*)d_out;

    cudaFuncSetAttribute(gemm_f16_dual, cudaFuncAttributeMaxDynamicSharedMemorySize,
                         HSMEM_BYTES);

    void *p_h, *p_lin, *p_x1h, *p_x2h, *p_w2h, *p_lw2h, *p_w3h, *p_lw3h;
    cudaGetSymbolAddress(&p_h, g_h);
    cudaGetSymbolAddress(&p_lin, g_lin);
    cudaGetSymbolAddress(&p_x1h, g_x1h);
    cudaGetSymbolAddress(&p_x2h, g_x2h);
    cudaGetSymbolAddress(&p_w2h, g_w2h);
    cudaGetSymbolAddress(&p_lw2h, g_lw2h);
    cudaGetSymbolAddress(&p_w3h, g_w3h);
    cudaGetSymbolAddress(&p_lw3h, g_lw3h);
    __half* h    = (__half*)p_h;
    float*  lin  = (float*)p_lin;
    __half* x1h  = (__half*)p_x1h;
    __half* x2h  = (__half*)p_x2h;
    __half* w2h  = (__half*)p_w2h;
    __half* lw2h = (__half*)p_lw2h;
    __half* w3h  = (__half*)p_w3h;
    __half* lw3h = (__half*)p_lw3h;

    // build CSR by dst (edges + self-loops)
    k_zero_counts<<<(N_NODES + 255) / 256, 256>>>();
    k_count<<<(ET + 255) / 256, 256>>>(ei);
    k_scan<<<1, 1024>>>();
    k_scatter<<<(ET + 255) / 256, 256>>>(ei);

    // convert weights to fp16 (once per launch)
    k_f2h<<<(1024 * 1024 + 255) / 256, 256>>>(W2, w2h, 1024 * 1024);
    k_f2h<<<(1024 * 1024 + 255) / 256, 256>>>(lw2, lw2h, 1024 * 1024);
    k_f2h<<<(1536 * 1024 + 255) / 256, 256>>>(W3, w3h, 1536 * 1024);
    k_f2h<<<(256 * 1024 + 255) / 256, 256>>>(lw3, lw3h, 256 * 1024);

    // ---- layer 1: 14 -> 4x256, concat, +skip, ELU ----
    {
        dim3 grid((1024 + 1024) / 64, (N_NODES + 127) / 128);
        sgemm_dual<<<grid, 256>>>(x, W1, lw1, h, lin, N_NODES, 1024, 1024, 14);
    }
    k_alpha<4><<<(N_NODES * 4 * 32 + 255) / 256, 256>>>(a1s, a1d);
    gat_agg<4, false, true, __half><<<N_NODES, 256>>>(b1, lb1, x1h);

    // ---- layer 2: 1024 -> 4x256, concat, +skip, ELU ----
    run_gemm_dual_tc(x1h, w2h, lw2h, h, lin, N_NODES, 1024, 1024, 1024);
    k_alpha<4><<<(N_NODES * 4 * 32 + 255) / 256, 256>>>(a2s, a2d);
    gat_agg<4, false, true, __half><<<N_NODES, 256>>>(b2, lb2, x2h);

    // ---- layer 3: 1024 -> mean of 6x256, +skip, no ELU ----
    run_gemm_dual_tc(x2h, w3h, lw3h, h, lin, N_NODES, 1536, 256, 1024);
    k_alpha<6><<<(N_NODES * 6 * 32 + 255) / 256, 256>>>(a3s, a3d);
    gat_agg<6, true, false, float><<<N_NODES, 256>>>(b3, lb3, out);
}

// round 9
// speedup vs baseline: 4.7259x; 1.0294x over previous
#include <cuda_runtime.h>
#include <cuda_fp16.h>
#include <math.h>
#include <stdint.h>

#define N_NODES 10000
#define N_EDGES 160000
#define ET (N_EDGES + N_NODES)

// ---------------- scratch (static __device__, no allocations) ----------------
__device__ __half g_h[(size_t)N_NODES * 1536];     // GAT linear output, fp16
__device__ __half g_linh[(size_t)N_NODES * 1024];  // skip-linear output, fp16
__device__ __half g_x1h[(size_t)N_NODES * 1024];
__device__ __half g_x2h[(size_t)N_NODES * 1024];
__device__ __half g_w2h[1024 * 1024];
__device__ __half g_lw2h[1024 * 1024];
__device__ __half g_w3h[1536 * 1024];
__device__ __half g_lw3h[256 * 1024];
__device__ float  g_as[N_NODES * 6];
__device__ float  g_ad[N_NODES * 6];
__device__ int    g_rowptr[N_NODES + 1];
__device__ int    g_cnt[N_NODES];
__device__ int    g_fill[N_NODES];
__device__ int    g_col[ET];

// ---------------- graph build ----------------
__global__ void k_zero_counts() {
    int i = blockIdx.x * blockDim.x + threadIdx.x;
    if (i < N_NODES) { g_cnt[i] = 0; g_fill[i] = 0; }
}
__global__ void k_count(const int* __restrict__ ei) {
    int i = blockIdx.x * blockDim.x + threadIdx.x;
    if (i >= ET) return;
    int d = (i < N_EDGES) ? ei[N_EDGES + i] : (i - N_EDGES);
    atomicAdd(&g_cnt[d], 1);
}
__global__ void k_scan() {
    __shared__ int tmp[1024];
    __shared__ int carry;
    int t = threadIdx.x;
    if (t == 0) { carry = 0; g_rowptr[0] = 0; }
    __syncthreads();
    for (int base = 0; base < N_NODES; base += 1024) {
        int v = (base + t < N_NODES) ? g_cnt[base + t] : 0;
        tmp[t] = v;
        __syncthreads();
        for (int off = 1; off < 1024; off <<= 1) {
            int add = (t >= off) ? tmp[t - off] : 0;
            __syncthreads();
            tmp[t] += add;
            __syncthreads();
        }
        if (base + t < N_NODES) g_rowptr[base + t + 1] = carry + tmp[t];
        __syncthreads();
        if (t == 0) carry += tmp[1023];
        __syncthreads();
    }
}
__global__ void k_scatter(const int* __restrict__ ei) {
    int i = blockIdx.x * blockDim.x + threadIdx.x;
    if (i >= ET) return;
    int s, d;
    if (i < N_EDGES) { s = ei[i]; d = ei[N_EDGES + i]; }
    else             { s = d = i - N_EDGES; }
    int pos = g_rowptr[d] + atomicAdd(&g_fill[d], 1);
    g_col[pos] = s;
}

// ---------------- fused fp32 -> fp16 weight conversion (float4 vectorized) ----
#define S_W2  (1024 * 1024)
#define S_LW2 (1024 * 1024)
#define S_W3  (1536 * 1024)
#define S_LW3 (256 * 1024)
#define F2H_TOTAL4 ((S_W2 + S_LW2 + S_W3 + S_LW3) / 4)

__global__ void k_f2h_all(const float* __restrict__ W2, const float* __restrict__ lw2,
                          const float* __restrict__ W3, const float* __restrict__ lw3) {
    int i = blockIdx.x * blockDim.x + threadIdx.x;   // float4 index
    if (i >= F2H_TOTAL4) return;
    const float* src;
    __half* dst;
    int off;
    if (i < S_W2 / 4)                      { src = W2;  dst = g_w2h;  off = i; }
    else if (i < (S_W2 + S_LW2) / 4)       { src = lw2; dst = g_lw2h; off = i - S_W2 / 4; }
    else if (i < (S_W2 + S_LW2 + S_W3) / 4){ src = W3;  dst = g_w3h;  off = i - (S_W2 + S_LW2) / 4; }
    else                                   { src = lw3; dst = g_lw3h; off = i - (S_W2 + S_LW2 + S_W3) / 4; }
    float4 v = *reinterpret_cast<const float4*>(src + 4 * off);
    uint2 o;
    __half2 a = __floats2half2_rn(v.x, v.y);
    __half2 b = __floats2half2_rn(v.z, v.w);
    o.x = *reinterpret_cast<uint32_t*>(&a);
    o.y = *reinterpret_cast<uint32_t*>(&b);
    *reinterpret_cast<uint2*>(dst + 4 * off) = o;
}

// -------- scalar SGEMM dual-output (layer 1, K=14): [C1|C2] = A * [B1|B2]^T --------
__global__ void sgemm_dual(const float* __restrict__ A,
                           const float* __restrict__ B1, const float* __restrict__ B2,
                           __half* __restrict__ C1, __half* __restrict__ C2,
                           int M, int N1, int N2, int K) {
    const int BM = 128, BN = 64, BK = 16;
    __shared__ float As[BK][BM + 4];
    __shared__ float Bs[BK][BN + 4];
    int bnG = blockIdx.x * BN;
    bool second = bnG >= N1;
    const float* B = second ? B2 : B1;
    __half* C = second ? C2 : C1;
    int bn = second ? bnG - N1 : bnG;
    int Nc = second ? N2 : N1;

    int bm = blockIdx.y * BM;
    int t = threadIdx.x;
    int tx = t & 15, ty = t >> 4;
    float acc[8][4];
#pragma unroll
    for (int i = 0; i < 8; i++)
#pragma unroll
        for (int j = 0; j < 4; j++) acc[i][j] = 0.f;
    for (int k0 = 0; k0 < K; k0 += BK) {
#pragma unroll
        for (int i = 0; i < 8; i++) {
            int idx = t + i * 256;
            int r = idx >> 4, kk = idx & 15;
            int gr = bm + r, gk = k0 + kk;
            As[kk][r] = (gr < M && gk < K) ? A[(size_t)gr * K + gk] : 0.f;
        }
#pragma unroll
        for (int i = 0; i < 4; i++) {
            int idx = t + i * 256;
            int r = idx >> 4, kk = idx & 15;
            int gr = bn + r, gk = k0 + kk;
            Bs[kk][r] = (gr < Nc && gk < K) ? B[(size_t)gr * K + gk] : 0.f;
        }
        __syncthreads();
#pragma unroll
        for (int kk = 0; kk < BK; kk++) {
            float a[8], b[4];
#pragma unroll
            for (int i = 0; i < 8; i++) a[i] = As[kk][ty * 8 + i];
#pragma unroll
            for (int j = 0; j < 4; j++) b[j] = Bs[kk][tx * 4 + j];
#pragma unroll
            for (int i = 0; i < 8; i++)
#pragma unroll
                for (int j = 0; j < 4; j++) acc[i][j] = fmaf(a[i], b[j], acc[i][j]);
        }
        __syncthreads();
    }
#pragma unroll
    for (int i = 0; i < 8; i++) {
        int r = bm + ty * 8 + i;
        if (r >= M) continue;
#pragma unroll
        for (int j = 0; j < 4; j++) {
            int c = bn + tx * 4 + j;
            if (c < Nc) C[(size_t)r * Nc + c] = __float2half_rn(acc[i][j]);
        }
    }
}

// ====== fp16 tensor-core dual GEMM (mma.sync m16n8k16): [C1|C2] = A*[B1|B2]^T ======
// 256 threads, 128x128 CTA tile, warp 32x64 (8 warps, 4x2), 4-stage cp.async.
// A fp16 [M,K] rm, B1/B2 fp16 rm, C1/C2 fp16. K%32==0, N1%128==0, N2%128==0, K/32>=3.

#define HBK 32
#define HSTRIDE 40
#define HSTAGE_BYTES (2 * 128 * HSTRIDE * 2)     // A + B per stage = 20480
#define HSMEM_BYTES  (4 * HSTAGE_BYTES)          // 81920

__device__ __forceinline__ void mma_f16(float c[4], const uint32_t a[4], const uint32_t b[2]) {
    asm volatile(
        "mma.sync.aligned.m16n8k16.row.col.f32.f16.f16.f32 "
        "{%0,%1,%2,%3}, {%4,%5,%6,%7}, {%8,%9}, {%0,%1,%2,%3};"
        : "+f"(c[0]), "+f"(c[1]), "+f"(c[2]), "+f"(c[3])
        : "r"(a[0]), "r"(a[1]), "r"(a[2]), "r"(a[3]), "r"(b[0]), "r"(b[1]));
}
__device__ __forceinline__ void ldsm_x4(uint32_t r[4], uint32_t saddr) {
    asm volatile("ldmatrix.sync.aligned.m8n8.x4.shared.b16 {%0,%1,%2,%3}, [%4];"
                 : "=r"(r[0]), "=r"(r[1]), "=r"(r[2]), "=r"(r[3]) : "r"(saddr));
}
__device__ __forceinline__ void cp_async16(uint32_t saddr, const void* gaddr) {
    asm volatile("cp.async.cg.shared.global [%0], [%1], 16;" :: "r"(saddr), "l"(gaddr));
}
__device__ __forceinline__ void cp_commit() { asm volatile("cp.async.commit_group;"); }
template <int N_> __device__ __forceinline__ void cp_wait() {
    asm volatile("cp.async.wait_group %0;" :: "n"(N_));
}
static __device__ __forceinline__ uint32_t smem_u32(const void* p) {
    uint32_t a;
    asm("{ .reg .u64 t; cvta.to.shared.u64 t, %1; cvt.u32.u64 %0, t; }" : "=r"(a) : "l"(p));
    return a;
}

__global__ __launch_bounds__(256, 2)
void gemm_f16_dual(const __half* __restrict__ A,
                   const __half* __restrict__ B1, const __half* __restrict__ B2,
                   __half* __restrict__ C1, __half* __restrict__ C2,
                   int M, int N1, int N2, int K) {
    extern __shared__ __half hsm[];
    const uint32_t s0 = smem_u32(hsm);

    const int bnG = blockIdx.x * 128;
    const bool second = bnG >= N1;
    const __half* B = second ? B2 : B1;
    __half* C = second ? C2 : C1;
    const int bn = second ? bnG - N1 : bnG;
    const int Nc = second ? N2 : N1;

    const int bm = blockIdx.y * 128;
    const int t = threadIdx.x;
    const int w = t >> 5, lane = t & 31;
    const int wm = (w >> 1) * 32;
    const int wn = (w & 1) * 64;
    const int g = lane >> 2;
    const int r = lane & 3;

    const int sub = lane >> 3;
    const int frow = (sub & 1) * 8 + (lane & 7);
    const int fkof = (sub >> 1) * 8;

    float acc[2][8][4];
#pragma unroll
    for (int mi = 0; mi < 2; mi++)
#pragma unroll
        for (int ni = 0; ni < 8; ni++)
#pragma unroll
            for (int q = 0; q < 4; q++) acc[mi][ni][q] = 0.f;

    const int nIter = K / HBK;

    const int c0 = t, c1 = t + 256;
    const int r0 = c0 >> 2, kc0 = (c0 & 3) * 8;
    const int r1 = c1 >> 2, kc1 = (c1 & 3) * 8;
    const __half* gA0 = A + (size_t)min(bm + r0, M - 1) * K + kc0;
    const __half* gA1 = A + (size_t)min(bm + r1, M - 1) * K + kc1;
    const __half* gB0 = B + (size_t)(bn + r0) * K + kc0;
    const __half* gB1 = B + (size_t)(bn + r1) * K + kc1;
    const uint32_t sa0 = (uint32_t)(r0 * HSTRIDE + kc0) * 2;
    const uint32_t sa1 = (uint32_t)(r1 * HSTRIDE + kc1) * 2;

    auto load_stage = [&](int j) {
        const int s = j & 3;
        const int k0 = j * HBK;
        const uint32_t aS = s0 + s * HSTAGE_BYTES;
        const uint32_t bS = aS + 128 * HSTRIDE * 2;
        cp_async16(aS + sa0, gA0 + k0);
        cp_async16(aS + sa1, gA1 + k0);
        cp_async16(bS + sa0, gB0 + k0);
        cp_async16(bS + sa1, gB1 + k0);
        cp_commit();
    };

    load_stage(0);
    load_stage(1);
    load_stage(2);

    for (int j = 0; j < nIter; j++) {
        const int s = j & 3;
        if (j + 3 < nIter) { load_stage(j + 3); cp_wait<3>(); }
        else if (j + 2 < nIter) cp_wait<2>();
        else if (j + 1 < nIter) cp_wait<1>();
        else cp_wait<0>();
        __syncthreads();

        const uint32_t aS = s0 + s * HSTAGE_BYTES;
        const uint32_t bS = aS + 128 * HSTRIDE * 2;
#pragma unroll
        for (int ks = 0; ks < 2; ks++) {
            const int kb = ks * 16;
            uint32_t af[4], af2[4], bf[8][2];
            ldsm_x4(af, aS + ((wm + frow) * HSTRIDE + kb + fkof) * 2);
            ldsm_x4(af2, aS + ((wm + 16 + frow) * HSTRIDE + kb + fkof) * 2);
#pragma unroll
            for (int np = 0; np < 4; np++) {
                uint32_t rr[4];
                ldsm_x4(rr, bS + ((wn + np * 16 + frow) * HSTRIDE + kb + fkof) * 2);
                bf[2 * np + 0][0] = rr[0];
                bf[2 * np + 1][0] = rr[1];
                bf[2 * np + 0][1] = rr[2];
                bf[2 * np + 1][1] = rr[3];
            }
#pragma unroll
            for (int ni = 0; ni < 8; ni++) {
                mma_f16(acc[0][ni], af, bf[ni]);
                mma_f16(acc[1][ni], af2, bf[ni]);
            }
        }
        __syncthreads();
    }

    // epilogue (fp16 both outputs)
#pragma unroll
    for (int mi = 0; mi < 2; mi++) {
        int row0 = bm + wm + mi * 16 + g;
        int row1 = row0 + 8;
#pragma unroll
        for (int ni = 0; ni < 8; ni++) {
            int col = bn + wn + ni * 8 + 2 * r;
            if (row0 < M)
                *reinterpret_cast<__half2*>(C + (size_t)row0 * Nc + col) =
                    __floats2half2_rn(acc[mi][ni][0], acc[mi][ni][1]);
            if (row1 < M)
                *reinterpret_cast<__half2*>(C + (size_t)row1 * Nc + col) =
                    __floats2half2_rn(acc[mi][ni][2], acc[mi][ni][3]);
        }
    }
}

// ---------------- attention logits (fp16 h, half2 loads) ----------------
template <int H>
__global__ void k_alpha(const float* __restrict__ a_s, const float* __restrict__ a_d) {
    int gw = (blockIdx.x * blockDim.x + threadIdx.x) >> 5;
    int lane = threadIdx.x & 31;
    if (gw >= N_NODES * H) return;
    int n = gw / H, h = gw - n * H;
    const __half2* row = reinterpret_cast<const __half2*>(g_h + (size_t)n * (H * 256)) + h * 128;
    float ss = 0.f, sd = 0.f;
    for (int c = lane; c < 128; c += 32) {
        float2 v = __half22float2(row[c]);
        float2 a1 = *reinterpret_cast<const float2*>(a_s + h * 256 + 2 * c);
        float2 a2 = *reinterpret_cast<const float2*>(a_d + h * 256 + 2 * c);
        ss = fmaf(v.x, a1.x, fmaf(v.y, a1.y, ss));
        sd = fmaf(v.x, a2.x, fmaf(v.y, a2.y, sd));
    }
#pragma unroll
    for (int o = 16; o; o >>= 1) {
        ss += __shfl_xor_sync(0xffffffffu, ss, o);
        sd += __shfl_xor_sync(0xffffffffu, sd, o);
    }
    if (lane == 0) { g_as[n * H + h] = ss; g_ad[n * H + h] = sd; }
}

__device__ __forceinline__ float lrelu(float x) { return x > 0.f ? x : 0.2f * x; }

// ---------------- fused segment-softmax + aggregation + epilogue ----------------
// Contiguous channel mapping: thread t owns channels {4t..4t+3} (head t/64);
// for H=6 additionally channels {1024+2t, 1024+2t+1} (head 4 + t/128).
template <int H, bool MEAN, bool APPLY_ELU, typename OT>
__global__ void gat_agg(const float* __restrict__ bgat, const float* __restrict__ lb,
                        OT* __restrict__ out) {
    int n = blockIdx.x;
    int t = threadIdx.x;
    int start = g_rowptr[n];
    int deg = g_rowptr[n + 1] - start;

    __shared__ float s_m[H], s_dinv[H];
    int w = t >> 5, lane = t & 31;
    if (w < H) {
        float ad = g_ad[n * H + w];
        float mx = -1e30f;
        for (int j = lane; j < deg; j += 32)
            mx = fmaxf(mx, lrelu(g_as[g_col[start + j] * H + w] + ad));
#pragma unroll
        for (int o = 16; o; o >>= 1) mx = fmaxf(mx, __shfl_xor_sync(0xffffffffu, mx, o));
        float sum = 0.f;
        for (int j = lane; j < deg; j += 32)
            sum += __expf(lrelu(g_as[g_col[start + j] * H + w] + ad) - mx);
#pragma unroll
        for (int o = 16; o; o >>= 1) sum += __shfl_xor_sync(0xffffffffu, sum, o);
        if (lane == 0) { s_m[w] = mx; s_dinv[w] = 1.f / (sum + 1e-16f); }
    }
    __syncthreads();

    const int CH = 32;
    __shared__ float s_coef[CH][H];
    __shared__ int   s_src[CH];
    const int hA = t >> 6;                 // head of channels 4t..4t+3
    const int hB = 4 + (t >> 7);           // head of channels 1024+2t (H==6)

    float2 accA0 = make_float2(0.f, 0.f);
    float2 accA1 = make_float2(0.f, 0.f);
    float2 accB  = make_float2(0.f, 0.f);

    for (int cs = 0; cs < deg; cs += CH) {
        int cnt = min(CH, deg - cs);
        if (t < cnt) s_src[t] = g_col[start + cs + t];
        for (int idx = t; idx < cnt * H; idx += 256) {
            int j = idx / H, h = idx - j * H;
            int s = g_col[start + cs + j];
            float ee = lrelu(g_as[s * H + h] + g_ad[n * H + h]);
            s_coef[j][h] = __expf(ee - s_m[h]) * s_dinv[h];
        }
        __syncthreads();
        for (int j = 0; j < cnt; j++) {
            const __half* row = g_h + (size_t)s_src[j] * (H * 256);
            uint2 va = *reinterpret_cast<const uint2*>(row + 4 * t);
            float cA = s_coef[j][hA];
            float2 f0 = __half22float2(*reinterpret_cast<__half2*>(&va.x));
            float2 f1 = __half22float2(*reinterpret_cast<__half2*>(&va.y));
            accA0.x = fmaf(f0.x, cA, accA0.x);
            accA0.y = fmaf(f0.y, cA, accA0.y);
            accA1.x = fmaf(f1.x, cA, accA1.x);
            accA1.y = fmaf(f1.y, cA, accA1.y);
            if (H == 6) {
                __half2 vb = *reinterpret_cast<const __half2*>(row + 1024 + 2 * t);
                float cB = s_coef[j][hB];
                float2 fb = __half22float2(vb);
                accB.x = fmaf(fb.x, cB, accB.x);
                accB.y = fmaf(fb.y, cB, accB.y);
            }
        }
        __syncthreads();
    }

    if (MEAN) {
        // per-channel mean over H heads via smem accumulation
        __shared__ float s_sum[256];
        s_sum[t] = 0.f;
        __syncthreads();
        int cA = (4 * t) & 255;
        atomicAdd(&s_sum[cA + 0], accA0.x);
        atomicAdd(&s_sum[cA + 1], accA0.y);
        atomicAdd(&s_sum[cA + 2], accA1.x);
        atomicAdd(&s_sum[cA + 3], accA1.y);
        int cB = (2 * t) & 255;
        atomicAdd(&s_sum[cB + 0], accB.x);
        atomicAdd(&s_sum[cB + 1], accB.y);
        __syncthreads();
        float ln = __half2float(g_linh[(size_t)n * 256 + t]);
        float v = s_sum[t] * (1.f / (float)H) + bgat[t] + ln + lb[t];
        reinterpret_cast<float*>(out)[(size_t)n * 256 + t] = v;
    } else {
        int c = 4 * t;
        float4 bg = *reinterpret_cast<const float4*>(bgat + c);
        float4 lb4 = *reinterpret_cast<const float4*>(lb + c);
        uint2 lv = *reinterpret_cast<const uint2*>(g_linh + (size_t)n * 1024 + c);
        float2 l0 = __half22float2(*reinterpret_cast<__half2*>(&lv.x));
        float2 l1 = __half22float2(*reinterpret_cast<__half2*>(&lv.y));
        float v0 = accA0.x + bg.x + l0.x + lb4.x;
        float v1 = accA0.y + bg.y + l0.y + lb4.y;
        float v2 = accA1.x + bg.z + l1.x + lb4.z;
        float v3 = accA1.y + bg.w + l1.y + lb4.w;
        if (APPLY_ELU) {
            v0 = v0 > 0.f ? v0 : (__expf(v0) - 1.f);
            v1 = v1 > 0.f ? v1 : (__expf(v1) - 1.f);
            v2 = v2 > 0.f ? v2 : (__expf(v2) - 1.f);
            v3 = v3 > 0.f ? v3 : (__expf(v3) - 1.f);
        }
        uint2 o;
        __half2 ha = __floats2half2_rn(v0, v1);
        __half2 hb = __floats2half2_rn(v2, v3);
        o.x = *reinterpret_cast<uint32_t*>(&ha);
        o.y = *reinterpret_cast<uint32_t*>(&hb);
        *reinterpret_cast<uint2*>(reinterpret_cast<__half*>(out) + (size_t)n * 1024 + c) = o;
    }
}

// ---------------- host launcher ----------------
static inline void run_gemm_dual_tc(const __half* A, const __half* B1, const __half* B2,
                                    __half* C1, __half* C2, int M, int N1, int N2, int K) {
    dim3 grid((N1 + N2) / 128, (M + 127) / 128);
    gemm_f16_dual<<<grid, 256, HSMEM_BYTES>>>(A, B1, B2, C1, C2, M, N1, N2, K);
}

extern "C" void kernel_launch(void* const* d_in, const int* in_sizes, int n_in,
                              void* d_out, int out_size) {
    const float* x   = (const float*)d_in[0];
    const int*   ei  = (const int*)d_in[1];
    const float* W1  = (const float*)d_in[2];
    const float* a1s = (const float*)d_in[3];
    const float* a1d = (const float*)d_in[4];
    const float* b1  = (const float*)d_in[5];
    const float* lw1 = (const float*)d_in[6];
    const float* lb1 = (const float*)d_in[7];
    const float* W2  = (const float*)d_in[8];
    const float* a2s = (const float*)d_in[9];
    const float* a2d = (const float*)d_in[10];
    const float* b2  = (const float*)d_in[11];
    const float* lw2 = (const float*)d_in[12];
    const float* lb2 = (const float*)d_in[13];
    const float* W3  = (const float*)d_in[14];
    const float* a3s = (const float*)d_in[15];
    const float* a3d = (const float*)d_in[16];
    const float* b3  = (const float*)d_in[17];
    const float* lw3 = (const float*)d_in[18];
    const float* lb3 = (const float*)d_in[19];
    float* out = (float*)d_out;

    cudaFuncSetAttribute(gemm_f16_dual, cudaFuncAttributeMaxDynamicSharedMemorySize,
                         HSMEM_BYTES);

    void *p_h, *p_lin, *p_x1h, *p_x2h;
    cudaGetSymbolAddress(&p_h, g_h);
    cudaGetSymbolAddress(&p_lin, g_linh);
    cudaGetSymbolAddress(&p_x1h, g_x1h);
    cudaGetSymbolAddress(&p_x2h, g_x2h);
    __half* h    = (__half*)p_h;
    __half* lin  = (__half*)p_lin;
    __half* x1h  = (__half*)p_x1h;
    __half* x2h  = (__half*)p_x2h;

    void *p_w2h, *p_lw2h, *p_w3h, *p_lw3h;
    cudaGetSymbolAddress(&p_w2h, g_w2h);
    cudaGetSymbolAddress(&p_lw2h, g_lw2h);
    cudaGetSymbolAddress(&p_w3h, g_w3h);
    cudaGetSymbolAddress(&p_lw3h, g_lw3h);
    __half* w2h  = (__half*)p_w2h;
    __half* lw2h = (__half*)p_lw2h;
    __half* w3h  = (__half*)p_w3h;
    __half* lw3h = (__half*)p_lw3h;

    // build CSR by dst (edges + self-loops)
    k_zero_counts<<<(N_NODES + 255) / 256, 256>>>();
    k_count<<<(ET + 255) / 256, 256>>>(ei);
    k_scan<<<1, 1024>>>();
    k_scatter<<<(ET + 255) / 256, 256>>>(ei);

    // convert all weights to fp16 (one fused launch)
    k_f2h_all<<<(F2H_TOTAL4 + 255) / 256, 256>>>(W2, lw2, W3, lw3);

    // ---- layer 1: 14 -> 4x256, concat, +skip, ELU ----
    {
        dim3 grid((1024 + 1024) / 64, (N_NODES + 127) / 128);
        sgemm_dual<<<grid, 256>>>(x, W1, lw1, h, lin, N_NODES, 1024, 1024, 14);
    }
    k_alpha<4><<<(N_NODES * 4 * 32 + 255) / 256, 256>>>(a1s, a1d);
    gat_agg<4, false, true, __half><<<N_NODES, 256>>>(b1, lb1, x1h);

    // ---- layer 2: 1024 -> 4x256, concat, +skip, ELU ----
    run_gemm_dual_tc(x1h, w2h, lw2h, h, lin, N_NODES, 1024, 1024, 1024);
    k_alpha<4><<<(N_NODES * 4 * 32 + 255) / 256, 256>>>(a2s, a2d);
    gat_agg<4, false, true, __half><<<N_NODES, 256>>>(b2, lb2, x2h);

    // ---- layer 3: 1024 -> mean of 6x256, +skip, no ELU ----
    run_gemm_dual_tc(x2h, w3h, lw3h, h, lin, N_NODES, 1536, 256, 1024);
    k_alpha<6><<<(N_NODES * 6 * 32 + 255) / 256, 256>>>(a3s, a3d);
    gat_agg<6, true, false, float><<<N_NODES, 256>>>(b3, lb3, out);
}

// round 10
// speedup vs baseline: 4.7787x; 1.0112x over previous
#include <cuda_runtime.h>
#include <cuda_fp16.h>
#include <math.h>
#include <stdint.h>

#define N_NODES 10000
#define N_EDGES 160000
#define ET (N_EDGES + N_NODES)

// ---------------- scratch (static __device__, no allocations) ----------------
__device__ __half g_h[(size_t)N_NODES * 1536];     // GAT linear output, fp16
__device__ __half g_linh[(size_t)N_NODES * 1024];  // skip-linear output, fp16
__device__ __half g_x1h[(size_t)N_NODES * 1024];
__device__ __half g_x2h[(size_t)N_NODES * 1024];
__device__ __half g_w2h[1024 * 1024];
__device__ __half g_lw2h[1024 * 1024];
__device__ __half g_w3h[1536 * 1024];
__device__ __half g_lw3h[256 * 1024];
__device__ float  g_as[N_NODES * 6];
__device__ float  g_ad[N_NODES * 6];
__device__ int    g_rowptr[N_NODES + 1];
__device__ int    g_cnt[N_NODES];
__device__ int    g_fill[N_NODES];
__device__ int    g_col[ET];

// ---------------- graph build ----------------
__global__ void k_count(const int* __restrict__ ei) {
    int i = blockIdx.x * blockDim.x + threadIdx.x;
    if (i >= ET) return;
    int d = (i < N_EDGES) ? ei[N_EDGES + i] : (i - N_EDGES);
    atomicAdd(&g_cnt[d], 1);
}
__global__ void k_scan() {
    __shared__ int tmp[1024];
    __shared__ int carry;
    int t = threadIdx.x;
    if (t == 0) { carry = 0; g_rowptr[0] = 0; }
    __syncthreads();
    for (int base = 0; base < N_NODES; base += 1024) {
        int v = (base + t < N_NODES) ? g_cnt[base + t] : 0;
        tmp[t] = v;
        __syncthreads();
        for (int off = 1; off < 1024; off <<= 1) {
            int add = (t >= off) ? tmp[t - off] : 0;
            __syncthreads();
            tmp[t] += add;
            __syncthreads();
        }
        if (base + t < N_NODES) g_rowptr[base + t + 1] = carry + tmp[t];
        __syncthreads();
        if (t == 0) carry += tmp[1023];
        __syncthreads();
    }
}
__global__ void k_scatter(const int* __restrict__ ei) {
    int i = blockIdx.x * blockDim.x + threadIdx.x;
    if (i >= ET) return;
    int s, d;
    if (i < N_EDGES) { s = ei[i]; d = ei[N_EDGES + i]; }
    else             { s = d = i - N_EDGES; }
    int pos = g_rowptr[d] + atomicAdd(&g_fill[d], 1);
    g_col[pos] = s;
}

// ---------------- fused fp32 -> fp16 weight conversion (float4 vectorized) ----
#define S_W2  (1024 * 1024)
#define S_LW2 (1024 * 1024)
#define S_W3  (1536 * 1024)
#define S_LW3 (256 * 1024)
#define F2H_TOTAL4 ((S_W2 + S_LW2 + S_W3 + S_LW3) / 4)

__global__ void k_f2h_all(const float* __restrict__ W2, const float* __restrict__ lw2,
                          const float* __restrict__ W3, const float* __restrict__ lw3) {
    int i = blockIdx.x * blockDim.x + threadIdx.x;   // float4 index
    if (i >= F2H_TOTAL4) return;
    const float* src;
    __half* dst;
    int off;
    if (i < S_W2 / 4)                      { src = W2;  dst = g_w2h;  off = i; }
    else if (i < (S_W2 + S_LW2) / 4)       { src = lw2; dst = g_lw2h; off = i - S_W2 / 4; }
    else if (i < (S_W2 + S_LW2 + S_W3) / 4){ src = W3;  dst = g_w3h;  off = i - (S_W2 + S_LW2) / 4; }
    else                                   { src = lw3; dst = g_lw3h; off = i - (S_W2 + S_LW2 + S_W3) / 4; }
    float4 v = *reinterpret_cast<const float4*>(src + 4 * off);
    uint2 o;
    __half2 a = __floats2half2_rn(v.x, v.y);
    __half2 b = __floats2half2_rn(v.z, v.w);
    o.x = *reinterpret_cast<uint32_t*>(&a);
    o.y = *reinterpret_cast<uint32_t*>(&b);
    *reinterpret_cast<uint2*>(dst + 4 * off) = o;
}

// -------- scalar SGEMM dual-output (layer 1, K=14): [C1|C2] = A * [B1|B2]^T --------
__global__ void sgemm_dual(const float* __restrict__ A,
                           const float* __restrict__ B1, const float* __restrict__ B2,
                           __half* __restrict__ C1, __half* __restrict__ C2,
                           int M, int N1, int N2, int K) {
    const int BM = 128, BN = 64, BK = 16;
    __shared__ float As[BK][BM + 4];
    __shared__ float Bs[BK][BN + 4];
    int bnG = blockIdx.x * BN;
    bool second = bnG >= N1;
    const float* B = second ? B2 : B1;
    __half* C = second ? C2 : C1;
    int bn = second ? bnG - N1 : bnG;
    int Nc = second ? N2 : N1;

    int bm = blockIdx.y * BM;
    int t = threadIdx.x;
    int tx = t & 15, ty = t >> 4;
    float acc[8][4];
#pragma unroll
    for (int i = 0; i < 8; i++)
#pragma unroll
        for (int j = 0; j < 4; j++) acc[i][j] = 0.f;
    for (int k0 = 0; k0 < K; k0 += BK) {
#pragma unroll
        for (int i = 0; i < 8; i++) {
            int idx = t + i * 256;
            int r = idx >> 4, kk = idx & 15;
            int gr = bm + r, gk = k0 + kk;
            As[kk][r] = (gr < M && gk < K) ? A[(size_t)gr * K + gk] : 0.f;
        }
#pragma unroll
        for (int i = 0; i < 4; i++) {
            int idx = t + i * 256;
            int r = idx >> 4, kk = idx & 15;
            int gr = bn + r, gk = k0 + kk;
            Bs[kk][r] = (gr < Nc && gk < K) ? B[(size_t)gr * K + gk] : 0.f;
        }
        __syncthreads();
#pragma unroll
        for (int kk = 0; kk < BK; kk++) {
            float a[8], b[4];
#pragma unroll
            for (int i = 0; i < 8; i++) a[i] = As[kk][ty * 8 + i];
#pragma unroll
            for (int j = 0; j < 4; j++) b[j] = Bs[kk][tx * 4 + j];
#pragma unroll
            for (int i = 0; i < 8; i++)
#pragma unroll
                for (int j = 0; j < 4; j++) acc[i][j] = fmaf(a[i], b[j], acc[i][j]);
        }
        __syncthreads();
    }
#pragma unroll
    for (int i = 0; i < 8; i++) {
        int r = bm + ty * 8 + i;
        if (r >= M) continue;
#pragma unroll
        for (int j = 0; j < 4; j++) {
            int c = bn + tx * 4 + j;
            if (c < Nc) C[(size_t)r * Nc + c] = __float2half_rn(acc[i][j]);
        }
    }
}

// ====== fp16 tensor-core dual GEMM (mma.sync m16n8k16): [C1|C2] = A*[B1|B2]^T ======
// 256 threads, 128x128 CTA tile, warp 32x64 (8 warps, 4x2), 4-stage cp.async,
// single-barrier mainloop. K%32==0, N1%128==0, N2%128==0, K/32>=4.

#define HBK 32
#define HSTRIDE 40
#define HSTAGE_BYTES (2 * 128 * HSTRIDE * 2)     // A + B per stage = 20480
#define HSMEM_BYTES  (4 * HSTAGE_BYTES)          // 81920

__device__ __forceinline__ void mma_f16(float c[4], const uint32_t a[4], const uint32_t b[2]) {
    asm volatile(
        "mma.sync.aligned.m16n8k16.row.col.f32.f16.f16.f32 "
        "{%0,%1,%2,%3}, {%4,%5,%6,%7}, {%8,%9}, {%0,%1,%2,%3};"
        : "+f"(c[0]), "+f"(c[1]), "+f"(c[2]), "+f"(c[3])
        : "r"(a[0]), "r"(a[1]), "r"(a[2]), "r"(a[3]), "r"(b[0]), "r"(b[1]));
}
__device__ __forceinline__ void ldsm_x4(uint32_t r[4], uint32_t saddr) {
    asm volatile("ldmatrix.sync.aligned.m8n8.x4.shared.b16 {%0,%1,%2,%3}, [%4];"
                 : "=r"(r[0]), "=r"(r[1]), "=r"(r[2]), "=r"(r[3]) : "r"(saddr));
}
__device__ __forceinline__ void cp_async16(uint32_t saddr, const void* gaddr) {
    asm volatile("cp.async.cg.shared.global [%0], [%1], 16;" :: "r"(saddr), "l"(gaddr));
}
__device__ __forceinline__ void cp_commit() { asm volatile("cp.async.commit_group;"); }
template <int N_> __device__ __forceinline__ void cp_wait() {
    asm volatile("cp.async.wait_group %0;" :: "n"(N_));
}
static __device__ __forceinline__ uint32_t smem_u32(const void* p) {
    uint32_t a;
    asm("{ .reg .u64 t; cvta.to.shared.u64 t, %1; cvt.u32.u64 %0, t; }" : "=r"(a) : "l"(p));
    return a;
}

__global__ __launch_bounds__(256, 2)
void gemm_f16_dual(const __half* __restrict__ A,
                   const __half* __restrict__ B1, const __half* __restrict__ B2,
                   __half* __restrict__ C1, __half* __restrict__ C2,
                   int M, int N1, int N2, int K) {
    extern __shared__ __half hsm[];
    const uint32_t s0 = smem_u32(hsm);

    const int bnG = blockIdx.x * 128;
    const bool second = bnG >= N1;
    const __half* B = second ? B2 : B1;
    __half* C = second ? C2 : C1;
    const int bn = second ? bnG - N1 : bnG;
    const int Nc = second ? N2 : N1;

    const int bm = blockIdx.y * 128;
    const int t = threadIdx.x;
    const int w = t >> 5, lane = t & 31;
    const int wm = (w >> 1) * 32;
    const int wn = (w & 1) * 64;
    const int g = lane >> 2;
    const int r = lane & 3;

    const int sub = lane >> 3;
    const int frow = (sub & 1) * 8 + (lane & 7);
    const int fkof = (sub >> 1) * 8;

    float acc[2][8][4];
#pragma unroll
    for (int mi = 0; mi < 2; mi++)
#pragma unroll
        for (int ni = 0; ni < 8; ni++)
#pragma unroll
            for (int q = 0; q < 4; q++) acc[mi][ni][q] = 0.f;

    const int nIter = K / HBK;

    const int c0 = t, c1 = t + 256;
    const int r0 = c0 >> 2, kc0 = (c0 & 3) * 8;
    const int r1 = c1 >> 2, kc1 = (c1 & 3) * 8;
    const __half* gA0 = A + (size_t)min(bm + r0, M - 1) * K + kc0;
    const __half* gA1 = A + (size_t)min(bm + r1, M - 1) * K + kc1;
    const __half* gB0 = B + (size_t)(bn + r0) * K + kc0;
    const __half* gB1 = B + (size_t)(bn + r1) * K + kc1;
    const uint32_t sa0 = (uint32_t)(r0 * HSTRIDE + kc0) * 2;
    const uint32_t sa1 = (uint32_t)(r1 * HSTRIDE + kc1) * 2;

    auto load_stage = [&](int j) {
        const int s = j & 3;
        const int k0 = j * HBK;
        const uint32_t aS = s0 + s * HSTAGE_BYTES;
        const uint32_t bS = aS + 128 * HSTRIDE * 2;
        cp_async16(aS + sa0, gA0 + k0);
        cp_async16(aS + sa1, gA1 + k0);
        cp_async16(bS + sa0, gB0 + k0);
        cp_async16(bS + sa1, gB1 + k0);
        cp_commit();
    };

    load_stage(0);
    load_stage(1);
    load_stage(2);

    for (int j = 0; j < nIter; j++) {
        const int s = j & 3;
        // complete stage j (own groups), then publish via single barrier
        if (j + 2 < nIter)      cp_wait<2>();
        else if (j + 1 < nIter) cp_wait<1>();
        else                    cp_wait<0>();
        __syncthreads();
        // all warps are past compute(j-1); safe to overwrite stage (j-1)&3
        if (j + 3 < nIter) load_stage(j + 3);

        const uint32_t aS = s0 + s * HSTAGE_BYTES;
        const uint32_t bS = aS + 128 * HSTRIDE * 2;
#pragma unroll
        for (int ks = 0; ks < 2; ks++) {
            const int kb = ks * 16;
            uint32_t af[4], af2[4], bf[8][2];
            ldsm_x4(af, aS + ((wm + frow) * HSTRIDE + kb + fkof) * 2);
            ldsm_x4(af2, aS + ((wm + 16 + frow) * HSTRIDE + kb + fkof) * 2);
#pragma unroll
            for (int np = 0; np < 4; np++) {
                uint32_t rr[4];
                ldsm_x4(rr, bS + ((wn + np * 16 + frow) * HSTRIDE + kb + fkof) * 2);
                bf[2 * np + 0][0] = rr[0];
                bf[2 * np + 1][0] = rr[1];
                bf[2 * np + 0][1] = rr[2];
                bf[2 * np + 1][1] = rr[3];
            }
#pragma unroll
            for (int ni = 0; ni < 8; ni++) {
                mma_f16(acc[0][ni], af, bf[ni]);
                mma_f16(acc[1][ni], af2, bf[ni]);
            }
        }
    }

    // epilogue (fp16 both outputs)
#pragma unroll
    for (int mi = 0; mi < 2; mi++) {
        int row0 = bm + wm + mi * 16 + g;
        int row1 = row0 + 8;
#pragma unroll
        for (int ni = 0; ni < 8; ni++) {
            int col = bn + wn + ni * 8 + 2 * r;
            if (row0 < M)
                *reinterpret_cast<__half2*>(C + (size_t)row0 * Nc + col) =
                    __floats2half2_rn(acc[mi][ni][0], acc[mi][ni][1]);
            if (row1 < M)
                *reinterpret_cast<__half2*>(C + (size_t)row1 * Nc + col) =
                    __floats2half2_rn(acc[mi][ni][2], acc[mi][ni][3]);
        }
    }
}

// ---------------- attention logits (fp16 h, half2 loads) ----------------
template <int H>
__global__ void k_alpha(const float* __restrict__ a_s, const float* __restrict__ a_d) {
    int gw = (blockIdx.x * blockDim.x + threadIdx.x) >> 5;
    int lane = threadIdx.x & 31;
    if (gw >= N_NODES * H) return;
    int n = gw / H, h = gw - n * H;
    const __half2* row = reinterpret_cast<const __half2*>(g_h + (size_t)n * (H * 256)) + h * 128;
    float ss = 0.f, sd = 0.f;
    for (int c = lane; c < 128; c += 32) {
        float2 v = __half22float2(row[c]);
        float2 a1 = *reinterpret_cast<const float2*>(a_s + h * 256 + 2 * c);
        float2 a2 = *reinterpret_cast<const float2*>(a_d + h * 256 + 2 * c);
        ss = fmaf(v.x, a1.x, fmaf(v.y, a1.y, ss));
        sd = fmaf(v.x, a2.x, fmaf(v.y, a2.y, sd));
    }
#pragma unroll
    for (int o = 16; o; o >>= 1) {
        ss += __shfl_xor_sync(0xffffffffu, ss, o);
        sd += __shfl_xor_sync(0xffffffffu, sd, o);
    }
    if (lane == 0) { g_as[n * H + h] = ss; g_ad[n * H + h] = sd; }
}

__device__ __forceinline__ float lrelu(float x) { return x > 0.f ? x : 0.2f * x; }

// ---------------- fused segment-softmax + aggregation + epilogue ----------------
template <int H, bool MEAN, bool APPLY_ELU, typename OT>
__global__ void gat_agg(const float* __restrict__ bgat, const float* __restrict__ lb,
                        OT* __restrict__ out) {
    int n = blockIdx.x;
    int t = threadIdx.x;
    int start = g_rowptr[n];
    int deg = g_rowptr[n + 1] - start;

    __shared__ float s_m[H], s_dinv[H];
    int w = t >> 5, lane = t & 31;
    if (w < H) {
        float ad = g_ad[n * H + w];
        float mx = -1e30f;
        for (int j = lane; j < deg; j += 32)
            mx = fmaxf(mx, lrelu(g_as[g_col[start + j] * H + w] + ad));
#pragma unroll
        for (int o = 16; o; o >>= 1) mx = fmaxf(mx, __shfl_xor_sync(0xffffffffu, mx, o));
        float sum = 0.f;
        for (int j = lane; j < deg; j += 32)
            sum += __expf(lrelu(g_as[g_col[start + j] * H + w] + ad) - mx);
#pragma unroll
        for (int o = 16; o; o >>= 1) sum += __shfl_xor_sync(0xffffffffu, sum, o);
        if (lane == 0) { s_m[w] = mx; s_dinv[w] = 1.f / (sum + 1e-16f); }
    }
    __syncthreads();

    const int CH = 32;
    __shared__ float s_coef[CH][H];
    __shared__ int   s_src[CH];
    const int hA = t >> 6;                 // head of channels 4t..4t+3
    const int hB = 4 + (t >> 7);           // head of channels 1024+2t (H==6)

    float2 accA0 = make_float2(0.f, 0.f);
    float2 accA1 = make_float2(0.f, 0.f);
    float2 accB  = make_float2(0.f, 0.f);

    for (int cs = 0; cs < deg; cs += CH) {
        int cnt = min(CH, deg - cs);
        if (t < cnt) s_src[t] = g_col[start + cs + t];
        for (int idx = t; idx < cnt * H; idx += 256) {
            int j = idx / H, h = idx - j * H;
            int s = g_col[start + cs + j];
            float ee = lrelu(g_as[s * H + h] + g_ad[n * H + h]);
            s_coef[j][h] = __expf(ee - s_m[h]) * s_dinv[h];
        }
        __syncthreads();
        for (int j = 0; j < cnt; j++) {
            const __half* row = g_h + (size_t)s_src[j] * (H * 256);
            uint2 va = *reinterpret_cast<const uint2*>(row + 4 * t);
            float cA = s_coef[j][hA];
            float2 f0 = __half22float2(*reinterpret_cast<__half2*>(&va.x));
            float2 f1 = __half22float2(*reinterpret_cast<__half2*>(&va.y));
            accA0.x = fmaf(f0.x, cA, accA0.x);
            accA0.y = fmaf(f0.y, cA, accA0.y);
            accA1.x = fmaf(f1.x, cA, accA1.x);
            accA1.y = fmaf(f1.y, cA, accA1.y);
            if (H == 6) {
                __half2 vb = *reinterpret_cast<const __half2*>(row + 1024 + 2 * t);
                float cB = s_coef[j][hB];
                float2 fb = __half22float2(vb);
                accB.x = fmaf(fb.x, cB, accB.x);
                accB.y = fmaf(fb.y, cB, accB.y);
            }
        }
        __syncthreads();
    }

    if (MEAN) {
        __shared__ float s_sum[256];
        s_sum[t] = 0.f;
        __syncthreads();
        int cA = (4 * t) & 255;
        atomicAdd(&s_sum[cA + 0], accA0.x);
        atomicAdd(&s_sum[cA + 1], accA0.y);
        atomicAdd(&s_sum[cA + 2], accA1.x);
        atomicAdd(&s_sum[cA + 3], accA1.y);
        int cB = (2 * t) & 255;
        atomicAdd(&s_sum[cB + 0], accB.x);
        atomicAdd(&s_sum[cB + 1], accB.y);
        __syncthreads();
        float ln = __half2float(g_linh[(size_t)n * 256 + t]);
        float v = s_sum[t] * (1.f / (float)H) + bgat[t] + ln + lb[t];
        reinterpret_cast<float*>(out)[(size_t)n * 256 + t] = v;
    } else {
        int c = 4 * t;
        float4 bg = *reinterpret_cast<const float4*>(bgat + c);
        float4 lb4 = *reinterpret_cast<const float4*>(lb + c);
        uint2 lv = *reinterpret_cast<const uint2*>(g_linh + (size_t)n * 1024 + c);
        float2 l0 = __half22float2(*reinterpret_cast<__half2*>(&lv.x));
        float2 l1 = __half22float2(*reinterpret_cast<__half2*>(&lv.y));
        float v0 = accA0.x + bg.x + l0.x + lb4.x;
        float v1 = accA0.y + bg.y + l0.y + lb4.y;
        float v2 = accA1.x + bg.z + l1.x + lb4.z;
        float v3 = accA1.y + bg.w + l1.y + lb4.w;
        if (APPLY_ELU) {
            v0 = v0 > 0.f ? v0 : (__expf(v0) - 1.f);
            v1 = v1 > 0.f ? v1 : (__expf(v1) - 1.f);
            v2 = v2 > 0.f ? v2 : (__expf(v2) - 1.f);
            v3 = v3 > 0.f ? v3 : (__expf(v3) - 1.f);
        }
        uint2 o;
        __half2 ha = __floats2half2_rn(v0, v1);
        __half2 hb = __floats2half2_rn(v2, v3);
        o.x = *reinterpret_cast<uint32_t*>(&ha);
        o.y = *reinterpret_cast<uint32_t*>(&hb);
        *reinterpret_cast<uint2*>(reinterpret_cast<__half*>(out) + (size_t)n * 1024 + c) = o;
    }
}

// ---------------- host launcher ----------------
static inline void run_gemm_dual_tc(const __half* A, const __half* B1, const __half* B2,
                                    __half* C1, __half* C2, int M, int N1, int N2, int K) {
    dim3 grid((N1 + N2) / 128, (M + 127) / 128);
    gemm_f16_dual<<<grid, 256, HSMEM_BYTES>>>(A, B1, B2, C1, C2, M, N1, N2, K);
}

extern "C" void kernel_launch(void* const* d_in, const int* in_sizes, int n_in,
                              void* d_out, int out_size) {
    const float* x   = (const float*)d_in[0];
    const int*   ei  = (const int*)d_in[1];
    const float* W1  = (const float*)d_in[2];
    const float* a1s = (const float*)d_in[3];
    const float* a1d = (const float*)d_in[4];
    const float* b1  = (const float*)d_in[5];
    const float* lw1 = (const float*)d_in[6];
    const float* lb1 = (const float*)d_in[7];
    const float* W2  = (const float*)d_in[8];
    const float* a2s = (const float*)d_in[9];
    const float* a2d = (const float*)d_in[10];
    const float* b2  = (const float*)d_in[11];
    const float* lw2 = (const float*)d_in[12];
    const float* lb2 = (const float*)d_in[13];
    const float* W3  = (const float*)d_in[14];
    const float* a3s = (const float*)d_in[15];
    const float* a3d = (const float*)d_in[16];
    const float* b3  = (const float*)d_in[17];
    const float* lw3 = (const float*)d_in[18];
    const float* lb3 = (const float*)d_in[19];
    float* out = (float*)d_out;

    cudaFuncSetAttribute(gemm_f16_dual, cudaFuncAttributeMaxDynamicSharedMemorySize,
                         HSMEM_BYTES);

    void *p_h, *p_lin, *p_x1h, *p_x2h;
    cudaGetSymbolAddress(&p_h, g_h);
    cudaGetSymbolAddress(&p_lin, g_linh);
    cudaGetSymbolAddress(&p_x1h, g_x1h);
    cudaGetSymbolAddress(&p_x2h, g_x2h);
    __half* h    = (__half*)p_h;
    __half* lin  = (__half*)p_lin;
    __half* x1h  = (__half*)p_x1h;
    __half* x2h  = (__half*)p_x2h;

    void *p_w2h, *p_lw2h, *p_w3h, *p_lw3h;
    cudaGetSymbolAddress(&p_w2h, g_w2h);
    cudaGetSymbolAddress(&p_lw2h, g_lw2h);
    cudaGetSymbolAddress(&p_w3h, g_w3h);
    cudaGetSymbolAddress(&p_lw3h, g_lw3h);
    __half* w2h  = (__half*)p_w2h;
    __half* lw2h = (__half*)p_lw2h;
    __half* w3h  = (__half*)p_w3h;
    __half* lw3h = (__half*)p_lw3h;

    void *p_cnt, *p_fill;
    cudaGetSymbolAddress(&p_cnt, g_cnt);
    cudaGetSymbolAddress(&p_fill, g_fill);

    // build CSR by dst (edges + self-loops)
    cudaMemsetAsync(p_cnt, 0, N_NODES * sizeof(int));
    cudaMemsetAsync(p_fill, 0, N_NODES * sizeof(int));
    k_count<<<(ET + 255) / 256, 256>>>(ei);
    k_scan<<<1, 1024>>>();
    k_scatter<<<(ET + 255) / 256, 256>>>(ei);

    // convert all weights to fp16 (one fused launch)
    k_f2h_all<<<(F2H_TOTAL4 + 255) / 256, 256>>>(W2, lw2, W3, lw3);

    // ---- layer 1: 14 -> 4x256, concat, +skip, ELU ----
    {
        dim3 grid((1024 + 1024) / 64, (N_NODES + 127) / 128);
        sgemm_dual<<<grid, 256>>>(x, W1, lw1, h, lin, N_NODES, 1024, 1024, 14);
    }
    k_alpha<4><<<(N_NODES * 4 * 32 + 255) / 256, 256>>>(a1s, a1d);
    gat_agg<4, false, true, __half><<<N_NODES, 256>>>(b1, lb1, x1h);

    // ---- layer 2: 1024 -> 4x256, concat, +skip, ELU ----
    run_gemm_dual_tc(x1h, w2h, lw2h, h, lin, N_NODES, 1024, 1024, 1024);
    k_alpha<4><<<(N_NODES * 4 * 32 + 255) / 256, 256>>>(a2s, a2d);
    gat_agg<4, false, true, __half><<<N_NODES, 256>>>(b2, lb2, x2h);

    // ---- layer 3: 1024 -> mean of 6x256, +skip, no ELU ----
    run_gemm_dual_tc(x2h, w3h, lw3h, h, lin, N_NODES, 1536, 256, 1024);
    k_alpha<6><<<(N_NODES * 6 * 32 + 255) / 256, 256>>>(a3s, a3d);
    gat_agg<6, true, false, float><<<N_NODES, 256>>>(b3, lb3, out);
}

// round 11
// speedup vs baseline: 5.0220x; 1.0509x over previous
#include <cuda_runtime.h>
#include <cuda_fp16.h>
#include <math.h>
#include <stdint.h>

#define N_NODES 10000
#define N_EDGES 160000
#define ET (N_EDGES + N_NODES)
#define NSCAN_BLOCKS ((N_NODES + 255) / 256)

// ---------------- scratch (static __device__, no allocations) ----------------
__device__ __half g_h[(size_t)N_NODES * 1536];     // GAT linear output, fp16
__device__ __half g_linh[(size_t)N_NODES * 1024];  // skip-linear output, fp16
__device__ __half g_x1h[(size_t)N_NODES * 1024];
__device__ __half g_x2h[(size_t)N_NODES * 1024];
__device__ __half g_w2h[1024 * 1024];
__device__ __half g_lw2h[1024 * 1024];
__device__ __half g_w3h[1536 * 1024];
__device__ __half g_lw3h[256 * 1024];
__device__ float  g_as[N_NODES * 6];
__device__ float  g_ad[N_NODES * 6];
__device__ float  g_asp[N_NODES * 6 * 4];   // alpha partials (4 slots, single-writer)
__device__ float  g_adp[N_NODES * 6 * 4];
__device__ int    g_rowptr[N_NODES + 1];
__device__ int    g_cnt[N_NODES];
__device__ int    g_fill[N_NODES];
__device__ int    g_col[ET];
__device__ int    g_bsum[NSCAN_BLOCKS];
__device__ int    g_boff[NSCAN_BLOCKS];

// ---------------- graph build ----------------
__global__ void k_count(const int* __restrict__ ei) {
    int i = blockIdx.x * blockDim.x + threadIdx.x;
    if (i >= ET) return;
    int d = (i < N_EDGES) ? ei[N_EDGES + i] : (i - N_EDGES);
    atomicAdd(&g_cnt[d], 1);
}

// 3-phase parallel scan of g_cnt into g_rowptr (exclusive; rowptr[0]=0)
__global__ void k_scan1() {
    int b = blockIdx.x, t = threadIdx.x;
    int i = b * 256 + t;
    int lane = t & 31, w = t >> 5;
    int x = (i < N_NODES) ? g_cnt[i] : 0;
#pragma unroll
    for (int o = 1; o < 32; o <<= 1) {
        int y = __shfl_up_sync(0xffffffffu, x, o);
        if (lane >= o) x += y;
    }
    __shared__ int ws[8];
    if (lane == 31) ws[w] = x;
    __syncthreads();
    if (t == 0) {
        int run = 0;
#pragma unroll
        for (int k = 0; k < 8; k++) { int v = ws[k]; ws[k] = run; run += v; }
    }
    __syncthreads();
    int incl = x + ws[w];
    if (i < N_NODES) g_rowptr[i + 1] = incl;   // pre-offset inclusive
    if (t == 255) g_bsum[b] = incl;
}
__global__ void k_scan2() {
    if (threadIdx.x == 0) {
        int run = 0;
        for (int k = 0; k < NSCAN_BLOCKS; k++) { int v = g_bsum[k]; g_boff[k] = run; run += v; }
        g_rowptr[0] = 0;
    }
}
__global__ void k_scan3() {
    int b = blockIdx.x;
    int i = b * 256 + threadIdx.x;
    if (i < N_NODES) g_rowptr[i + 1] += g_boff[b];
}

__global__ void k_scatter(const int* __restrict__ ei) {
    int i = blockIdx.x * blockDim.x + threadIdx.x;
    if (i >= ET) return;
    int s, d;
    if (i < N_EDGES) { s = ei[i]; d = ei[N_EDGES + i]; }
    else             { s = d = i - N_EDGES; }
    int pos = g_rowptr[d] + atomicAdd(&g_fill[d], 1);
    g_col[pos] = s;
}

// ---------------- fused fp32 -> fp16 weight conversion (float4 vectorized) ----
#define S_W2  (1024 * 1024)
#define S_LW2 (1024 * 1024)
#define S_W3  (1536 * 1024)
#define S_LW3 (256 * 1024)
#define F2H_TOTAL4 ((S_W2 + S_LW2 + S_W3 + S_LW3) / 4)

__global__ void k_f2h_all(const float* __restrict__ W2, const float* __restrict__ lw2,
                          const float* __restrict__ W3, const float* __restrict__ lw3) {
    int i = blockIdx.x * blockDim.x + threadIdx.x;   // float4 index
    if (i >= F2H_TOTAL4) return;
    const float* src;
    __half* dst;
    int off;
    if (i < S_W2 / 4)                      { src = W2;  dst = g_w2h;  off = i; }
    else if (i < (S_W2 + S_LW2) / 4)       { src = lw2; dst = g_lw2h; off = i - S_W2 / 4; }
    else if (i < (S_W2 + S_LW2 + S_W3) / 4){ src = W3;  dst = g_w3h;  off = i - (S_W2 + S_LW2) / 4; }
    else                                   { src = lw3; dst = g_lw3h; off = i - (S_W2 + S_LW2 + S_W3) / 4; }
    float4 v = *reinterpret_cast<const float4*>(src + 4 * off);
    uint2 o;
    __half2 a = __floats2half2_rn(v.x, v.y);
    __half2 b = __floats2half2_rn(v.z, v.w);
    o.x = *reinterpret_cast<uint32_t*>(&a);
    o.y = *reinterpret_cast<uint32_t*>(&b);
    *reinterpret_cast<uint2*>(dst + 4 * off) = o;
}

// ---------------- alpha partial fixup: g_as/g_ad = sum of 4 slots ----------------
__global__ void k_alpha_fix(int total) {    // total = N_NODES * H
    int i = blockIdx.x * blockDim.x + threadIdx.x;
    if (i >= total) return;
    float4 s = *reinterpret_cast<const float4*>(g_asp + 4 * i);
    float4 d = *reinterpret_cast<const float4*>(g_adp + 4 * i);
    g_as[i] = (s.x + s.y) + (s.z + s.w);
    g_ad[i] = (d.x + d.y) + (d.z + d.w);
}

// -------- scalar SGEMM dual-output (layer 1, K=14): [C1|C2] = A * [B1|B2]^T --------
// First half also emits alpha partials (slot = column-quarter of the head).
__global__ void sgemm_dual(const float* __restrict__ A,
                           const float* __restrict__ B1, const float* __restrict__ B2,
                           __half* __restrict__ C1, __half* __restrict__ C2,
                           const float* __restrict__ a_s, const float* __restrict__ a_d,
                           int M, int N1, int N2, int K) {
    const int BM = 128, BN = 64, BK = 16;
    __shared__ float As[BK][BM + 4];
    __shared__ float Bs[BK][BN + 4];
    int bnG = blockIdx.x * BN;
    bool second = bnG >= N1;
    const float* B = second ? B2 : B1;
    __half* C = second ? C2 : C1;
    int bn = second ? bnG - N1 : bnG;
    int Nc = second ? N2 : N1;
    const int H = N1 >> 8;

    int bm = blockIdx.y * BM;
    int t = threadIdx.x;
    int tx = t & 15, ty = t >> 4;
    float acc[8][4];
#pragma unroll
    for (int i = 0; i < 8; i++)
#pragma unroll
        for (int j = 0; j < 4; j++) acc[i][j] = 0.f;
    for (int k0 = 0; k0 < K; k0 += BK) {
#pragma unroll
        for (int i = 0; i < 8; i++) {
            int idx = t + i * 256;
            int r = idx >> 4, kk = idx & 15;
            int gr = bm + r, gk = k0 + kk;
            As[kk][r] = (gr < M && gk < K) ? A[(size_t)gr * K + gk] : 0.f;
        }
#pragma unroll
        for (int i = 0; i < 4; i++) {
            int idx = t + i * 256;
            int r = idx >> 4, kk = idx & 15;
            int gr = bn + r, gk = k0 + kk;
            Bs[kk][r] = (gr < Nc && gk < K) ? B[(size_t)gr * K + gk] : 0.f;
        }
        __syncthreads();
#pragma unroll
        for (int kk = 0; kk < BK; kk++) {
            float a[8], b[4];
#pragma unroll
            for (int i = 0; i < 8; i++) a[i] = As[kk][ty * 8 + i];
#pragma unroll
            for (int j = 0; j < 4; j++) b[j] = Bs[kk][tx * 4 + j];
#pragma unroll
            for (int i = 0; i < 8; i++)
#pragma unroll
                for (int j = 0; j < 4; j++) acc[i][j] = fmaf(a[i], b[j], acc[i][j]);
        }
        __syncthreads();
    }
#pragma unroll
    for (int i = 0; i < 8; i++) {
        int r = bm + ty * 8 + i;
        if (r >= M) continue;
        int c = bn + tx * 4;
        __half2 h0 = __floats2half2_rn(acc[i][0], acc[i][1]);
        __half2 h1 = __floats2half2_rn(acc[i][2], acc[i][3]);
        uint2 o;
        o.x = *reinterpret_cast<uint32_t*>(&h0);
        o.y = *reinterpret_cast<uint32_t*>(&h1);
        *reinterpret_cast<uint2*>(C + (size_t)r * Nc + c) = o;
    }

    // alpha partials (first half only); single writer per (row, slot)
    if (!second) {
        int head = bnG >> 8;
        int slot = (bnG >> 6) & 3;
        float av_s[4], av_d[4];
        int base = (bnG & 255) + tx * 4;
#pragma unroll
        for (int j = 0; j < 4; j++) {
            av_s[j] = a_s[head * 256 + base + j];
            av_d[j] = a_d[head * 256 + base + j];
        }
#pragma unroll
        for (int i = 0; i < 8; i++) {
            float ps = acc[i][0] * av_s[0] + acc[i][1] * av_s[1] +
                       acc[i][2] * av_s[2] + acc[i][3] * av_s[3];
            float pd = acc[i][0] * av_d[0] + acc[i][1] * av_d[1] +
                       acc[i][2] * av_d[2] + acc[i][3] * av_d[3];
#pragma unroll
            for (int o = 1; o < 16; o <<= 1) {
                ps += __shfl_xor_sync(0xffffffffu, ps, o);
                pd += __shfl_xor_sync(0xffffffffu, pd, o);
            }
            int r = bm + ty * 8 + i;
            if (tx == 0 && r < M) {
                g_asp[(r * H + head) * 4 + slot] = ps;
                g_adp[(r * H + head) * 4 + slot] = pd;
            }
        }
    }
}

// ====== fp16 tensor-core dual GEMM (mma.sync m16n8k16): [C1|C2] = A*[B1|B2]^T ======
// 256 threads, 128x128 CTA tile, warp 32x64 (8 warps, 4x2), 4-stage cp.async,
// single-barrier mainloop. First half emits alpha partials.
// K%32==0, N1%128==0, N2%128==0, K/32>=4.

#define HBK 32
#define HSTRIDE 40
#define HSTAGE_BYTES (2 * 128 * HSTRIDE * 2)     // A + B per stage = 20480
#define HSMEM_BYTES  (4 * HSTAGE_BYTES)          // 81920

__device__ __forceinline__ void mma_f16(float c[4], const uint32_t a[4], const uint32_t b[2]) {
    asm volatile(
        "mma.sync.aligned.m16n8k16.row.col.f32.f16.f16.f32 "
        "{%0,%1,%2,%3}, {%4,%5,%6,%7}, {%8,%9}, {%0,%1,%2,%3};"
        : "+f"(c[0]), "+f"(c[1]), "+f"(c[2]), "+f"(c[3])
        : "r"(a[0]), "r"(a[1]), "r"(a[2]), "r"(a[3]), "r"(b[0]), "r"(b[1]));
}
__device__ __forceinline__ void ldsm_x4(uint32_t r[4], uint32_t saddr) {
    asm volatile("ldmatrix.sync.aligned.m8n8.x4.shared.b16 {%0,%1,%2,%3}, [%4];"
                 : "=r"(r[0]), "=r"(r[1]), "=r"(r[2]), "=r"(r[3]) : "r"(saddr));
}
__device__ __forceinline__ void cp_async16(uint32_t saddr, const void* gaddr) {
    asm volatile("cp.async.cg.shared.global [%0], [%1], 16;" :: "r"(saddr), "l"(gaddr));
}
__device__ __forceinline__ void cp_commit() { asm volatile("cp.async.commit_group;"); }
template <int N_> __device__ __forceinline__ void cp_wait() {
    asm volatile("cp.async.wait_group %0;" :: "n"(N_));
}
static __device__ __forceinline__ uint32_t smem_u32(const void* p) {
    uint32_t a;
    asm("{ .reg .u64 t; cvta.to.shared.u64 t, %1; cvt.u32.u64 %0, t; }" : "=r"(a) : "l"(p));
    return a;
}

__global__ __launch_bounds__(256, 2)
void gemm_f16_dual(const __half* __restrict__ A,
                   const __half* __restrict__ B1, const __half* __restrict__ B2,
                   __half* __restrict__ C1, __half* __restrict__ C2,
                   const float* __restrict__ a_s, const float* __restrict__ a_d,
                   int M, int N1, int N2, int K) {
    extern __shared__ __half hsm[];
    const uint32_t s0 = smem_u32(hsm);

    const int bnG = blockIdx.x * 128;
    const bool second = bnG >= N1;
    const __half* B = second ? B2 : B1;
    __half* C = second ? C2 : C1;
    const int bn = second ? bnG - N1 : bnG;
    const int Nc = second ? N2 : N1;
    const int H = N1 >> 8;

    const int bm = blockIdx.y * 128;
    const int t = threadIdx.x;
    const int w = t >> 5, lane = t & 31;
    const int wm = (w >> 1) * 32;
    const int wn = (w & 1) * 64;
    const int g = lane >> 2;
    const int r = lane & 3;

    const int sub = lane >> 3;
    const int frow = (sub & 1) * 8 + (lane & 7);
    const int fkof = (sub >> 1) * 8;

    float acc[2][8][4];
#pragma unroll
    for (int mi = 0; mi < 2; mi++)
#pragma unroll
        for (int ni = 0; ni < 8; ni++)
#pragma unroll
            for (int q = 0; q < 4; q++) acc[mi][ni][q] = 0.f;

    const int nIter = K / HBK;

    const int c0 = t, c1 = t + 256;
    const int r0 = c0 >> 2, kc0 = (c0 & 3) * 8;
    const int r1 = c1 >> 2, kc1 = (c1 & 3) * 8;
    const __half* gA0 = A + (size_t)min(bm + r0, M - 1) * K + kc0;
    const __half* gA1 = A + (size_t)min(bm + r1, M - 1) * K + kc1;
    const __half* gB0 = B + (size_t)(bn + r0) * K + kc0;
    const __half* gB1 = B + (size_t)(bn + r1) * K + kc1;
    const uint32_t sa0 = (uint32_t)(r0 * HSTRIDE + kc0) * 2;
    const uint32_t sa1 = (uint32_t)(r1 * HSTRIDE + kc1) * 2;

    auto load_stage = [&](int j) {
        const int s = j & 3;
        const int k0 = j * HBK;
        const uint32_t aS = s0 + s * HSTAGE_BYTES;
        const uint32_t bS = aS + 128 * HSTRIDE * 2;
        cp_async16(aS + sa0, gA0 + k0);
        cp_async16(aS + sa1, gA1 + k0);
        cp_async16(bS + sa0, gB0 + k0);
        cp_async16(bS + sa1, gB1 + k0);
        cp_commit();
    };

    load_stage(0);
    load_stage(1);
    load_stage(2);

    for (int j = 0; j < nIter; j++) {
        const int s = j & 3;
        if (j + 2 < nIter)      cp_wait<2>();
        else if (j + 1 < nIter) cp_wait<1>();
        else                    cp_wait<0>();
        __syncthreads();
        if (j + 3 < nIter) load_stage(j + 3);

        const uint32_t aS = s0 + s * HSTAGE_BYTES;
        const uint32_t bS = aS + 128 * HSTRIDE * 2;
#pragma unroll
        for (int ks = 0; ks < 2; ks++) {
            const int kb = ks * 16;
            uint32_t af[4], af2[4], bf[8][2];
            ldsm_x4(af, aS + ((wm + frow) * HSTRIDE + kb + fkof) * 2);
            ldsm_x4(af2, aS + ((wm + 16 + frow) * HSTRIDE + kb + fkof) * 2);
#pragma unroll
            for (int np = 0; np < 4; np++) {
                uint32_t rr[4];
                ldsm_x4(rr, bS + ((wn + np * 16 + frow) * HSTRIDE + kb + fkof) * 2);
                bf[2 * np + 0][0] = rr[0];
                bf[2 * np + 1][0] = rr[1];
                bf[2 * np + 0][1] = rr[2];
                bf[2 * np + 1][1] = rr[3];
            }
#pragma unroll
            for (int ni = 0; ni < 8; ni++) {
                mma_f16(acc[0][ni], af, bf[ni]);
                mma_f16(acc[1][ni], af2, bf[ni]);
            }
        }
    }

    // epilogue (fp16 both outputs)
#pragma unroll
    for (int mi = 0; mi < 2; mi++) {
        int row0 = bm + wm + mi * 16 + g;
        int row1 = row0 + 8;
#pragma unroll
        for (int ni = 0; ni < 8; ni++) {
            int col = bn + wn + ni * 8 + 2 * r;
            if (row0 < M)
                *reinterpret_cast<__half2*>(C + (size_t)row0 * Nc + col) =
                    __floats2half2_rn(acc[mi][ni][0], acc[mi][ni][1]);
            if (row1 < M)
                *reinterpret_cast<__half2*>(C + (size_t)row1 * Nc + col) =
                    __floats2half2_rn(acc[mi][ni][2], acc[mi][ni][3]);
        }
    }

    // alpha partials (first half only); slot = 2*(column-128-tile) + warp-half
    if (!second) {
        const int head = bnG >> 8;
        const int slot = ((bnG >> 7) & 1) * 2 + (wn >> 6);
        float av_s[16], av_d[16];
        const int base = head * 256 + (bnG & 255) + wn + 2 * r;
#pragma unroll
        for (int ni = 0; ni < 8; ni++) {
#pragma unroll
            for (int q = 0; q < 2; q++) {
                av_s[ni * 2 + q] = a_s[base + ni * 8 + q];
                av_d[ni * 2 + q] = a_d[base + ni * 8 + q];
            }
        }
        float ps[4], pd[4];   // rows: (mi=0,row0),(mi=0,row1),(mi=1,row0),(mi=1,row1)
#pragma unroll
        for (int k = 0; k < 4; k++) { ps[k] = 0.f; pd[k] = 0.f; }
#pragma unroll
        for (int mi = 0; mi < 2; mi++) {
#pragma unroll
            for (int ni = 0; ni < 8; ni++) {
                ps[mi * 2 + 0] += acc[mi][ni][0] * av_s[ni * 2] + acc[mi][ni][1] * av_s[ni * 2 + 1];
                ps[mi * 2 + 1] += acc[mi][ni][2] * av_s[ni * 2] + acc[mi][ni][3] * av_s[ni * 2 + 1];
                pd[mi * 2 + 0] += acc[mi][ni][0] * av_d[ni * 2] + acc[mi][ni][1] * av_d[ni * 2 + 1];
                pd[mi * 2 + 1] += acc[mi][ni][2] * av_d[ni * 2] + acc[mi][ni][3] * av_d[ni * 2 + 1];
            }
        }
#pragma unroll
        for (int o = 1; o < 4; o <<= 1) {
#pragma unroll
            for (int k = 0; k < 4; k++) {
                ps[k] += __shfl_xor_sync(0xffffffffu, ps[k], o);
                pd[k] += __shfl_xor_sync(0xffffffffu, pd[k], o);
            }
        }
        if (r == 0) {
#pragma unroll
            for (int mi = 0; mi < 2; mi++) {
                int row0 = bm + wm + mi * 16 + g;
                int row1 = row0 + 8;
                if (row0 < M) {
                    g_asp[(row0 * H + head) * 4 + slot] = ps[mi * 2 + 0];
                    g_adp[(row0 * H + head) * 4 + slot] = pd[mi * 2 + 0];
                }
                if (row1 < M) {
                    g_asp[(row1 * H + head) * 4 + slot] = ps[mi * 2 + 1];
                    g_adp[(row1 * H + head) * 4 + slot] = pd[mi * 2 + 1];
                }
            }
        }
    }
}

__device__ __forceinline__ float lrelu(float x) { return x > 0.f ? x : 0.2f * x; }

// ---------------- fused segment-softmax + aggregation + epilogue ----------------
template <int H, bool MEAN, bool APPLY_ELU, typename OT>
__global__ void gat_agg(const float* __restrict__ bgat, const float* __restrict__ lb,
                        OT* __restrict__ out) {
    int n = blockIdx.x;
    int t = threadIdx.x;
    int start = g_rowptr[n];
    int deg = g_rowptr[n + 1] - start;

    __shared__ float s_m[H], s_dinv[H];
    int w = t >> 5, lane = t & 31;
    if (w < H) {
        float ad = g_ad[n * H + w];
        float mx = -1e30f;
        for (int j = lane; j < deg; j += 32)
            mx = fmaxf(mx, lrelu(g_as[g_col[start + j] * H + w] + ad));
#pragma unroll
        for (int o = 16; o; o >>= 1) mx = fmaxf(mx, __shfl_xor_sync(0xffffffffu, mx, o));
        float sum = 0.f;
        for (int j = lane; j < deg; j += 32)
            sum += __expf(lrelu(g_as[g_col[start + j] * H + w] + ad) - mx);
#pragma unroll
        for (int o = 16; o; o >>= 1) sum += __shfl_xor_sync(0xffffffffu, sum, o);
        if (lane == 0) { s_m[w] = mx; s_dinv[w] = 1.f / (sum + 1e-16f); }
    }
    __syncthreads();

    const int CH = 32;
    __shared__ float s_coef[CH][H];
    __shared__ int   s_src[CH];
    const int hA = t >> 6;                 // head of channels 4t..4t+3
    const int hB = 4 + (t >> 7);           // head of channels 1024+2t (H==6)

    float2 accA0 = make_float2(0.f, 0.f);
    float2 accA1 = make_float2(0.f, 0.f);
    float2 accB  = make_float2(0.f, 0.f);

    for (int cs = 0; cs < deg; cs += CH) {
        int cnt = min(CH, deg - cs);
        if (t < cnt) s_src[t] = g_col[start + cs + t];
        for (int idx = t; idx < cnt * H; idx += 256) {
            int j = idx / H, h = idx - j * H;
            int s = g_col[start + cs + j];
            float ee = lrelu(g_as[s * H + h] + g_ad[n * H + h]);
            s_coef[j][h] = __expf(ee - s_m[h]) * s_dinv[h];
        }
        __syncthreads();
        for (int j = 0; j < cnt; j++) {
            const __half* row = g_h + (size_t)s_src[j] * (H * 256);
            uint2 va = *reinterpret_cast<const uint2*>(row + 4 * t);
            float cA = s_coef[j][hA];
            float2 f0 = __half22float2(*reinterpret_cast<__half2*>(&va.x));
            float2 f1 = __half22float2(*reinterpret_cast<__half2*>(&va.y));
            accA0.x = fmaf(f0.x, cA, accA0.x);
            accA0.y = fmaf(f0.y, cA, accA0.y);
            accA1.x = fmaf(f1.x, cA, accA1.x);
            accA1.y = fmaf(f1.y, cA, accA1.y);
            if (H == 6) {
                __half2 vb = *reinterpret_cast<const __half2*>(row + 1024 + 2 * t);
                float cB = s_coef[j][hB];
                float2 fb = __half22float2(vb);
                accB.x = fmaf(fb.x, cB, accB.x);
                accB.y = fmaf(fb.y, cB, accB.y);
            }
        }
        __syncthreads();
    }

    if (MEAN) {
        __shared__ float s_sum[256];
        s_sum[t] = 0.f;
        __syncthreads();
        int cA = (4 * t) & 255;
        atomicAdd(&s_sum[cA + 0], accA0.x);
        atomicAdd(&s_sum[cA + 1], accA0.y);
        atomicAdd(&s_sum[cA + 2], accA1.x);
        atomicAdd(&s_sum[cA + 3], accA1.y);
        int cB = (2 * t) & 255;
        atomicAdd(&s_sum[cB + 0], accB.x);
        atomicAdd(&s_sum[cB + 1], accB.y);
        __syncthreads();
        float ln = __half2float(g_linh[(size_t)n * 256 + t]);
        float v = s_sum[t] * (1.f / (float)H) + bgat[t] + ln + lb[t];
        reinterpret_cast<float*>(out)[(size_t)n * 256 + t] = v;
    } else {
        int c = 4 * t;
        float4 bg = *reinterpret_cast<const float4*>(bgat + c);
        float4 lb4 = *reinterpret_cast<const float4*>(lb + c);
        uint2 lv = *reinterpret_cast<const uint2*>(g_linh + (size_t)n * 1024 + c);
        float2 l0 = __half22float2(*reinterpret_cast<__half2*>(&lv.x));
        float2 l1 = __half22float2(*reinterpret_cast<__half2*>(&lv.y));
        float v0 = accA0.x + bg.x + l0.x + lb4.x;
        float v1 = accA0.y + bg.y + l0.y + lb4.y;
        float v2 = accA1.x + bg.z + l1.x + lb4.z;
        float v3 = accA1.y + bg.w + l1.y + lb4.w;
        if (APPLY_ELU) {
            v0 = v0 > 0.f ? v0 : (__expf(v0) - 1.f);
            v1 = v1 > 0.f ? v1 : (__expf(v1) - 1.f);
            v2 = v2 > 0.f ? v2 : (__expf(v2) - 1.f);
            v3 = v3 > 0.f ? v3 : (__expf(v3) - 1.f);
        }
        uint2 o;
        __half2 ha = __floats2half2_rn(v0, v1);
        __half2 hb = __floats2half2_rn(v2, v3);
        o.x = *reinterpret_cast<uint32_t*>(&ha);
        o.y = *reinterpret_cast<uint32_t*>(&hb);
        *reinterpret_cast<uint2*>(reinterpret_cast<__half*>(out) + (size_t)n * 1024 + c) = o;
    }
}

// ---------------- host launcher ----------------
static inline void run_gemm_dual_tc(const __half* A, const __half* B1, const __half* B2,
                                    __half* C1, __half* C2,
                                    const float* a_s, const float* a_d,
                                    int M, int N1, int N2, int K) {
    dim3 grid((N1 + N2) / 128, (M + 127) / 128);
    gemm_f16_dual<<<grid, 256, HSMEM_BYTES>>>(A, B1, B2, C1, C2, a_s, a_d, M, N1, N2, K);
}

extern "C" void kernel_launch(void* const* d_in, const int* in_sizes, int n_in,
                              void* d_out, int out_size) {
    const float* x   = (const float*)d_in[0];
    const int*   ei  = (const int*)d_in[1];
    const float* W1  = (const float*)d_in[2];
    const float* a1s = (const float*)d_in[3];
    const float* a1d = (const float*)d_in[4];
    const float* b1  = (const float*)d_in[5];
    const float* lw1 = (const float*)d_in[6];
    const float* lb1 = (const float*)d_in[7];
    const float* W2  = (const float*)d_in[8];
    const float* a2s = (const float*)d_in[9];
    const float* a2d = (const float*)d_in[10];
    const float* b2  = (const float*)d_in[11];
    const float* lw2 = (const float*)d_in[12];
    const float* lb2 = (const float*)d_in[13];
    const float* W3  = (const float*)d_in[14];
    const float* a3s = (const float*)d_in[15];
    const float* a3d = (const float*)d_in[16];
    const float* b3  = (const float*)d_in[17];
    const float* lw3 = (const float*)d_in[18];
    const float* lb3 = (const float*)d_in[19];
    float* out = (float*)d_out;

    cudaFuncSetAttribute(gemm_f16_dual, cudaFuncAttributeMaxDynamicSharedMemorySize,
                         HSMEM_BYTES);

    void *p_h, *p_lin, *p_x1h, *p_x2h;
    cudaGetSymbolAddress(&p_h, g_h);
    cudaGetSymbolAddress(&p_lin, g_linh);
    cudaGetSymbolAddress(&p_x1h, g_x1h);
    cudaGetSymbolAddress(&p_x2h, g_x2h);
    __half* h    = (__half*)p_h;
    __half* lin  = (__half*)p_lin;
    __half* x1h  = (__half*)p_x1h;
    __half* x2h  = (__half*)p_x2h;

    void *p_w2h, *p_lw2h, *p_w3h, *p_lw3h;
    cudaGetSymbolAddress(&p_w2h, g_w2h);
    cudaGetSymbolAddress(&p_lw2h, g_lw2h);
    cudaGetSymbolAddress(&p_w3h, g_w3h);
    cudaGetSymbolAddress(&p_lw3h, g_lw3h);
    __half* w2h  = (__half*)p_w2h;
    __half* lw2h = (__half*)p_lw2h;
    __half* w3h  = (__half*)p_w3h;
    __half* lw3h = (__half*)p_lw3h;

    void *p_cnt, *p_fill;
    cudaGetSymbolAddress(&p_cnt, g_cnt);
    cudaGetSymbolAddress(&p_fill, g_fill);

    // build CSR by dst (edges + self-loops)
    cudaMemsetAsync(p_cnt, 0, N_NODES * sizeof(int));
    cudaMemsetAsync(p_fill, 0, N_NODES * sizeof(int));
    k_count<<<(ET + 255) / 256, 256>>>(ei);
    k_scan1<<<NSCAN_BLOCKS, 256>>>();
    k_scan2<<<1, 32>>>();
    k_scan3<<<NSCAN_BLOCKS, 256>>>();
    k_scatter<<<(ET + 255) / 256, 256>>>(ei);

    // convert all weights to fp16 (one fused launch)
    k_f2h_all<<<(F2H_TOTAL4 + 255) / 256, 256>>>(W2, lw2, W3, lw3);

    // ---- layer 1: 14 -> 4x256, concat, +skip, ELU ----
    {
        dim3 grid((1024 + 1024) / 64, (N_NODES + 127) / 128);
        sgemm_dual<<<grid, 256>>>(x, W1, lw1, h, lin, a1s, a1d, N_NODES, 1024, 1024, 14);
    }
    k_alpha_fix<<<(N_NODES * 4 + 255) / 256, 256>>>(N_NODES * 4);
    gat_agg<4, false, true, __half><<<N_NODES, 256>>>(b1, lb1, x1h);

    // ---- layer 2: 1024 -> 4x256, concat, +skip, ELU ----
    run_gemm_dual_tc(x1h, w2h, lw2h, h, lin, a2s, a2d, N_NODES, 1024, 1024, 1024);
    k_alpha_fix<<<(N_NODES * 4 + 255) / 256, 256>>>(N_NODES * 4);
    gat_agg<4, false, true, __half><<<N_NODES, 256>>>(b2, lb2, x2h);

    // ---- layer 3: 1024 -> mean of 6x256, +skip, no ELU ----
    run_gemm_dual_tc(x2h, w3h, lw3h, h, lin, a3s, a3d, N_NODES, 1536, 256, 1024);
    k_alpha_fix<<<(N_NODES * 6 + 255) / 256, 256>>>(N_NODES * 6);
    gat_agg<6, true, false, float><<<N_NODES, 256>>>(b3, lb3, out);
}